// round 1
// baseline (speedup 1.0000x reference)
#include <cuda_runtime.h>
#include <math.h>

#define NV 50000
#define NE 800000
#define NBATCH 8
#define H 128
#define LATD 64
#define TDIM 16
#define NLAYERS 4
#define EPSF 1e-5f

#define BM 64
#define BK 16
#define THREADS 256

// -------- scratch (device globals; no allocations allowed) --------
__device__ float g_h[NV * H];      // node features (25.6 MB)
__device__ float g_agg[NV * H];    // per-layer message aggregation
__device__ float g_xt[NV * 3];     // interpolated positions
__device__ float g_temb[TDIM];     // time embedding (constant across nodes)
__device__ double g_loss;

__device__ __forceinline__ float siluf(float x) { return x / (1.f + expf(-x)); }

// -------- prelude: zero loss accumulator, compute time embedding --------
__global__ void k_prelude(const float* t, const float* w1, const float* b1,
                          const float* w2, const float* b2) {
    __shared__ float s1[TDIM];
    if (threadIdx.x == 0) g_loss = 0.0;
    float ts = t[0];
    int i = threadIdx.x;
    if (i < TDIM) s1[i] = siluf(ts * w1[i] + b1[i]);
    __syncthreads();
    if (i < TDIM) {
        float acc = b2[i];
#pragma unroll
        for (int k = 0; k < TDIM; k++) acc += s1[k] * w2[k * TDIM + i];
        g_temb[i] = acc;
    }
}

// -------- x_t = (1-t)*pos0 + t*pos1 --------
__global__ void k_xt(const float* pos0, const float* pos1, const float* t) {
    int i = blockIdx.x * blockDim.x + threadIdx.x;
    if (i < NV * 3) {
        float ts = t[0];
        g_xt[i] = (1.f - ts) * pos0[i] + ts * pos1[i];
    }
}

// -------- h0 = concat(z[batch], t_emb) @ cp_w + cp_b --------
__global__ void k_h0(const float* z, const int* batch, const float* w, const float* b) {
    __shared__ float sW[80 * H];   // 40 KB, cp_w resident per block
    __shared__ float sin_[80];
    int tid = threadIdx.x;  // 128 threads
    for (int i = tid; i < 80 * H; i += 128) sW[i] = w[i];
    float bc = b[tid];
    int v0 = blockIdx.x * 64;
    for (int n = 0; n < 64; n++) {
        int v = v0 + n;
        if (v >= NV) break;
        __syncthreads();
        if (tid < 80) sin_[tid] = (tid < LATD) ? z[batch[v] * LATD + tid] : g_temb[tid - LATD];
        __syncthreads();
        float acc = bc;
#pragma unroll 16
        for (int k = 0; k < 80; k++) acc += sin_[k] * sW[k * H + tid];
        g_h[(size_t)v * H + tid] = acc;
    }
}

__global__ void k_zero_agg() {
    int i = blockIdx.x * blockDim.x + threadIdx.x;
    if (i < NV * H) g_agg[i] = 0.f;
}

// -------- edge kernel: fused 2-stage edge MLP + scatter-add --------
// GEMM tile: BM=64 edges x 128 cols, BK=16, 256 threads, 4x8 acc/thread.
__global__ __launch_bounds__(THREADS) void k_edge(const int* ei,
        const float* w1, const float* b1, const float* w2, const float* b2) {
    __shared__ float sBig[BM * 132];   // stage1: A^T [16][68] front; stage2: t1 [64][132]
    __shared__ float sB[BK * 132];
    __shared__ int sDst[BM];
    __shared__ int sSrc[BM];
    __shared__ float sDp[BM * 3];

    int tid = threadIdx.x;
    int tr = tid >> 4;   // 0..15 -> rows tr*4..tr*4+3
    int tc = tid & 15;   // 0..15 -> cols tc*8..tc*8+7
    int e0 = blockIdx.x * BM;

    if (tid < BM) { sSrc[tid] = ei[e0 + tid]; sDst[tid] = ei[NE + e0 + tid]; }
    __syncthreads();
    if (tid < BM * 3) {
        int r = tid / 3, c = tid - r * 3;
        sDp[r * 3 + c] = g_xt[sDst[r] * 3 + c] - g_xt[sSrc[r] * 3 + c];
    }
    __syncthreads();

    float acc[4][8];
#pragma unroll
    for (int i = 0; i < 4; i++)
#pragma unroll
        for (int j = 0; j < 8; j++) acc[i][j] = 0.f;

    // ---- stage 1: e_in[64x259] @ w1[259x128] ----
    for (int k0 = 0; k0 < 272; k0 += BK) {
#pragma unroll
        for (int it = 0; it < 8; it++) {            // B chunk 16x128
            int idx = tid + it * THREADS;
            int kk = idx >> 7, c = idx & 127;
            int k = k0 + kk;
            sB[kk * 132 + c] = (k < 259) ? w1[k * H + c] : 0.f;
        }
#pragma unroll
        for (int it = 0; it < 4; it++) {            // A chunk (gathered), transposed
            int idx = tid + it * THREADS;
            int kk = idx & 15, r = idx >> 4;
            int k = k0 + kk;
            float v;
            if (k < H)            v = g_h[(size_t)sDst[r] * H + k];
            else if (k < 2 * H)   v = g_h[(size_t)sSrc[r] * H + (k - H)];
            else if (k < 259)     v = sDp[r * 3 + (k - 2 * H)];
            else                  v = 0.f;
            sBig[kk * 68 + r] = v;
        }
        __syncthreads();
#pragma unroll
        for (int kk = 0; kk < BK; kk++) {
            float4 av  = *(const float4*)&sBig[kk * 68 + tr * 4];
            float4 bv0 = *(const float4*)&sB[kk * 132 + tc * 8];
            float4 bv1 = *(const float4*)&sB[kk * 132 + tc * 8 + 4];
            float a[4] = {av.x, av.y, av.z, av.w};
            float b[8] = {bv0.x, bv0.y, bv0.z, bv0.w, bv1.x, bv1.y, bv1.z, bv1.w};
#pragma unroll
            for (int i = 0; i < 4; i++)
#pragma unroll
                for (int j = 0; j < 8; j++) acc[i][j] += a[i] * b[j];
        }
        __syncthreads();
    }

    // ---- epilogue 1: t1 = silu(acc+b1) -> sBig[r][c] ----
#pragma unroll
    for (int j = 0; j < 8; j++) {
        float bb = b1[tc * 8 + j];
#pragma unroll
        for (int i = 0; i < 4; i++) {
            sBig[(tr * 4 + i) * 132 + tc * 8 + j] = siluf(acc[i][j] + bb);
            acc[i][j] = 0.f;
        }
    }
    __syncthreads();

    // ---- stage 2: t1[64x128] @ w2[128x128] ----
    for (int k0 = 0; k0 < H; k0 += BK) {
#pragma unroll
        for (int it = 0; it < 8; it++) {
            int idx = tid + it * THREADS;
            int kk = idx >> 7, c = idx & 127;
            sB[kk * 132 + c] = w2[(k0 + kk) * H + c];
        }
        __syncthreads();
#pragma unroll
        for (int kk = 0; kk < BK; kk++) {
            float4 bv0 = *(const float4*)&sB[kk * 132 + tc * 8];
            float4 bv1 = *(const float4*)&sB[kk * 132 + tc * 8 + 4];
            float b[8] = {bv0.x, bv0.y, bv0.z, bv0.w, bv1.x, bv1.y, bv1.z, bv1.w};
            float a[4];
#pragma unroll
            for (int i = 0; i < 4; i++) a[i] = sBig[(tr * 4 + i) * 132 + k0 + kk];
#pragma unroll
            for (int i = 0; i < 4; i++)
#pragma unroll
                for (int j = 0; j < 8; j++) acc[i][j] += a[i] * b[j];
        }
        __syncthreads();
    }

    // ---- epilogue 2: m = silu(acc+b2); scatter-add to agg[dst] ----
#pragma unroll
    for (int j = 0; j < 8; j++) {
        float bb = b2[tc * 8 + j];
#pragma unroll
        for (int i = 0; i < 4; i++) {
            float m = siluf(acc[i][j] + bb);
            atomicAdd(&g_agg[(size_t)sDst[tr * 4 + i] * H + tc * 8 + j], m);
        }
    }
}

// -------- node kernel: fused node MLP + residual + LayerNorm (in-place h) ----
__global__ __launch_bounds__(THREADS) void k_node(
        const float* w1, const float* b1, const float* w2, const float* b2,
        const float* lng, const float* lnb) {
    __shared__ float sBig[BM * 132];
    __shared__ float sB[BK * 132];
    __shared__ float sMu[BM];
    __shared__ float sRs[BM];

    int tid = threadIdx.x;
    int tr = tid >> 4, tc = tid & 15;
    int v0 = blockIdx.x * BM;

    float acc[4][8];
#pragma unroll
    for (int i = 0; i < 4; i++)
#pragma unroll
        for (int j = 0; j < 8; j++) acc[i][j] = 0.f;

    // ---- stage 1: concat(h,agg)[64x256] @ w1[256x128] ----
    for (int k0 = 0; k0 < 2 * H; k0 += BK) {
#pragma unroll
        for (int it = 0; it < 8; it++) {
            int idx = tid + it * THREADS;
            int kk = idx >> 7, c = idx & 127;
            sB[kk * 132 + c] = w1[(k0 + kk) * H + c];
        }
#pragma unroll
        for (int it = 0; it < 4; it++) {
            int idx = tid + it * THREADS;
            int kk = idx & 15, r = idx >> 4;
            int k = k0 + kk;
            int vv = v0 + r; if (vv >= NV) vv = NV - 1;   // clamped; row discarded later
            float v = (k < H) ? g_h[(size_t)vv * H + k]
                              : g_agg[(size_t)vv * H + (k - H)];
            sBig[kk * 68 + r] = v;
        }
        __syncthreads();
#pragma unroll
        for (int kk = 0; kk < BK; kk++) {
            float4 av  = *(const float4*)&sBig[kk * 68 + tr * 4];
            float4 bv0 = *(const float4*)&sB[kk * 132 + tc * 8];
            float4 bv1 = *(const float4*)&sB[kk * 132 + tc * 8 + 4];
            float a[4] = {av.x, av.y, av.z, av.w};
            float b[8] = {bv0.x, bv0.y, bv0.z, bv0.w, bv1.x, bv1.y, bv1.z, bv1.w};
#pragma unroll
            for (int i = 0; i < 4; i++)
#pragma unroll
                for (int j = 0; j < 8; j++) acc[i][j] += a[i] * b[j];
        }
        __syncthreads();
    }

#pragma unroll
    for (int j = 0; j < 8; j++) {
        float bb = b1[tc * 8 + j];
#pragma unroll
        for (int i = 0; i < 4; i++) {
            sBig[(tr * 4 + i) * 132 + tc * 8 + j] = siluf(acc[i][j] + bb);
            acc[i][j] = 0.f;
        }
    }
    __syncthreads();

    // ---- stage 2: t1 @ w2 ----
    for (int k0 = 0; k0 < H; k0 += BK) {
#pragma unroll
        for (int it = 0; it < 8; it++) {
            int idx = tid + it * THREADS;
            int kk = idx >> 7, c = idx & 127;
            sB[kk * 132 + c] = w2[(k0 + kk) * H + c];
        }
        __syncthreads();
#pragma unroll
        for (int kk = 0; kk < BK; kk++) {
            float4 bv0 = *(const float4*)&sB[kk * 132 + tc * 8];
            float4 bv1 = *(const float4*)&sB[kk * 132 + tc * 8 + 4];
            float b[8] = {bv0.x, bv0.y, bv0.z, bv0.w, bv1.x, bv1.y, bv1.z, bv1.w};
            float a[4];
#pragma unroll
            for (int i = 0; i < 4; i++) a[i] = sBig[(tr * 4 + i) * 132 + k0 + kk];
#pragma unroll
            for (int i = 0; i < 4; i++)
#pragma unroll
                for (int j = 0; j < 8; j++) acc[i][j] += a[i] * b[j];
        }
        __syncthreads();
    }

    // ---- residual + LayerNorm ----
    float xv[4][8];
#pragma unroll
    for (int j = 0; j < 8; j++) {
        float bb = b2[tc * 8 + j];
#pragma unroll
        for (int i = 0; i < 4; i++) {
            int v = v0 + tr * 4 + i;
            float hres = (v < NV) ? g_h[(size_t)v * H + tc * 8 + j] : 0.f;
            xv[i][j] = acc[i][j] + bb + hres;
        }
    }
    __syncthreads();
#pragma unroll
    for (int j = 0; j < 8; j++)
#pragma unroll
        for (int i = 0; i < 4; i++)
            sBig[(tr * 4 + i) * 132 + tc * 8 + j] = xv[i][j];
    __syncthreads();
    if (tid < BM) {
        float s = 0.f, s2 = 0.f;
#pragma unroll 8
        for (int c = 0; c < H; c++) {
            float x = sBig[tid * 132 + c];
            s += x; s2 += x * x;
        }
        float mu = s * (1.f / H);
        float var = s2 * (1.f / H) - mu * mu;
        sMu[tid] = mu;
        sRs[tid] = rsqrtf(var + EPSF);
    }
    __syncthreads();
#pragma unroll
    for (int j = 0; j < 8; j++) {
        int c = tc * 8 + j;
        float g = lng[c], bbn = lnb[c];
#pragma unroll
        for (int i = 0; i < 4; i++) {
            int r = tr * 4 + i;
            int v = v0 + r;
            if (v < NV)
                g_h[(size_t)v * H + c] = g * (xv[i][j] - sMu[r]) * sRs[r] + bbn;
        }
    }
}

// -------- loss: v_pred = h @ op_w + op_b ; MSE vs (pos1-pos0) --------
__global__ void k_loss(const float* pos0, const float* pos1,
                       const float* opw, const float* opb) {
    __shared__ double sAcc[8];
    int lane = threadIdx.x & 31;
    int wid = threadIdx.x >> 5;
    int gw = blockIdx.x * (blockDim.x >> 5) + wid;
    int nw = gridDim.x * (blockDim.x >> 5);
    double local = 0.0;
    for (int v = gw; v < NV; v += nw) {
        float h0 = g_h[(size_t)v * H + lane];
        float h1 = g_h[(size_t)v * H + lane + 32];
        float h2 = g_h[(size_t)v * H + lane + 64];
        float h3 = g_h[(size_t)v * H + lane + 96];
#pragma unroll
        for (int c = 0; c < 3; c++) {
            float s = h0 * opw[lane * 3 + c] + h1 * opw[(lane + 32) * 3 + c]
                    + h2 * opw[(lane + 64) * 3 + c] + h3 * opw[(lane + 96) * 3 + c];
#pragma unroll
            for (int off = 16; off; off >>= 1) s += __shfl_down_sync(0xffffffffu, s, off);
            if (lane == 0) {
                float vp = s + opb[c];
                float tg = pos1[v * 3 + c] - pos0[v * 3 + c];
                float d = vp - tg;
                local += (double)d * (double)d;
            }
        }
    }
    if (lane == 0) sAcc[wid] = local;
    __syncthreads();
    if (threadIdx.x == 0) {
        double t = 0.0;
        for (int i = 0; i < (int)(blockDim.x >> 5); i++) t += sAcc[i];
        atomicAdd(&g_loss, t);
    }
}

__global__ void k_final(float* out) {
    if (threadIdx.x == 0) out[0] = (float)(g_loss / (double)(NV * 3));
}

extern "C" void kernel_launch(void* const* d_in, const int* in_sizes, int n_in,
                              void* d_out, int out_size) {
    const float* pos0  = (const float*)d_in[0];
    const float* pos1  = (const float*)d_in[1];
    const float* z     = (const float*)d_in[2];
    const float* t     = (const float*)d_in[3];
    const int*   ei    = (const int*)d_in[4];
    const int*   batch = (const int*)d_in[5];
    const float* te_w1 = (const float*)d_in[6];
    const float* te_b1 = (const float*)d_in[7];
    const float* te_w2 = (const float*)d_in[8];
    const float* te_b2 = (const float*)d_in[9];
    const float* cp_w  = (const float*)d_in[10];
    const float* cp_b  = (const float*)d_in[11];
    const float* ew1   = (const float*)d_in[12];
    const float* eb1   = (const float*)d_in[13];
    const float* ew2   = (const float*)d_in[14];
    const float* eb2   = (const float*)d_in[15];
    const float* nw1   = (const float*)d_in[16];
    const float* nb1   = (const float*)d_in[17];
    const float* nw2   = (const float*)d_in[18];
    const float* nb2   = (const float*)d_in[19];
    const float* ln_g  = (const float*)d_in[20];
    const float* ln_b  = (const float*)d_in[21];
    const float* op_w  = (const float*)d_in[22];
    const float* op_b  = (const float*)d_in[23];

    k_prelude<<<1, 32>>>(t, te_w1, te_b1, te_w2, te_b2);
    k_xt<<<(NV * 3 + 255) / 256, 256>>>(pos0, pos1, t);
    k_h0<<<(NV + 63) / 64, 128>>>(z, batch, cp_w, cp_b);

    for (int l = 0; l < NLAYERS; l++) {
        k_zero_agg<<<(NV * H + 255) / 256, 256>>>();
        k_edge<<<NE / BM, THREADS>>>(ei,
            ew1 + (size_t)l * 259 * H, eb1 + (size_t)l * H,
            ew2 + (size_t)l * H * H,   eb2 + (size_t)l * H);
        k_node<<<(NV + BM - 1) / BM, THREADS>>>(
            nw1 + (size_t)l * 2 * H * H, nb1 + (size_t)l * H,
            nw2 + (size_t)l * H * H,     nb2 + (size_t)l * H,
            ln_g + (size_t)l * H,        ln_b + (size_t)l * H);
    }

    k_loss<<<256, 256>>>(pos0, pos1, op_w, op_b);
    k_final<<<1, 1>>>((float*)d_out);
}

// round 2
// speedup vs baseline: 4.3655x; 4.3655x over previous
#include <cuda_runtime.h>
#include <cuda_bf16.h>
#include <math.h>
#include <stdint.h>

#define NV 50000
#define NE 800000
#define H 128
#define LATD 64
#define TDIM 16
#define NLAYERS 4
#define EPSF 1e-5f

#define PADA 24    // bf16 elems per row, A/B k16 tiles (conflict-free frag loads)
#define PADT 136   // bf16 elems per row, t1 buffer
#define PADM 132   // f32 elems per row, message/x buffer

// -------- scratch (device globals; no allocations allowed) --------
__device__ float g_h[NV * H];
__device__ float g_agg[NV * H];
__device__ float g_xt[NV * 3];
__device__ float g_temb[TDIM];
__device__ double g_loss;

// bf16 transposed weights [layer][N][K]
__device__ __nv_bfloat16 g_ew1t[NLAYERS][H][272];
__device__ __nv_bfloat16 g_ew2t[NLAYERS][H][H];
__device__ __nv_bfloat16 g_nw1t[NLAYERS][H][256];
__device__ __nv_bfloat16 g_nw2t[NLAYERS][H][H];

__device__ __forceinline__ float siluf(float x) { return x / (1.f + expf(-x)); }

__device__ __forceinline__ uint32_t packbf(float x, float y) {
    __nv_bfloat162 h = __floats2bfloat162_rn(x, y);
    return *(uint32_t*)&h;
}

__device__ __forceinline__ void mma_bf16(float* c, const uint32_t* a, const uint32_t* b) {
    asm volatile(
        "mma.sync.aligned.m16n8k16.row.col.f32.bf16.bf16.f32 "
        "{%0,%1,%2,%3}, {%4,%5,%6,%7}, {%8,%9}, {%0,%1,%2,%3};\n"
        : "+f"(c[0]), "+f"(c[1]), "+f"(c[2]), "+f"(c[3])
        : "r"(a[0]), "r"(a[1]), "r"(a[2]), "r"(a[3]), "r"(b[0]), "r"(b[1]));
}

__device__ __forceinline__ void red_v4(float* addr, float4 m) {
    asm volatile("red.global.add.v4.f32 [%0], {%1,%2,%3,%4};"
                 :: "l"(addr), "f"(m.x), "f"(m.y), "f"(m.z), "f"(m.w) : "memory");
}

// -------- prelude --------
__global__ void k_prelude(const float* t, const float* w1, const float* b1,
                          const float* w2, const float* b2) {
    __shared__ float s1[TDIM];
    if (threadIdx.x == 0) g_loss = 0.0;
    float ts = t[0];
    int i = threadIdx.x;
    if (i < TDIM) s1[i] = siluf(ts * w1[i] + b1[i]);
    __syncthreads();
    if (i < TDIM) {
        float acc = b2[i];
#pragma unroll
        for (int k = 0; k < TDIM; k++) acc += s1[k] * w2[k * TDIM + i];
        g_temb[i] = acc;
    }
}

__global__ void k_xt(const float* pos0, const float* pos1, const float* t) {
    int i = blockIdx.x * blockDim.x + threadIdx.x;
    if (i < NV * 3) {
        float ts = t[0];
        g_xt[i] = (1.f - ts) * pos0[i] + ts * pos1[i];
    }
}

// -------- weight transpose/convert to bf16 --------
__global__ void k_wt(const float* ew1, const float* ew2, const float* nw1, const float* nw2) {
    int i = blockIdx.x * 256 + threadIdx.x;
    const int S1 = NLAYERS * H * 272;
    const int S2 = NLAYERS * H * H;
    const int S3 = NLAYERS * H * 256;
    if (i < S1) {
        int l = i / (H * 272), r = i % (H * 272), n = r / 272, k = r % 272;
        float v = (k < 259) ? ew1[((size_t)l * 259 + k) * H + n] : 0.f;
        g_ew1t[l][n][k] = __float2bfloat16(v);
    } else if (i < S1 + S2) {
        int j = i - S1;
        int l = j / (H * H), r = j % (H * H), n = r / H, k = r % H;
        g_ew2t[l][n][k] = __float2bfloat16(ew2[((size_t)l * H + k) * H + n]);
    } else if (i < S1 + S2 + S3) {
        int j = i - S1 - S2;
        int l = j / (H * 256), r = j % (H * 256), n = r / 256, k = r % 256;
        g_nw1t[l][n][k] = __float2bfloat16(nw1[((size_t)l * 256 + k) * H + n]);
    } else if (i < S1 + S2 + S3 + S2) {
        int j = i - S1 - S2 - S3;
        int l = j / (H * H), r = j % (H * H), n = r / H, k = r % H;
        g_nw2t[l][n][k] = __float2bfloat16(nw2[((size_t)l * H + k) * H + n]);
    }
}

// -------- h0 = concat(z[batch], t_emb) @ cp_w + cp_b --------
__global__ void k_h0(const float* z, const int* batch, const float* w, const float* b) {
    __shared__ float sW[80 * H];
    __shared__ float sin_[80];
    int tid = threadIdx.x;  // 128
    for (int i = tid; i < 80 * H; i += 128) sW[i] = w[i];
    float bc = b[tid];
    int v0 = blockIdx.x * 64;
    for (int n = 0; n < 64; n++) {
        int v = v0 + n;
        if (v >= NV) break;
        __syncthreads();
        if (tid < 80) sin_[tid] = (tid < LATD) ? z[batch[v] * LATD + tid] : g_temb[tid - LATD];
        __syncthreads();
        float acc = bc;
#pragma unroll 16
        for (int k = 0; k < 80; k++) acc += sin_[k] * sW[k * H + tid];
        g_h[(size_t)v * H + tid] = acc;
    }
}

__global__ void k_zero_agg() {
    int i = blockIdx.x * blockDim.x + threadIdx.x;
    if (i < NV * H / 4) ((float4*)g_agg)[i] = make_float4(0.f, 0.f, 0.f, 0.f);
}

// ===================== edge kernel (bf16 mma) =====================
__global__ __launch_bounds__(256) void k_edge(const int* ei, int layer,
                                              const float* b1, const float* b2) {
    __shared__ __align__(16) unsigned char smbuf[64 * PADM * 4];  // 33792 B
    __shared__ int sDst[64], sSrc[64];
    __shared__ float sDp[64][3];
    __nv_bfloat16* sA = (__nv_bfloat16*)smbuf;            // [64][PADA]
    __nv_bfloat16* sB = (__nv_bfloat16*)(smbuf + 3072);   // [128][PADA]
    __nv_bfloat16* sT = (__nv_bfloat16*)(smbuf + 9216);   // [64][PADT]
    float* sMsg = (float*)smbuf;                          // [64][PADM] (aliases all)

    int tid = threadIdx.x;
    int lane = tid & 31, warp = tid >> 5;
    int gID = lane >> 2, tIG = lane & 3;
    int wr = warp >> 2, wc = warp & 3;
    int e0 = blockIdx.x * 64;

    if (tid < 64) { sSrc[tid] = ei[e0 + tid]; sDst[tid] = ei[NE + e0 + tid]; }
    __syncthreads();
    if (tid < 192) {
        int r = tid / 3, c = tid - r * 3;
        sDp[r][c] = g_xt[sDst[r] * 3 + c] - g_xt[sSrc[r] * 3 + c];
    }

    float acc[2][4][4];
#pragma unroll
    for (int mt = 0; mt < 2; mt++)
#pragma unroll
        for (int nt = 0; nt < 4; nt++)
#pragma unroll
            for (int q = 0; q < 4; q++) acc[mt][nt][q] = 0.f;

    const __nv_bfloat16* w1t = &g_ew1t[layer][0][0];

    // ---- stage 1: e_in[64x259] @ w1 -> acc ----
    for (int ch = 0; ch < 17; ch++) {
        int k0 = ch * 16;
        __syncthreads();
        // fill B tile [128][16]
#pragma unroll
        for (int it = 0; it < 4; it++) {
            int idx = tid + it * 256;
            int n = idx >> 3, p = idx & 7;
            *(uint32_t*)&sB[n * PADA + p * 2] = *(const uint32_t*)&w1t[n * 272 + k0 + p * 2];
        }
        // fill A tile [64][16] (gathered, fp32 -> bf16)
#pragma unroll
        for (int it = 0; it < 2; it++) {
            int idx = tid + it * 256;
            int r = idx >> 3, p = idx & 7;
            int k = k0 + p * 2;
            float v0, v1;
            if (k0 < 128) {
                const float* hp = &g_h[(size_t)sDst[r] * H + k];
                v0 = hp[0]; v1 = hp[1];
            } else if (k0 < 256) {
                const float* hp = &g_h[(size_t)sSrc[r] * H + (k - 128)];
                v0 = hp[0]; v1 = hp[1];
            } else {
                int kk = k - 256;
                v0 = (kk < 3) ? sDp[r][kk] : 0.f;
                v1 = (kk + 1 < 3) ? sDp[r][kk + 1] : 0.f;
            }
            *(uint32_t*)&sA[r * PADA + p * 2] = packbf(v0, v1);
        }
        __syncthreads();

        uint32_t af[2][4], bfr[4][2];
#pragma unroll
        for (int mt = 0; mt < 2; mt++) {
            int row = wr * 32 + mt * 16 + gID;
            af[mt][0] = *(uint32_t*)&sA[row * PADA + tIG * 2];
            af[mt][1] = *(uint32_t*)&sA[(row + 8) * PADA + tIG * 2];
            af[mt][2] = *(uint32_t*)&sA[row * PADA + tIG * 2 + 8];
            af[mt][3] = *(uint32_t*)&sA[(row + 8) * PADA + tIG * 2 + 8];
        }
#pragma unroll
        for (int nt = 0; nt < 4; nt++) {
            int n = wc * 32 + nt * 8 + gID;
            bfr[nt][0] = *(uint32_t*)&sB[n * PADA + tIG * 2];
            bfr[nt][1] = *(uint32_t*)&sB[n * PADA + tIG * 2 + 8];
        }
#pragma unroll
        for (int mt = 0; mt < 2; mt++)
#pragma unroll
            for (int nt = 0; nt < 4; nt++)
                mma_bf16(acc[mt][nt], af[mt], bfr[nt]);
    }
    __syncthreads();

    // ---- epilogue 1: t1 = silu(acc + b1) -> sT (bf16) ----
#pragma unroll
    for (int mt = 0; mt < 2; mt++)
#pragma unroll
        for (int nt = 0; nt < 4; nt++) {
            int row = wr * 32 + mt * 16 + gID;
            int col = wc * 32 + nt * 8 + tIG * 2;
            float bb0 = b1[col], bb1 = b1[col + 1];
            *(uint32_t*)&sT[row * PADT + col] =
                packbf(siluf(acc[mt][nt][0] + bb0), siluf(acc[mt][nt][1] + bb1));
            *(uint32_t*)&sT[(row + 8) * PADT + col] =
                packbf(siluf(acc[mt][nt][2] + bb0), siluf(acc[mt][nt][3] + bb1));
#pragma unroll
            for (int q = 0; q < 4; q++) acc[mt][nt][q] = 0.f;
        }

    const __nv_bfloat16* w2t = &g_ew2t[layer][0][0];

    // ---- stage 2: t1[64x128] @ w2 ----
    for (int ch = 0; ch < 8; ch++) {
        int k0 = ch * 16;
        __syncthreads();
#pragma unroll
        for (int it = 0; it < 4; it++) {
            int idx = tid + it * 256;
            int n = idx >> 3, p = idx & 7;
            *(uint32_t*)&sB[n * PADA + p * 2] = *(const uint32_t*)&w2t[n * H + k0 + p * 2];
        }
        __syncthreads();

        uint32_t af[2][4], bfr[4][2];
#pragma unroll
        for (int mt = 0; mt < 2; mt++) {
            int row = wr * 32 + mt * 16 + gID;
            af[mt][0] = *(uint32_t*)&sT[row * PADT + k0 + tIG * 2];
            af[mt][1] = *(uint32_t*)&sT[(row + 8) * PADT + k0 + tIG * 2];
            af[mt][2] = *(uint32_t*)&sT[row * PADT + k0 + tIG * 2 + 8];
            af[mt][3] = *(uint32_t*)&sT[(row + 8) * PADT + k0 + tIG * 2 + 8];
        }
#pragma unroll
        for (int nt = 0; nt < 4; nt++) {
            int n = wc * 32 + nt * 8 + gID;
            bfr[nt][0] = *(uint32_t*)&sB[n * PADA + tIG * 2];
            bfr[nt][1] = *(uint32_t*)&sB[n * PADA + tIG * 2 + 8];
        }
#pragma unroll
        for (int mt = 0; mt < 2; mt++)
#pragma unroll
            for (int nt = 0; nt < 4; nt++)
                mma_bf16(acc[mt][nt], af[mt], bfr[nt]);
    }
    __syncthreads();

    // ---- epilogue 2: m = silu(acc + b2) -> sMsg; vector scatter-add ----
#pragma unroll
    for (int mt = 0; mt < 2; mt++)
#pragma unroll
        for (int nt = 0; nt < 4; nt++) {
            int row = wr * 32 + mt * 16 + gID;
            int col = wc * 32 + nt * 8 + tIG * 2;
            float bb0 = b2[col], bb1 = b2[col + 1];
            sMsg[row * PADM + col]           = siluf(acc[mt][nt][0] + bb0);
            sMsg[row * PADM + col + 1]       = siluf(acc[mt][nt][1] + bb1);
            sMsg[(row + 8) * PADM + col]     = siluf(acc[mt][nt][2] + bb0);
            sMsg[(row + 8) * PADM + col + 1] = siluf(acc[mt][nt][3] + bb1);
        }
    __syncthreads();
#pragma unroll
    for (int it = 0; it < 8; it++) {
        int idx = tid + it * 256;           // 2048 float4s
        int r = idx >> 5, c4 = (idx & 31) * 4;
        float4 m = *(float4*)&sMsg[r * PADM + c4];
        red_v4(&g_agg[(size_t)sDst[r] * H + c4], m);
    }
}

// ===================== node kernel (bf16 mma + LN) =====================
__global__ __launch_bounds__(256) void k_node(int layer,
        const float* b1, const float* b2, const float* lng, const float* lnb) {
    __shared__ __align__(16) unsigned char smbuf[64 * PADM * 4];
    __shared__ float sMu[64], sRs[64];
    __nv_bfloat16* sA = (__nv_bfloat16*)smbuf;
    __nv_bfloat16* sB = (__nv_bfloat16*)(smbuf + 3072);
    __nv_bfloat16* sT = (__nv_bfloat16*)(smbuf + 9216);
    float* sX = (float*)smbuf;

    int tid = threadIdx.x;
    int lane = tid & 31, warp = tid >> 5;
    int gID = lane >> 2, tIG = lane & 3;
    int wr = warp >> 2, wc = warp & 3;
    int v0 = blockIdx.x * 64;

    float acc[2][4][4];
#pragma unroll
    for (int mt = 0; mt < 2; mt++)
#pragma unroll
        for (int nt = 0; nt < 4; nt++)
#pragma unroll
            for (int q = 0; q < 4; q++) acc[mt][nt][q] = 0.f;

    const __nv_bfloat16* w1t = &g_nw1t[layer][0][0];

    // ---- stage 1: concat(h,agg)[64x256] @ nw1 ----
    for (int ch = 0; ch < 16; ch++) {
        int k0 = ch * 16;
        __syncthreads();
#pragma unroll
        for (int it = 0; it < 4; it++) {
            int idx = tid + it * 256;
            int n = idx >> 3, p = idx & 7;
            *(uint32_t*)&sB[n * PADA + p * 2] = *(const uint32_t*)&w1t[n * 256 + k0 + p * 2];
        }
#pragma unroll
        for (int it = 0; it < 2; it++) {
            int idx = tid + it * 256;
            int r = idx >> 3, p = idx & 7;
            int vv = v0 + r; if (vv >= NV) vv = NV - 1;
            int k = k0 + p * 2;
            const float* hp = (k0 < 128) ? &g_h[(size_t)vv * H + k]
                                         : &g_agg[(size_t)vv * H + (k - 128)];
            *(uint32_t*)&sA[r * PADA + p * 2] = packbf(hp[0], hp[1]);
        }
        __syncthreads();

        uint32_t af[2][4], bfr[4][2];
#pragma unroll
        for (int mt = 0; mt < 2; mt++) {
            int row = wr * 32 + mt * 16 + gID;
            af[mt][0] = *(uint32_t*)&sA[row * PADA + tIG * 2];
            af[mt][1] = *(uint32_t*)&sA[(row + 8) * PADA + tIG * 2];
            af[mt][2] = *(uint32_t*)&sA[row * PADA + tIG * 2 + 8];
            af[mt][3] = *(uint32_t*)&sA[(row + 8) * PADA + tIG * 2 + 8];
        }
#pragma unroll
        for (int nt = 0; nt < 4; nt++) {
            int n = wc * 32 + nt * 8 + gID;
            bfr[nt][0] = *(uint32_t*)&sB[n * PADA + tIG * 2];
            bfr[nt][1] = *(uint32_t*)&sB[n * PADA + tIG * 2 + 8];
        }
#pragma unroll
        for (int mt = 0; mt < 2; mt++)
#pragma unroll
            for (int nt = 0; nt < 4; nt++)
                mma_bf16(acc[mt][nt], af[mt], bfr[nt]);
    }
    __syncthreads();

    // ---- epilogue 1: t1 = silu(acc + b1) ----
#pragma unroll
    for (int mt = 0; mt < 2; mt++)
#pragma unroll
        for (int nt = 0; nt < 4; nt++) {
            int row = wr * 32 + mt * 16 + gID;
            int col = wc * 32 + nt * 8 + tIG * 2;
            float bb0 = b1[col], bb1 = b1[col + 1];
            *(uint32_t*)&sT[row * PADT + col] =
                packbf(siluf(acc[mt][nt][0] + bb0), siluf(acc[mt][nt][1] + bb1));
            *(uint32_t*)&sT[(row + 8) * PADT + col] =
                packbf(siluf(acc[mt][nt][2] + bb0), siluf(acc[mt][nt][3] + bb1));
#pragma unroll
            for (int q = 0; q < 4; q++) acc[mt][nt][q] = 0.f;
        }

    const __nv_bfloat16* w2t = &g_nw2t[layer][0][0];

    // ---- stage 2 ----
    for (int ch = 0; ch < 8; ch++) {
        int k0 = ch * 16;
        __syncthreads();
#pragma unroll
        for (int it = 0; it < 4; it++) {
            int idx = tid + it * 256;
            int n = idx >> 3, p = idx & 7;
            *(uint32_t*)&sB[n * PADA + p * 2] = *(const uint32_t*)&w2t[n * H + k0 + p * 2];
        }
        __syncthreads();

        uint32_t af[2][4], bfr[4][2];
#pragma unroll
        for (int mt = 0; mt < 2; mt++) {
            int row = wr * 32 + mt * 16 + gID;
            af[mt][0] = *(uint32_t*)&sT[row * PADT + k0 + tIG * 2];
            af[mt][1] = *(uint32_t*)&sT[(row + 8) * PADT + k0 + tIG * 2];
            af[mt][2] = *(uint32_t*)&sT[row * PADT + k0 + tIG * 2 + 8];
            af[mt][3] = *(uint32_t*)&sT[(row + 8) * PADT + k0 + tIG * 2 + 8];
        }
#pragma unroll
        for (int nt = 0; nt < 4; nt++) {
            int n = wc * 32 + nt * 8 + gID;
            bfr[nt][0] = *(uint32_t*)&sB[n * PADA + tIG * 2];
            bfr[nt][1] = *(uint32_t*)&sB[n * PADA + tIG * 2 + 8];
        }
#pragma unroll
        for (int mt = 0; mt < 2; mt++)
#pragma unroll
            for (int nt = 0; nt < 4; nt++)
                mma_bf16(acc[mt][nt], af[mt], bfr[nt]);
    }
    __syncthreads();

    // ---- residual + x -> sX ----
    float xv[2][4][4];
#pragma unroll
    for (int mt = 0; mt < 2; mt++)
#pragma unroll
        for (int nt = 0; nt < 4; nt++) {
            int row = wr * 32 + mt * 16 + gID;
            int col = wc * 32 + nt * 8 + tIG * 2;
            float bb0 = b2[col], bb1 = b2[col + 1];
            int va = v0 + row; if (va >= NV) va = NV - 1;
            int vb = v0 + row + 8; if (vb >= NV) vb = NV - 1;
            xv[mt][nt][0] = acc[mt][nt][0] + bb0 + g_h[(size_t)va * H + col];
            xv[mt][nt][1] = acc[mt][nt][1] + bb1 + g_h[(size_t)va * H + col + 1];
            xv[mt][nt][2] = acc[mt][nt][2] + bb0 + g_h[(size_t)vb * H + col];
            xv[mt][nt][3] = acc[mt][nt][3] + bb1 + g_h[(size_t)vb * H + col + 1];
            sX[row * PADM + col]           = xv[mt][nt][0];
            sX[row * PADM + col + 1]       = xv[mt][nt][1];
            sX[(row + 8) * PADM + col]     = xv[mt][nt][2];
            sX[(row + 8) * PADM + col + 1] = xv[mt][nt][3];
        }
    __syncthreads();

    // ---- LN stats: warp per 8 rows, float4 lanes + shuffle ----
    {
#pragma unroll
        for (int i = 0; i < 8; i++) {
            int row = warp * 8 + i;
            float4 v = *(float4*)&sX[row * PADM + lane * 4];
            float s = v.x + v.y + v.z + v.w;
            float s2 = v.x * v.x + v.y * v.y + v.z * v.z + v.w * v.w;
#pragma unroll
            for (int off = 16; off; off >>= 1) {
                s += __shfl_xor_sync(0xffffffffu, s, off);
                s2 += __shfl_xor_sync(0xffffffffu, s2, off);
            }
            if (lane == 0) {
                float mu = s * (1.f / H);
                float var = s2 * (1.f / H) - mu * mu;
                sMu[row] = mu;
                sRs[row] = rsqrtf(var + EPSF);
            }
        }
    }
    __syncthreads();

    // ---- write h ----
#pragma unroll
    for (int mt = 0; mt < 2; mt++)
#pragma unroll
        for (int nt = 0; nt < 4; nt++) {
            int row = wr * 32 + mt * 16 + gID;
            int col = wc * 32 + nt * 8 + tIG * 2;
            float g0 = lng[col], g1 = lng[col + 1];
            float bb0 = lnb[col], bb1 = lnb[col + 1];
            int va = v0 + row, vb = v0 + row + 8;
            if (va < NV) {
                g_h[(size_t)va * H + col]     = g0 * (xv[mt][nt][0] - sMu[row]) * sRs[row] + bb0;
                g_h[(size_t)va * H + col + 1] = g1 * (xv[mt][nt][1] - sMu[row]) * sRs[row] + bb1;
            }
            if (vb < NV) {
                g_h[(size_t)vb * H + col]     = g0 * (xv[mt][nt][2] - sMu[row + 8]) * sRs[row + 8] + bb0;
                g_h[(size_t)vb * H + col + 1] = g1 * (xv[mt][nt][3] - sMu[row + 8]) * sRs[row + 8] + bb1;
            }
        }

    // ---- zero this block's agg rows for next layer ----
#pragma unroll
    for (int it = 0; it < 8; it++) {
        int idx = tid + it * 256;           // 2048 float4s
        int r = idx >> 5, c4 = (idx & 31) * 4;
        int v = v0 + r;
        if (v < NV)
            *(float4*)&g_agg[(size_t)v * H + c4] = make_float4(0.f, 0.f, 0.f, 0.f);
    }
}

// -------- loss --------
__global__ void k_loss(const float* pos0, const float* pos1,
                       const float* opw, const float* opb) {
    __shared__ double sAcc[8];
    int lane = threadIdx.x & 31;
    int wid = threadIdx.x >> 5;
    int gw = blockIdx.x * (blockDim.x >> 5) + wid;
    int nw = gridDim.x * (blockDim.x >> 5);
    double local = 0.0;
    for (int v = gw; v < NV; v += nw) {
        float h0 = g_h[(size_t)v * H + lane];
        float h1 = g_h[(size_t)v * H + lane + 32];
        float h2 = g_h[(size_t)v * H + lane + 64];
        float h3 = g_h[(size_t)v * H + lane + 96];
#pragma unroll
        for (int c = 0; c < 3; c++) {
            float s = h0 * opw[lane * 3 + c] + h1 * opw[(lane + 32) * 3 + c]
                    + h2 * opw[(lane + 64) * 3 + c] + h3 * opw[(lane + 96) * 3 + c];
#pragma unroll
            for (int off = 16; off; off >>= 1) s += __shfl_down_sync(0xffffffffu, s, off);
            if (lane == 0) {
                float vp = s + opb[c];
                float tg = pos1[v * 3 + c] - pos0[v * 3 + c];
                float d = vp - tg;
                local += (double)d * (double)d;
            }
        }
    }
    if (lane == 0) sAcc[wid] = local;
    __syncthreads();
    if (threadIdx.x == 0) {
        double t = 0.0;
        for (int i = 0; i < (int)(blockDim.x >> 5); i++) t += sAcc[i];
        atomicAdd(&g_loss, t);
    }
}

__global__ void k_final(float* out) {
    if (threadIdx.x == 0) out[0] = (float)(g_loss / (double)(NV * 3));
}

extern "C" void kernel_launch(void* const* d_in, const int* in_sizes, int n_in,
                              void* d_out, int out_size) {
    const float* pos0  = (const float*)d_in[0];
    const float* pos1  = (const float*)d_in[1];
    const float* z     = (const float*)d_in[2];
    const float* t     = (const float*)d_in[3];
    const int*   ei    = (const int*)d_in[4];
    const int*   batch = (const int*)d_in[5];
    const float* te_w1 = (const float*)d_in[6];
    const float* te_b1 = (const float*)d_in[7];
    const float* te_w2 = (const float*)d_in[8];
    const float* te_b2 = (const float*)d_in[9];
    const float* cp_w  = (const float*)d_in[10];
    const float* cp_b  = (const float*)d_in[11];
    const float* ew1   = (const float*)d_in[12];
    const float* eb1   = (const float*)d_in[13];
    const float* ew2   = (const float*)d_in[14];
    const float* eb2   = (const float*)d_in[15];
    const float* nw1   = (const float*)d_in[16];
    const float* nb1   = (const float*)d_in[17];
    const float* nw2   = (const float*)d_in[18];
    const float* nb2   = (const float*)d_in[19];
    const float* ln_g  = (const float*)d_in[20];
    const float* ln_b  = (const float*)d_in[21];
    const float* op_w  = (const float*)d_in[22];
    const float* op_b  = (const float*)d_in[23];

    k_prelude<<<1, 32>>>(t, te_w1, te_b1, te_w2, te_b2);
    k_xt<<<(NV * 3 + 255) / 256, 256>>>(pos0, pos1, t);
    k_wt<<<1568, 256>>>(ew1, ew2, nw1, nw2);
    k_h0<<<(NV + 63) / 64, 128>>>(z, batch, cp_w, cp_b);
    k_zero_agg<<<(NV * H / 4 + 255) / 256, 256>>>();

    for (int l = 0; l < NLAYERS; l++) {
        k_edge<<<NE / 64, 256>>>(ei, l, eb1 + (size_t)l * H, eb2 + (size_t)l * H);
        k_node<<<(NV + 63) / 64, 256>>>(l,
            nb1 + (size_t)l * H, nb2 + (size_t)l * H,
            ln_g + (size_t)l * H, ln_b + (size_t)l * H);
    }

    k_loss<<<256, 256>>>(pos0, pos1, op_w, op_b);
    k_final<<<1, 1>>>((float*)d_out);
}

// round 3
// speedup vs baseline: 5.8699x; 1.3446x over previous
#include <cuda_runtime.h>
#include <cuda_bf16.h>
#include <math.h>
#include <stdint.h>

#define NV 50000
#define NE 800000
#define H 128
#define LATD 64
#define TDIM 16
#define NLAYERS 4
#define EPSF 1e-5f

#define PADA 24    // bf16 per row in k16 tiles (48B stride: ldmatrix conflict-free)
#define PADT 136   // bf16 per row t1 (272B stride: conflict-free)
#define PADM 132   // f32 per row message staging
#define EBM 128    // edge block tile rows
#define ESMEM 61952

// -------- scratch --------
__device__ float g_h[NV * H];
__device__ __nv_bfloat16 g_hb[NV * H];
__device__ float g_agg[NV * H];
__device__ float g_xt[NV * 3];
__device__ float g_temb[TDIM];
__device__ float g_h0tab[8][H];
__device__ double g_loss;

__device__ __nv_bfloat16 g_ew1t[NLAYERS][H][272];
__device__ __nv_bfloat16 g_ew2t[NLAYERS][H][H];
__device__ __nv_bfloat16 g_nw1t[NLAYERS][H][256];
__device__ __nv_bfloat16 g_nw2t[NLAYERS][H][H];

__device__ __forceinline__ float siluf(float x) { return x / (1.f + expf(-x)); }

__device__ __forceinline__ uint32_t packbf(float x, float y) {
    __nv_bfloat162 h = __floats2bfloat162_rn(x, y);
    return *(uint32_t*)&h;
}

__device__ __forceinline__ void mma_bf16(float* c, const uint32_t* a, const uint32_t* b) {
    asm volatile(
        "mma.sync.aligned.m16n8k16.row.col.f32.bf16.bf16.f32 "
        "{%0,%1,%2,%3}, {%4,%5,%6,%7}, {%8,%9}, {%0,%1,%2,%3};\n"
        : "+f"(c[0]), "+f"(c[1]), "+f"(c[2]), "+f"(c[3])
        : "r"(a[0]), "r"(a[1]), "r"(a[2]), "r"(a[3]), "r"(b[0]), "r"(b[1]));
}

__device__ __forceinline__ void ldsm4(uint32_t* r, const void* p) {
    uint32_t a = (uint32_t)__cvta_generic_to_shared(p);
    asm volatile("ldmatrix.sync.aligned.m8n8.x4.shared.b16 {%0,%1,%2,%3}, [%4];"
                 : "=r"(r[0]), "=r"(r[1]), "=r"(r[2]), "=r"(r[3]) : "r"(a));
}

__device__ __forceinline__ void cp16(void* smem, const void* gmem) {
    uint32_t s = (uint32_t)__cvta_generic_to_shared(smem);
    asm volatile("cp.async.cg.shared.global [%0], [%1], 16;" :: "r"(s), "l"(gmem));
}
#define CP_COMMIT() asm volatile("cp.async.commit_group;")
#define CP_WAIT(n)  asm volatile("cp.async.wait_group %0;" :: "n"(n))

__device__ __forceinline__ void red_v4(float* addr, float4 m) {
    asm volatile("red.global.add.v4.f32 [%0], {%1,%2,%3,%4};"
                 :: "l"(addr), "f"(m.x), "f"(m.y), "f"(m.z), "f"(m.w) : "memory");
}

// -------- prelude --------
__global__ void k_prelude(const float* t, const float* w1, const float* b1,
                          const float* w2, const float* b2) {
    __shared__ float s1[TDIM];
    if (threadIdx.x == 0) g_loss = 0.0;
    float ts = t[0];
    int i = threadIdx.x;
    if (i < TDIM) s1[i] = siluf(ts * w1[i] + b1[i]);
    __syncthreads();
    if (i < TDIM) {
        float acc = b2[i];
#pragma unroll
        for (int k = 0; k < TDIM; k++) acc += s1[k] * w2[k * TDIM + i];
        g_temb[i] = acc;
    }
}

__global__ void k_xt(const float* pos0, const float* pos1, const float* t) {
    int i = blockIdx.x * blockDim.x + threadIdx.x;
    if (i < NV * 3) {
        float ts = t[0];
        g_xt[i] = (1.f - ts) * pos0[i] + ts * pos1[i];
    }
}

// -------- weight transpose/convert --------
__global__ void k_wt(const float* ew1, const float* ew2, const float* nw1, const float* nw2) {
    int i = blockIdx.x * 256 + threadIdx.x;
    const int S1 = NLAYERS * H * 272;
    const int S2 = NLAYERS * H * H;
    const int S3 = NLAYERS * H * 256;
    if (i < S1) {
        int l = i / (H * 272), r = i % (H * 272), n = r / 272, k = r % 272;
        float v = (k < 259) ? ew1[((size_t)l * 259 + k) * H + n] : 0.f;
        g_ew1t[l][n][k] = __float2bfloat16(v);
    } else if (i < S1 + S2) {
        int j = i - S1;
        int l = j / (H * H), r = j % (H * H), n = r / H, k = r % H;
        g_ew2t[l][n][k] = __float2bfloat16(ew2[((size_t)l * H + k) * H + n]);
    } else if (i < S1 + S2 + S3) {
        int j = i - S1 - S2;
        int l = j / (H * 256), r = j % (H * 256), n = r / 256, k = r % 256;
        g_nw1t[l][n][k] = __float2bfloat16(nw1[((size_t)l * 256 + k) * H + n]);
    } else if (i < S1 + S2 + S3 + S2) {
        int j = i - S1 - S2 - S3;
        int l = j / (H * H), r = j % (H * H), n = r / H, k = r % H;
        g_nw2t[l][n][k] = __float2bfloat16(nw2[((size_t)l * H + k) * H + n]);
    }
}

// -------- h0 table (only 8 distinct rows) + gather --------
__global__ void k_h0tab(const float* z, const float* w, const float* b) {
    __shared__ float sz[8][LATD];
    int tid = threadIdx.x;  // 128
    for (int i = tid; i < 8 * LATD; i += 128) sz[i >> 6][i & 63] = z[i];
    __syncthreads();
#pragma unroll
    for (int bb = 0; bb < 8; bb++) {
        float acc = b[tid];
#pragma unroll 16
        for (int k = 0; k < LATD; k++) acc += sz[bb][k] * w[k * H + tid];
#pragma unroll
        for (int k = 0; k < TDIM; k++) acc += g_temb[k] * w[(LATD + k) * H + tid];
        g_h0tab[bb][tid] = acc;
    }
}

__global__ void k_h0g(const int* batch) {
    int idx = blockIdx.x * 256 + threadIdx.x;
    if (idx < NV * 32) {
        int v = idx >> 5, c4 = (idx & 31) * 4;
        float4 h4 = *(const float4*)&g_h0tab[batch[v]][c4];
        *(float4*)&g_h[(size_t)v * H + c4] = h4;
        uint2 p = make_uint2(packbf(h4.x, h4.y), packbf(h4.z, h4.w));
        *(uint2*)&g_hb[(size_t)v * H + c4] = p;
    }
}

__global__ void k_zero_agg() {
    int i = blockIdx.x * blockDim.x + threadIdx.x;
    if (i < NV * H / 4) ((float4*)g_agg)[i] = make_float4(0.f, 0.f, 0.f, 0.f);
}

// ===================== edge kernel =====================
__global__ __launch_bounds__(256, 2) void k_edge(const int* ei, int layer,
                                                 const float* b1, const float* b2) {
    extern __shared__ __align__(16) unsigned char dyn[];
    __nv_bfloat16* sA = (__nv_bfloat16*)dyn;            // [2][128][PADA]
    __nv_bfloat16* sB = sA + 2 * EBM * PADA;            // [2][128][PADA]
    __nv_bfloat16* sT = sB + 2 * 128 * PADA;            // [128][PADT]
    float* sMsg = (float*)sT;                           // [64][PADM] alias
    int* sDst = (int*)(dyn + 59392);
    int* sSrc = sDst + EBM;
    float* sDp = (float*)(sSrc + EBM);                  // [128][3]

    int tid = threadIdx.x;
    int lane = tid & 31, warp = tid >> 5;
    int wr = warp >> 2, wc = warp & 3;                  // m64 x n32 warp tile
    int e0 = blockIdx.x * EBM;
    int r2 = tid >> 1, seg = tid & 1;

    if (tid < EBM) { sSrc[tid] = ei[e0 + tid]; sDst[tid] = ei[NE + e0 + tid]; }
    __syncthreads();
    for (int idx = tid; idx < EBM * 3; idx += 256) {
        int r = idx / 3, c = idx - r * 3;
        sDp[idx] = g_xt[sDst[r] * 3 + c] - g_xt[sSrc[r] * 3 + c];
    }
    __syncthreads();

    const __nv_bfloat16* w1t = &g_ew1t[layer][0][0];
    const __nv_bfloat16* w2t = &g_ew2t[layer][0][0];

    float acc[4][4][4];
#pragma unroll
    for (int mt = 0; mt < 4; mt++)
#pragma unroll
        for (int nt = 0; nt < 4; nt++)
#pragma unroll
            for (int q = 0; q < 4; q++) acc[mt][nt][q] = 0.f;

    int arow = lane & 15, acol = (lane >> 4) * 8;
    int brow = (lane & 7) + ((lane >> 4) * 8), bcol = ((lane >> 3) & 1) * 8;

    // ---------- stage 1: e_in[128x259] @ w1 ----------
    auto issueA = [&](int ch, int buf) {
        __nv_bfloat16* dstp = sA + buf * EBM * PADA + r2 * PADA + seg * 8;
        if (ch < 16) {
            int k0 = ch * 16;
            const __nv_bfloat16* gp = (k0 < 128)
                ? &g_hb[(size_t)sDst[r2] * H + k0 + seg * 8]
                : &g_hb[(size_t)sSrc[r2] * H + (k0 - 128) + seg * 8];
            cp16(dstp, gp);
        } else {
            uint32_t v0 = 0, v1 = 0;
            if (seg == 0) {
                v0 = packbf(sDp[r2 * 3], sDp[r2 * 3 + 1]);
                v1 = packbf(sDp[r2 * 3 + 2], 0.f);
            }
            uint4 q = make_uint4(v0, v1, 0u, 0u);
            *(uint4*)dstp = q;
        }
    };
    auto issueB = [&](int ch, int buf, const __nv_bfloat16* w, int stride) {
        cp16(sB + buf * 128 * PADA + r2 * PADA + seg * 8,
             w + (size_t)r2 * stride + ch * 16 + seg * 8);
    };
    auto compute = [&](const __nv_bfloat16* At, const __nv_bfloat16* Bt) {
        uint32_t af[4][4], bfr[4][2];
#pragma unroll
        for (int mt = 0; mt < 4; mt++)
            ldsm4(af[mt], At + (wr * 64 + mt * 16 + arow) * PADA + acol);
#pragma unroll
        for (int np = 0; np < 2; np++) {
            uint32_t rr[4];
            ldsm4(rr, Bt + (wc * 32 + np * 16 + brow) * PADA + bcol);
            bfr[np * 2][0] = rr[0]; bfr[np * 2][1] = rr[1];
            bfr[np * 2 + 1][0] = rr[2]; bfr[np * 2 + 1][1] = rr[3];
        }
#pragma unroll
        for (int mt = 0; mt < 4; mt++)
#pragma unroll
            for (int nt = 0; nt < 4; nt++)
                mma_bf16(acc[mt][nt], af[mt], bfr[nt]);
    };

    issueA(0, 0); issueB(0, 0, w1t, 272); CP_COMMIT();
    for (int ch = 0; ch < 17; ch++) {
        int cur = ch & 1;
        if (ch < 16) {
            issueA(ch + 1, cur ^ 1); issueB(ch + 1, cur ^ 1, w1t, 272);
            CP_COMMIT(); CP_WAIT(1);
        } else {
            CP_WAIT(0);
        }
        __syncthreads();
        compute(sA + cur * EBM * PADA, sB + cur * 128 * PADA);
        __syncthreads();
    }

    // ---------- epilogue 1: t1 = silu(acc + b1) -> sT ----------
#pragma unroll
    for (int mt = 0; mt < 4; mt++)
#pragma unroll
        for (int nt = 0; nt < 4; nt++) {
            int row = wr * 64 + mt * 16 + (lane >> 2);
            int col = wc * 32 + nt * 8 + (lane & 3) * 2;
            float bb0 = b1[col], bb1 = b1[col + 1];
            *(uint32_t*)&sT[row * PADT + col] =
                packbf(siluf(acc[mt][nt][0] + bb0), siluf(acc[mt][nt][1] + bb1));
            *(uint32_t*)&sT[(row + 8) * PADT + col] =
                packbf(siluf(acc[mt][nt][2] + bb0), siluf(acc[mt][nt][3] + bb1));
#pragma unroll
            for (int q = 0; q < 4; q++) acc[mt][nt][q] = 0.f;
        }

    // ---------- stage 2: t1[128x128] @ w2 ----------
    issueB(0, 0, w2t, H); CP_COMMIT();
    for (int ch = 0; ch < 8; ch++) {
        int cur = ch & 1;
        if (ch < 7) { issueB(ch + 1, cur ^ 1, w2t, H); CP_COMMIT(); CP_WAIT(1); }
        else CP_WAIT(0);
        __syncthreads();
        int k0 = ch * 16;
        uint32_t af[4][4], bfr[4][2];
        const __nv_bfloat16* Bt = sB + cur * 128 * PADA;
#pragma unroll
        for (int mt = 0; mt < 4; mt++)
            ldsm4(af[mt], sT + (wr * 64 + mt * 16 + arow) * PADT + k0 + acol);
#pragma unroll
        for (int np = 0; np < 2; np++) {
            uint32_t rr[4];
            ldsm4(rr, Bt + (wc * 32 + np * 16 + brow) * PADA + bcol);
            bfr[np * 2][0] = rr[0]; bfr[np * 2][1] = rr[1];
            bfr[np * 2 + 1][0] = rr[2]; bfr[np * 2 + 1][1] = rr[3];
        }
#pragma unroll
        for (int mt = 0; mt < 4; mt++)
#pragma unroll
            for (int nt = 0; nt < 4; nt++)
                mma_bf16(acc[mt][nt], af[mt], bfr[nt]);
        __syncthreads();
    }

    // ---------- epilogue 2: messages -> staged v4 scatter (2 passes) ----------
#pragma unroll
    for (int p = 0; p < 2; p++) {
        if (wr == p) {
#pragma unroll
            for (int mt = 0; mt < 4; mt++)
#pragma unroll
                for (int nt = 0; nt < 4; nt++) {
                    int row = mt * 16 + (lane >> 2);          // local 0..63
                    int col = wc * 32 + nt * 8 + (lane & 3) * 2;
                    float bb0 = b2[col], bb1 = b2[col + 1];
                    sMsg[row * PADM + col]           = siluf(acc[mt][nt][0] + bb0);
                    sMsg[row * PADM + col + 1]       = siluf(acc[mt][nt][1] + bb1);
                    sMsg[(row + 8) * PADM + col]     = siluf(acc[mt][nt][2] + bb0);
                    sMsg[(row + 8) * PADM + col + 1] = siluf(acc[mt][nt][3] + bb1);
                }
        }
        __syncthreads();
#pragma unroll
        for (int it = 0; it < 8; it++) {
            int idx = tid + it * 256;                 // 2048 float4s
            int r = idx >> 5, c4 = (idx & 31) * 4;
            float4 m = *(float4*)&sMsg[r * PADM + c4];
            red_v4(&g_agg[(size_t)sDst[p * 64 + r] * H + c4], m);
        }
        __syncthreads();
    }
}

// ===================== node kernel (bf16 mma + LN) =====================
__global__ __launch_bounds__(256) void k_node(int layer,
        const float* b1, const float* b2, const float* lng, const float* lnb) {
    __shared__ __align__(16) unsigned char smbuf[64 * PADM * 4];
    __shared__ float sMu[64], sRs[64];
    __nv_bfloat16* sA = (__nv_bfloat16*)smbuf;
    __nv_bfloat16* sB = (__nv_bfloat16*)(smbuf + 3072);
    __nv_bfloat16* sT = (__nv_bfloat16*)(smbuf + 9216);
    float* sX = (float*)smbuf;

    int tid = threadIdx.x;
    int lane = tid & 31, warp = tid >> 5;
    int gID = lane >> 2, tIG = lane & 3;
    int wr = warp >> 2, wc = warp & 3;
    int v0 = blockIdx.x * 64;

    float acc[2][4][4];
#pragma unroll
    for (int mt = 0; mt < 2; mt++)
#pragma unroll
        for (int nt = 0; nt < 4; nt++)
#pragma unroll
            for (int q = 0; q < 4; q++) acc[mt][nt][q] = 0.f;

    const __nv_bfloat16* w1t = &g_nw1t[layer][0][0];

    for (int ch = 0; ch < 16; ch++) {
        int k0 = ch * 16;
        __syncthreads();
#pragma unroll
        for (int it = 0; it < 4; it++) {
            int idx = tid + it * 256;
            int n = idx >> 3, p = idx & 7;
            *(uint32_t*)&sB[n * PADA + p * 2] = *(const uint32_t*)&w1t[n * 256 + k0 + p * 2];
        }
#pragma unroll
        for (int it = 0; it < 2; it++) {
            int idx = tid + it * 256;
            int r = idx >> 3, p = idx & 7;
            int vv = v0 + r; if (vv >= NV) vv = NV - 1;
            int k = k0 + p * 2;
            const float* hp = (k0 < 128) ? &g_h[(size_t)vv * H + k]
                                         : &g_agg[(size_t)vv * H + (k - 128)];
            *(uint32_t*)&sA[r * PADA + p * 2] = packbf(hp[0], hp[1]);
        }
        __syncthreads();

        uint32_t af[2][4], bfr[4][2];
#pragma unroll
        for (int mt = 0; mt < 2; mt++) {
            int row = wr * 32 + mt * 16 + (lane & 15);
            ldsm4(af[mt], sA + row * PADA + (lane >> 4) * 8);
        }
#pragma unroll
        for (int np = 0; np < 2; np++) {
            uint32_t rr[4];
            int n = wc * 32 + np * 16 + (lane & 7) + (lane >> 4) * 8;
            ldsm4(rr, sB + n * PADA + ((lane >> 3) & 1) * 8);
            bfr[np * 2][0] = rr[0]; bfr[np * 2][1] = rr[1];
            bfr[np * 2 + 1][0] = rr[2]; bfr[np * 2 + 1][1] = rr[3];
        }
#pragma unroll
        for (int mt = 0; mt < 2; mt++)
#pragma unroll
            for (int nt = 0; nt < 4; nt++)
                mma_bf16(acc[mt][nt], af[mt], bfr[nt]);
    }
    __syncthreads();

#pragma unroll
    for (int mt = 0; mt < 2; mt++)
#pragma unroll
        for (int nt = 0; nt < 4; nt++) {
            int row = wr * 32 + mt * 16 + gID;
            int col = wc * 32 + nt * 8 + tIG * 2;
            float bb0 = b1[col], bb1 = b1[col + 1];
            *(uint32_t*)&sT[row * PADT + col] =
                packbf(siluf(acc[mt][nt][0] + bb0), siluf(acc[mt][nt][1] + bb1));
            *(uint32_t*)&sT[(row + 8) * PADT + col] =
                packbf(siluf(acc[mt][nt][2] + bb0), siluf(acc[mt][nt][3] + bb1));
#pragma unroll
            for (int q = 0; q < 4; q++) acc[mt][nt][q] = 0.f;
        }

    const __nv_bfloat16* w2t = &g_nw2t[layer][0][0];

    for (int ch = 0; ch < 8; ch++) {
        int k0 = ch * 16;
        __syncthreads();
#pragma unroll
        for (int it = 0; it < 4; it++) {
            int idx = tid + it * 256;
            int n = idx >> 3, p = idx & 7;
            *(uint32_t*)&sB[n * PADA + p * 2] = *(const uint32_t*)&w2t[n * H + k0 + p * 2];
        }
        __syncthreads();

        uint32_t af[2][4], bfr[4][2];
#pragma unroll
        for (int mt = 0; mt < 2; mt++) {
            int row = wr * 32 + mt * 16 + (lane & 15);
            ldsm4(af[mt], sT + row * PADT + k0 + (lane >> 4) * 8);
        }
#pragma unroll
        for (int np = 0; np < 2; np++) {
            uint32_t rr[4];
            int n = wc * 32 + np * 16 + (lane & 7) + (lane >> 4) * 8;
            ldsm4(rr, sB + n * PADA + ((lane >> 3) & 1) * 8);
            bfr[np * 2][0] = rr[0]; bfr[np * 2][1] = rr[1];
            bfr[np * 2 + 1][0] = rr[2]; bfr[np * 2 + 1][1] = rr[3];
        }
#pragma unroll
        for (int mt = 0; mt < 2; mt++)
#pragma unroll
            for (int nt = 0; nt < 4; nt++)
                mma_bf16(acc[mt][nt], af[mt], bfr[nt]);
    }
    __syncthreads();

    float xv[2][4][4];
#pragma unroll
    for (int mt = 0; mt < 2; mt++)
#pragma unroll
        for (int nt = 0; nt < 4; nt++) {
            int row = wr * 32 + mt * 16 + gID;
            int col = wc * 32 + nt * 8 + tIG * 2;
            float bb0 = b2[col], bb1 = b2[col + 1];
            int va = v0 + row; if (va >= NV) va = NV - 1;
            int vb = v0 + row + 8; if (vb >= NV) vb = NV - 1;
            xv[mt][nt][0] = acc[mt][nt][0] + bb0 + g_h[(size_t)va * H + col];
            xv[mt][nt][1] = acc[mt][nt][1] + bb1 + g_h[(size_t)va * H + col + 1];
            xv[mt][nt][2] = acc[mt][nt][2] + bb0 + g_h[(size_t)vb * H + col];
            xv[mt][nt][3] = acc[mt][nt][3] + bb1 + g_h[(size_t)vb * H + col + 1];
            sX[row * PADM + col]           = xv[mt][nt][0];
            sX[row * PADM + col + 1]       = xv[mt][nt][1];
            sX[(row + 8) * PADM + col]     = xv[mt][nt][2];
            sX[(row + 8) * PADM + col + 1] = xv[mt][nt][3];
        }
    __syncthreads();

#pragma unroll
    for (int i = 0; i < 8; i++) {
        int row = warp * 8 + i;
        float4 v = *(float4*)&sX[row * PADM + lane * 4];
        float s = v.x + v.y + v.z + v.w;
        float s2 = v.x * v.x + v.y * v.y + v.z * v.z + v.w * v.w;
#pragma unroll
        for (int off = 16; off; off >>= 1) {
            s += __shfl_xor_sync(0xffffffffu, s, off);
            s2 += __shfl_xor_sync(0xffffffffu, s2, off);
        }
        if (lane == 0) {
            float mu = s * (1.f / H);
            float var = s2 * (1.f / H) - mu * mu;
            sMu[row] = mu;
            sRs[row] = rsqrtf(var + EPSF);
        }
    }
    __syncthreads();

#pragma unroll
    for (int mt = 0; mt < 2; mt++)
#pragma unroll
        for (int nt = 0; nt < 4; nt++) {
            int row = wr * 32 + mt * 16 + gID;
            int col = wc * 32 + nt * 8 + tIG * 2;
            float g0 = lng[col], g1 = lng[col + 1];
            float bb0 = lnb[col], bb1 = lnb[col + 1];
            int va = v0 + row, vb = v0 + row + 8;
            if (va < NV) {
                float o0 = g0 * (xv[mt][nt][0] - sMu[row]) * sRs[row] + bb0;
                float o1 = g1 * (xv[mt][nt][1] - sMu[row]) * sRs[row] + bb1;
                g_h[(size_t)va * H + col] = o0;
                g_h[(size_t)va * H + col + 1] = o1;
                *(uint32_t*)&g_hb[(size_t)va * H + col] = packbf(o0, o1);
            }
            if (vb < NV) {
                float o0 = g0 * (xv[mt][nt][2] - sMu[row + 8]) * sRs[row + 8] + bb0;
                float o1 = g1 * (xv[mt][nt][3] - sMu[row + 8]) * sRs[row + 8] + bb1;
                g_h[(size_t)vb * H + col] = o0;
                g_h[(size_t)vb * H + col + 1] = o1;
                *(uint32_t*)&g_hb[(size_t)vb * H + col] = packbf(o0, o1);
            }
        }

#pragma unroll
    for (int it = 0; it < 8; it++) {
        int idx = tid + it * 256;
        int r = idx >> 5, c4 = (idx & 31) * 4;
        int v = v0 + r;
        if (v < NV)
            *(float4*)&g_agg[(size_t)v * H + c4] = make_float4(0.f, 0.f, 0.f, 0.f);
    }
}

// -------- loss --------
__global__ void k_loss(const float* pos0, const float* pos1,
                       const float* opw, const float* opb) {
    __shared__ double sAcc[8];
    int lane = threadIdx.x & 31;
    int wid = threadIdx.x >> 5;
    int gw = blockIdx.x * (blockDim.x >> 5) + wid;
    int nw = gridDim.x * (blockDim.x >> 5);
    double local = 0.0;
    for (int v = gw; v < NV; v += nw) {
        float h0 = g_h[(size_t)v * H + lane];
        float h1 = g_h[(size_t)v * H + lane + 32];
        float h2 = g_h[(size_t)v * H + lane + 64];
        float h3 = g_h[(size_t)v * H + lane + 96];
#pragma unroll
        for (int c = 0; c < 3; c++) {
            float s = h0 * opw[lane * 3 + c] + h1 * opw[(lane + 32) * 3 + c]
                    + h2 * opw[(lane + 64) * 3 + c] + h3 * opw[(lane + 96) * 3 + c];
#pragma unroll
            for (int off = 16; off; off >>= 1) s += __shfl_down_sync(0xffffffffu, s, off);
            if (lane == 0) {
                float vp = s + opb[c];
                float tg = pos1[v * 3 + c] - pos0[v * 3 + c];
                float d = vp - tg;
                local += (double)d * (double)d;
            }
        }
    }
    if (lane == 0) sAcc[wid] = local;
    __syncthreads();
    if (threadIdx.x == 0) {
        double t = 0.0;
        for (int i = 0; i < (int)(blockDim.x >> 5); i++) t += sAcc[i];
        atomicAdd(&g_loss, t);
    }
}

__global__ void k_final(float* out) {
    if (threadIdx.x == 0) out[0] = (float)(g_loss / (double)(NV * 3));
}

extern "C" void kernel_launch(void* const* d_in, const int* in_sizes, int n_in,
                              void* d_out, int out_size) {
    const float* pos0  = (const float*)d_in[0];
    const float* pos1  = (const float*)d_in[1];
    const float* z     = (const float*)d_in[2];
    const float* t     = (const float*)d_in[3];
    const int*   ei    = (const int*)d_in[4];
    const int*   batch = (const int*)d_in[5];
    const float* te_w1 = (const float*)d_in[6];
    const float* te_b1 = (const float*)d_in[7];
    const float* te_w2 = (const float*)d_in[8];
    const float* te_b2 = (const float*)d_in[9];
    const float* cp_w  = (const float*)d_in[10];
    const float* cp_b  = (const float*)d_in[11];
    const float* ew1   = (const float*)d_in[12];
    const float* eb1   = (const float*)d_in[13];
    const float* ew2   = (const float*)d_in[14];
    const float* eb2   = (const float*)d_in[15];
    const float* nw1   = (const float*)d_in[16];
    const float* nb1   = (const float*)d_in[17];
    const float* nw2   = (const float*)d_in[18];
    const float* nb2   = (const float*)d_in[19];
    const float* ln_g  = (const float*)d_in[20];
    const float* ln_b  = (const float*)d_in[21];
    const float* op_w  = (const float*)d_in[22];
    const float* op_b  = (const float*)d_in[23];

    cudaFuncSetAttribute(k_edge, cudaFuncAttributeMaxDynamicSharedMemorySize, ESMEM);

    k_prelude<<<1, 32>>>(t, te_w1, te_b1, te_w2, te_b2);
    k_xt<<<(NV * 3 + 255) / 256, 256>>>(pos0, pos1, t);
    k_wt<<<1568, 256>>>(ew1, ew2, nw1, nw2);
    k_h0tab<<<1, 128>>>(z, cp_w, cp_b);
    k_h0g<<<(NV * 32 + 255) / 256, 256>>>(batch);
    k_zero_agg<<<(NV * H / 4 + 255) / 256, 256>>>();

    for (int l = 0; l < NLAYERS; l++) {
        k_edge<<<NE / EBM, 256, ESMEM>>>(ei, l, eb1 + (size_t)l * H, eb2 + (size_t)l * H);
        k_node<<<(NV + 63) / 64, 256>>>(l,
            nb1 + (size_t)l * H, nb2 + (size_t)l * H,
            ln_g + (size_t)l * H, ln_b + (size_t)l * H);
    }

    k_loss<<<256, 256>>>(pos0, pos1, op_w, op_b);
    k_final<<<1, 1>>>((float*)d_out);
}

// round 4
// speedup vs baseline: 6.0032x; 1.0227x over previous
#include <cuda_runtime.h>
#include <cuda_bf16.h>
#include <math.h>
#include <stdint.h>

#define NV 50000
#define NE 800000
#define H 128
#define LATD 64
#define TDIM 16
#define NLAYERS 4
#define EPSF 1e-5f

#define PADA 24
#define PADT 136
#define PADM 132
#define EBM 128
#define ESMEM 61952
#define NSMEM (33792 + 16384)
#define NBLK_SCAN 196

// -------- scratch --------
__device__ float g_h[NV * H];
__device__ __nv_bfloat16 g_hb[NV * H];
__device__ float g_xt[NV * 3];
__device__ float g_temb[TDIM];
__device__ float g_h0tab[8][H];
__device__ double g_loss;

// sorted-edge machinery
__device__ int g_cnt[NV];
__device__ int g_rowptr[NV + 1];
__device__ int g_blk[256];
__device__ int g_esrc[NE];
__device__ int g_edst[NE];
__device__ __nv_bfloat16 g_msg[(size_t)NE * H];   // 204.8 MB

__device__ __nv_bfloat16 g_ew1t[NLAYERS][H][272];
__device__ __nv_bfloat16 g_ew2t[NLAYERS][H][H];
__device__ __nv_bfloat16 g_nw1t[NLAYERS][H][256];
__device__ __nv_bfloat16 g_nw2t[NLAYERS][H][H];

__device__ __forceinline__ float siluf(float x) { return x / (1.f + expf(-x)); }

__device__ __forceinline__ uint32_t packbf(float x, float y) {
    __nv_bfloat162 h = __floats2bfloat162_rn(x, y);
    return *(uint32_t*)&h;
}

__device__ __forceinline__ void mma_bf16(float* c, const uint32_t* a, const uint32_t* b) {
    asm volatile(
        "mma.sync.aligned.m16n8k16.row.col.f32.bf16.bf16.f32 "
        "{%0,%1,%2,%3}, {%4,%5,%6,%7}, {%8,%9}, {%0,%1,%2,%3};\n"
        : "+f"(c[0]), "+f"(c[1]), "+f"(c[2]), "+f"(c[3])
        : "r"(a[0]), "r"(a[1]), "r"(a[2]), "r"(a[3]), "r"(b[0]), "r"(b[1]));
}

__device__ __forceinline__ void ldsm4(uint32_t* r, const void* p) {
    uint32_t a = (uint32_t)__cvta_generic_to_shared(p);
    asm volatile("ldmatrix.sync.aligned.m8n8.x4.shared.b16 {%0,%1,%2,%3}, [%4];"
                 : "=r"(r[0]), "=r"(r[1]), "=r"(r[2]), "=r"(r[3]) : "r"(a));
}

__device__ __forceinline__ void cp16(void* smem, const void* gmem) {
    uint32_t s = (uint32_t)__cvta_generic_to_shared(smem);
    asm volatile("cp.async.cg.shared.global [%0], [%1], 16;" :: "r"(s), "l"(gmem));
}
#define CP_COMMIT() asm volatile("cp.async.commit_group;")
#define CP_WAIT(n)  asm volatile("cp.async.wait_group %0;" :: "n"(n))

// -------- prelude --------
__global__ void k_prelude(const float* t, const float* w1, const float* b1,
                          const float* w2, const float* b2) {
    __shared__ float s1[TDIM];
    if (threadIdx.x == 0) g_loss = 0.0;
    float ts = t[0];
    int i = threadIdx.x;
    if (i < TDIM) s1[i] = siluf(ts * w1[i] + b1[i]);
    __syncthreads();
    if (i < TDIM) {
        float acc = b2[i];
#pragma unroll
        for (int k = 0; k < TDIM; k++) acc += s1[k] * w2[k * TDIM + i];
        g_temb[i] = acc;
    }
}

__global__ void k_xt(const float* pos0, const float* pos1, const float* t) {
    int i = blockIdx.x * blockDim.x + threadIdx.x;
    if (i < NV * 3) {
        float ts = t[0];
        g_xt[i] = (1.f - ts) * pos0[i] + ts * pos1[i];
    }
}

// -------- weight transpose/convert --------
__global__ void k_wt(const float* ew1, const float* ew2, const float* nw1, const float* nw2) {
    int i = blockIdx.x * 256 + threadIdx.x;
    const int S1 = NLAYERS * H * 272;
    const int S2 = NLAYERS * H * H;
    const int S3 = NLAYERS * H * 256;
    if (i < S1) {
        int l = i / (H * 272), r = i % (H * 272), n = r / 272, k = r % 272;
        float v = (k < 259) ? ew1[((size_t)l * 259 + k) * H + n] : 0.f;
        g_ew1t[l][n][k] = __float2bfloat16(v);
    } else if (i < S1 + S2) {
        int j = i - S1;
        int l = j / (H * H), r = j % (H * H), n = r / H, k = r % H;
        g_ew2t[l][n][k] = __float2bfloat16(ew2[((size_t)l * H + k) * H + n]);
    } else if (i < S1 + S2 + S3) {
        int j = i - S1 - S2;
        int l = j / (H * 256), r = j % (H * 256), n = r / 256, k = r % 256;
        g_nw1t[l][n][k] = __float2bfloat16(nw1[((size_t)l * 256 + k) * H + n]);
    } else if (i < S1 + S2 + S3 + S2) {
        int j = i - S1 - S2 - S3;
        int l = j / (H * H), r = j % (H * H), n = r / H, k = r % H;
        g_nw2t[l][n][k] = __float2bfloat16(nw2[((size_t)l * H + k) * H + n]);
    }
}

// -------- h0 table + gather --------
__global__ void k_h0tab(const float* z, const float* w, const float* b) {
    __shared__ float sz[8][LATD];
    int tid = threadIdx.x;
    for (int i = tid; i < 8 * LATD; i += 128) sz[i >> 6][i & 63] = z[i];
    __syncthreads();
#pragma unroll
    for (int bb = 0; bb < 8; bb++) {
        float acc = b[tid];
#pragma unroll 16
        for (int k = 0; k < LATD; k++) acc += sz[bb][k] * w[k * H + tid];
#pragma unroll
        for (int k = 0; k < TDIM; k++) acc += g_temb[k] * w[(LATD + k) * H + tid];
        g_h0tab[bb][tid] = acc;
    }
}

__global__ void k_h0g(const int* batch) {
    int idx = blockIdx.x * 256 + threadIdx.x;
    if (idx < NV * 32) {
        int v = idx >> 5, c4 = (idx & 31) * 4;
        float4 h4 = *(const float4*)&g_h0tab[batch[v]][c4];
        *(float4*)&g_h[(size_t)v * H + c4] = h4;
        uint2 p = make_uint2(packbf(h4.x, h4.y), packbf(h4.z, h4.w));
        *(uint2*)&g_hb[(size_t)v * H + c4] = p;
    }
}

// -------- counting sort of edges by dst --------
__global__ void k_zero_cnt() {
    int i = blockIdx.x * 256 + threadIdx.x;
    if (i < NV) g_cnt[i] = 0;
}

__global__ void k_hist(const int* ei) {
    int e = blockIdx.x * 256 + threadIdx.x;
    if (e < NE) atomicAdd(&g_cnt[ei[NE + e]], 1);
}

__global__ void k_scan1() {
    __shared__ int sh[256];
    int t = threadIdx.x;
    int i = blockIdx.x * 256 + t;
    int v = (i < NV) ? g_cnt[i] : 0;
    sh[t] = v;
    __syncthreads();
#pragma unroll
    for (int off = 1; off < 256; off <<= 1) {
        int x = (t >= off) ? sh[t - off] : 0;
        __syncthreads();
        sh[t] += x;
        __syncthreads();
    }
    if (i < NV) g_rowptr[i] = sh[t] - v;          // exclusive
    if (t == 255) g_blk[blockIdx.x] = sh[255];
}

__global__ void k_scan2() {
    __shared__ int sh[256];
    int t = threadIdx.x;
    int v = (t < NBLK_SCAN) ? g_blk[t] : 0;
    sh[t] = v;
    __syncthreads();
#pragma unroll
    for (int off = 1; off < 256; off <<= 1) {
        int x = (t >= off) ? sh[t - off] : 0;
        __syncthreads();
        sh[t] += x;
        __syncthreads();
    }
    if (t < NBLK_SCAN) g_blk[t] = sh[t] - v;      // exclusive
}

__global__ void k_scan3() {
    int i = blockIdx.x * 256 + threadIdx.x;
    if (i < NV) g_rowptr[i] += g_blk[blockIdx.x];
    if (i == 0) g_rowptr[NV] = NE;
}

__global__ void k_sortidx(const int* ei) {
    int e = blockIdx.x * 256 + threadIdx.x;
    if (e < NE) {
        int d = ei[NE + e];
        int s = ei[e];
        int p = g_rowptr[d] + atomicAdd(&g_cnt[d], 1);
        g_esrc[p] = s;
        g_edst[p] = d;
    }
}

// ===================== edge kernel (sorted edges -> linear msg) =====================
__global__ __launch_bounds__(256, 2) void k_edge(int layer,
                                                 const float* b1, const float* b2) {
    extern __shared__ __align__(16) unsigned char dyn[];
    __nv_bfloat16* sA = (__nv_bfloat16*)dyn;            // [2][128][PADA]
    __nv_bfloat16* sB = sA + 2 * EBM * PADA;            // [2][128][PADA]
    __nv_bfloat16* sT = sB + 2 * 128 * PADA;            // [128][PADT]
    int* sDst = (int*)(dyn + 59392);
    int* sSrc = sDst + EBM;
    float* sDp = (float*)(sSrc + EBM);                  // [128][3]

    int tid = threadIdx.x;
    int lane = tid & 31, warp = tid >> 5;
    int wr = warp >> 2, wc = warp & 3;
    int e0 = blockIdx.x * EBM;
    int r2 = tid >> 1, seg = tid & 1;

    if (tid < EBM) { sSrc[tid] = g_esrc[e0 + tid]; sDst[tid] = g_edst[e0 + tid]; }
    __syncthreads();
    for (int idx = tid; idx < EBM * 3; idx += 256) {
        int r = idx / 3, c = idx - r * 3;
        sDp[idx] = g_xt[sDst[r] * 3 + c] - g_xt[sSrc[r] * 3 + c];
    }
    __syncthreads();

    const __nv_bfloat16* w1t = &g_ew1t[layer][0][0];
    const __nv_bfloat16* w2t = &g_ew2t[layer][0][0];

    float acc[4][4][4];
#pragma unroll
    for (int mt = 0; mt < 4; mt++)
#pragma unroll
        for (int nt = 0; nt < 4; nt++)
#pragma unroll
            for (int q = 0; q < 4; q++) acc[mt][nt][q] = 0.f;

    int arow = lane & 15, acol = (lane >> 4) * 8;
    int brow = (lane & 7) + ((lane >> 4) * 8), bcol = ((lane >> 3) & 1) * 8;

    auto issueA = [&](int ch, int buf) {
        __nv_bfloat16* dstp = sA + buf * EBM * PADA + r2 * PADA + seg * 8;
        if (ch < 16) {
            int k0 = ch * 16;
            const __nv_bfloat16* gp = (k0 < 128)
                ? &g_hb[(size_t)sDst[r2] * H + k0 + seg * 8]
                : &g_hb[(size_t)sSrc[r2] * H + (k0 - 128) + seg * 8];
            cp16(dstp, gp);
        } else {
            uint32_t v0 = 0, v1 = 0;
            if (seg == 0) {
                v0 = packbf(sDp[r2 * 3], sDp[r2 * 3 + 1]);
                v1 = packbf(sDp[r2 * 3 + 2], 0.f);
            }
            uint4 q = make_uint4(v0, v1, 0u, 0u);
            *(uint4*)dstp = q;
        }
    };
    auto issueB = [&](int ch, int buf, const __nv_bfloat16* w, int stride) {
        cp16(sB + buf * 128 * PADA + r2 * PADA + seg * 8,
             w + (size_t)r2 * stride + ch * 16 + seg * 8);
    };
    auto compute = [&](const __nv_bfloat16* At, const __nv_bfloat16* Bt) {
        uint32_t af[4][4], bfr[4][2];
#pragma unroll
        for (int mt = 0; mt < 4; mt++)
            ldsm4(af[mt], At + (wr * 64 + mt * 16 + arow) * PADA + acol);
#pragma unroll
        for (int np = 0; np < 2; np++) {
            uint32_t rr[4];
            ldsm4(rr, Bt + (wc * 32 + np * 16 + brow) * PADA + bcol);
            bfr[np * 2][0] = rr[0]; bfr[np * 2][1] = rr[1];
            bfr[np * 2 + 1][0] = rr[2]; bfr[np * 2 + 1][1] = rr[3];
        }
#pragma unroll
        for (int mt = 0; mt < 4; mt++)
#pragma unroll
            for (int nt = 0; nt < 4; nt++)
                mma_bf16(acc[mt][nt], af[mt], bfr[nt]);
    };

    // ---------- stage 1 ----------
    issueA(0, 0); issueB(0, 0, w1t, 272); CP_COMMIT();
    for (int ch = 0; ch < 17; ch++) {
        int cur = ch & 1;
        if (ch < 16) {
            issueA(ch + 1, cur ^ 1); issueB(ch + 1, cur ^ 1, w1t, 272);
            CP_COMMIT(); CP_WAIT(1);
        } else {
            CP_WAIT(0);
        }
        __syncthreads();
        compute(sA + cur * EBM * PADA, sB + cur * 128 * PADA);
        __syncthreads();
    }

    // ---------- epilogue 1: t1 -> sT ----------
#pragma unroll
    for (int mt = 0; mt < 4; mt++)
#pragma unroll
        for (int nt = 0; nt < 4; nt++) {
            int row = wr * 64 + mt * 16 + (lane >> 2);
            int col = wc * 32 + nt * 8 + (lane & 3) * 2;
            float bb0 = b1[col], bb1 = b1[col + 1];
            *(uint32_t*)&sT[row * PADT + col] =
                packbf(siluf(acc[mt][nt][0] + bb0), siluf(acc[mt][nt][1] + bb1));
            *(uint32_t*)&sT[(row + 8) * PADT + col] =
                packbf(siluf(acc[mt][nt][2] + bb0), siluf(acc[mt][nt][3] + bb1));
#pragma unroll
            for (int q = 0; q < 4; q++) acc[mt][nt][q] = 0.f;
        }

    // ---------- stage 2 ----------
    issueB(0, 0, w2t, H); CP_COMMIT();
    for (int ch = 0; ch < 8; ch++) {
        int cur = ch & 1;
        if (ch < 7) { issueB(ch + 1, cur ^ 1, w2t, H); CP_COMMIT(); CP_WAIT(1); }
        else CP_WAIT(0);
        __syncthreads();
        int k0 = ch * 16;
        uint32_t af[4][4], bfr[4][2];
        const __nv_bfloat16* Bt = sB + cur * 128 * PADA;
#pragma unroll
        for (int mt = 0; mt < 4; mt++)
            ldsm4(af[mt], sT + (wr * 64 + mt * 16 + arow) * PADT + k0 + acol);
#pragma unroll
        for (int np = 0; np < 2; np++) {
            uint32_t rr[4];
            ldsm4(rr, Bt + (wc * 32 + np * 16 + brow) * PADA + bcol);
            bfr[np * 2][0] = rr[0]; bfr[np * 2][1] = rr[1];
            bfr[np * 2 + 1][0] = rr[2]; bfr[np * 2 + 1][1] = rr[3];
        }
#pragma unroll
        for (int mt = 0; mt < 4; mt++)
#pragma unroll
            for (int nt = 0; nt < 4; nt++)
                mma_bf16(acc[mt][nt], af[mt], bfr[nt]);
        __syncthreads();
    }

    // ---------- epilogue 2: m = silu(acc+b2) -> sT (bf16) -> g_msg ----------
#pragma unroll
    for (int mt = 0; mt < 4; mt++)
#pragma unroll
        for (int nt = 0; nt < 4; nt++) {
            int row = wr * 64 + mt * 16 + (lane >> 2);
            int col = wc * 32 + nt * 8 + (lane & 3) * 2;
            float bb0 = b2[col], bb1 = b2[col + 1];
            *(uint32_t*)&sT[row * PADT + col] =
                packbf(siluf(acc[mt][nt][0] + bb0), siluf(acc[mt][nt][1] + bb1));
            *(uint32_t*)&sT[(row + 8) * PADT + col] =
                packbf(siluf(acc[mt][nt][2] + bb0), siluf(acc[mt][nt][3] + bb1));
        }
    __syncthreads();
#pragma unroll
    for (int it = 0; it < 8; it++) {
        int idx = tid + it * 256;                 // 2048 uint4s
        int r = idx >> 4, c8 = (idx & 15) * 8;
        *(uint4*)&g_msg[(size_t)(e0 + r) * H + c8] = *(uint4*)&sT[r * PADT + c8];
    }
}

// ===================== node kernel: CSR gather-reduce + MLP + LN =====================
__global__ __launch_bounds__(256) void k_node(int layer,
        const float* b1, const float* b2, const float* lng, const float* lnb) {
    extern __shared__ __align__(16) unsigned char dyn[];
    __nv_bfloat16* sA = (__nv_bfloat16*)dyn;                 // [64][PADA]
    __nv_bfloat16* sB = (__nv_bfloat16*)(dyn + 3072);        // [128][PADA]
    __nv_bfloat16* sT = (__nv_bfloat16*)(dyn + 9216);        // [64][PADT]
    float* sX = (float*)dyn;                                 // [64][PADM] alias
    __nv_bfloat16* sAgg = (__nv_bfloat16*)(dyn + 33792);     // [64][128]
    __shared__ float sMu[64], sRs[64];
    __shared__ int sRp[65];

    int tid = threadIdx.x;
    int lane = tid & 31, warp = tid >> 5;
    int gID = lane >> 2, tIG = lane & 3;
    int wr = warp >> 2, wc = warp & 3;
    int v0 = blockIdx.x * 64;

    if (tid < 65) {
        int v = v0 + tid;
        sRp[tid] = g_rowptr[v > NV ? NV : v];
    }
    __syncthreads();

    // ---- CSR gather-reduce: agg rows (fp32 accum -> bf16 smem) ----
#pragma unroll
    for (int i = 0; i < 8; i++) {
        int r = warp * 8 + i;
        float a0 = 0.f, a1 = 0.f, a2 = 0.f, a3 = 0.f;
        int s = sRp[r], e = sRp[r + 1];
        for (int ed = s; ed < e; ed++) {
            uint2 q = *(const uint2*)&g_msg[(size_t)ed * H + lane * 4];
            __nv_bfloat162 q0 = *(__nv_bfloat162*)&q.x;
            __nv_bfloat162 q1 = *(__nv_bfloat162*)&q.y;
            a0 += __bfloat162float(q0.x); a1 += __bfloat162float(q0.y);
            a2 += __bfloat162float(q1.x); a3 += __bfloat162float(q1.y);
        }
        *(uint32_t*)&sAgg[r * 128 + lane * 4]     = packbf(a0, a1);
        *(uint32_t*)&sAgg[r * 128 + lane * 4 + 2] = packbf(a2, a3);
    }
    __syncthreads();

    float acc[2][4][4];
#pragma unroll
    for (int mt = 0; mt < 2; mt++)
#pragma unroll
        for (int nt = 0; nt < 4; nt++)
#pragma unroll
            for (int q = 0; q < 4; q++) acc[mt][nt][q] = 0.f;

    const __nv_bfloat16* w1t = &g_nw1t[layer][0][0];

    for (int ch = 0; ch < 16; ch++) {
        int k0 = ch * 16;
        __syncthreads();
#pragma unroll
        for (int it = 0; it < 4; it++) {
            int idx = tid + it * 256;
            int n = idx >> 3, p = idx & 7;
            *(uint32_t*)&sB[n * PADA + p * 2] = *(const uint32_t*)&w1t[n * 256 + k0 + p * 2];
        }
#pragma unroll
        for (int it = 0; it < 2; it++) {
            int idx = tid + it * 256;
            int r = idx >> 3, p = idx & 7;
            uint32_t val;
            if (k0 < 128) {
                int vv = v0 + r; if (vv >= NV) vv = NV - 1;
                val = *(const uint32_t*)&g_hb[(size_t)vv * H + k0 + p * 2];
            } else {
                val = *(uint32_t*)&sAgg[r * 128 + (k0 - 128) + p * 2];
            }
            *(uint32_t*)&sA[r * PADA + p * 2] = val;
        }
        __syncthreads();

        uint32_t af[2][4], bfr[4][2];
#pragma unroll
        for (int mt = 0; mt < 2; mt++) {
            int row = wr * 32 + mt * 16 + (lane & 15);
            ldsm4(af[mt], sA + row * PADA + (lane >> 4) * 8);
        }
#pragma unroll
        for (int np = 0; np < 2; np++) {
            uint32_t rr[4];
            int n = wc * 32 + np * 16 + (lane & 7) + (lane >> 4) * 8;
            ldsm4(rr, sB + n * PADA + ((lane >> 3) & 1) * 8);
            bfr[np * 2][0] = rr[0]; bfr[np * 2][1] = rr[1];
            bfr[np * 2 + 1][0] = rr[2]; bfr[np * 2 + 1][1] = rr[3];
        }
#pragma unroll
        for (int mt = 0; mt < 2; mt++)
#pragma unroll
            for (int nt = 0; nt < 4; nt++)
                mma_bf16(acc[mt][nt], af[mt], bfr[nt]);
    }
    __syncthreads();

#pragma unroll
    for (int mt = 0; mt < 2; mt++)
#pragma unroll
        for (int nt = 0; nt < 4; nt++) {
            int row = wr * 32 + mt * 16 + gID;
            int col = wc * 32 + nt * 8 + tIG * 2;
            float bb0 = b1[col], bb1 = b1[col + 1];
            *(uint32_t*)&sT[row * PADT + col] =
                packbf(siluf(acc[mt][nt][0] + bb0), siluf(acc[mt][nt][1] + bb1));
            *(uint32_t*)&sT[(row + 8) * PADT + col] =
                packbf(siluf(acc[mt][nt][2] + bb0), siluf(acc[mt][nt][3] + bb1));
#pragma unroll
            for (int q = 0; q < 4; q++) acc[mt][nt][q] = 0.f;
        }

    const __nv_bfloat16* w2t = &g_nw2t[layer][0][0];

    for (int ch = 0; ch < 8; ch++) {
        int k0 = ch * 16;
        __syncthreads();
#pragma unroll
        for (int it = 0; it < 4; it++) {
            int idx = tid + it * 256;
            int n = idx >> 3, p = idx & 7;
            *(uint32_t*)&sB[n * PADA + p * 2] = *(const uint32_t*)&w2t[n * H + k0 + p * 2];
        }
        __syncthreads();

        uint32_t af[2][4], bfr[4][2];
#pragma unroll
        for (int mt = 0; mt < 2; mt++) {
            int row = wr * 32 + mt * 16 + (lane & 15);
            ldsm4(af[mt], sT + row * PADT + k0 + (lane >> 4) * 8);
        }
#pragma unroll
        for (int np = 0; np < 2; np++) {
            uint32_t rr[4];
            int n = wc * 32 + np * 16 + (lane & 7) + (lane >> 4) * 8;
            ldsm4(rr, sB + n * PADA + ((lane >> 3) & 1) * 8);
            bfr[np * 2][0] = rr[0]; bfr[np * 2][1] = rr[1];
            bfr[np * 2 + 1][0] = rr[2]; bfr[np * 2 + 1][1] = rr[3];
        }
#pragma unroll
        for (int mt = 0; mt < 2; mt++)
#pragma unroll
            for (int nt = 0; nt < 4; nt++)
                mma_bf16(acc[mt][nt], af[mt], bfr[nt]);
    }
    __syncthreads();

    float xv[2][4][4];
#pragma unroll
    for (int mt = 0; mt < 2; mt++)
#pragma unroll
        for (int nt = 0; nt < 4; nt++) {
            int row = wr * 32 + mt * 16 + gID;
            int col = wc * 32 + nt * 8 + tIG * 2;
            float bb0 = b2[col], bb1 = b2[col + 1];
            int va = v0 + row; if (va >= NV) va = NV - 1;
            int vb = v0 + row + 8; if (vb >= NV) vb = NV - 1;
            xv[mt][nt][0] = acc[mt][nt][0] + bb0 + g_h[(size_t)va * H + col];
            xv[mt][nt][1] = acc[mt][nt][1] + bb1 + g_h[(size_t)va * H + col + 1];
            xv[mt][nt][2] = acc[mt][nt][2] + bb0 + g_h[(size_t)vb * H + col];
            xv[mt][nt][3] = acc[mt][nt][3] + bb1 + g_h[(size_t)vb * H + col + 1];
            sX[row * PADM + col]           = xv[mt][nt][0];
            sX[row * PADM + col + 1]       = xv[mt][nt][1];
            sX[(row + 8) * PADM + col]     = xv[mt][nt][2];
            sX[(row + 8) * PADM + col + 1] = xv[mt][nt][3];
        }
    __syncthreads();

#pragma unroll
    for (int i = 0; i < 8; i++) {
        int row = warp * 8 + i;
        float4 v = *(float4*)&sX[row * PADM + lane * 4];
        float s = v.x + v.y + v.z + v.w;
        float s2 = v.x * v.x + v.y * v.y + v.z * v.z + v.w * v.w;
#pragma unroll
        for (int off = 16; off; off >>= 1) {
            s += __shfl_xor_sync(0xffffffffu, s, off);
            s2 += __shfl_xor_sync(0xffffffffu, s2, off);
        }
        if (lane == 0) {
            float mu = s * (1.f / H);
            float var = s2 * (1.f / H) - mu * mu;
            sMu[row] = mu;
            sRs[row] = rsqrtf(var + EPSF);
        }
    }
    __syncthreads();

#pragma unroll
    for (int mt = 0; mt < 2; mt++)
#pragma unroll
        for (int nt = 0; nt < 4; nt++) {
            int row = wr * 32 + mt * 16 + gID;
            int col = wc * 32 + nt * 8 + tIG * 2;
            float g0 = lng[col], g1 = lng[col + 1];
            float bb0 = lnb[col], bb1 = lnb[col + 1];
            int va = v0 + row, vb = v0 + row + 8;
            if (va < NV) {
                float o0 = g0 * (xv[mt][nt][0] - sMu[row]) * sRs[row] + bb0;
                float o1 = g1 * (xv[mt][nt][1] - sMu[row]) * sRs[row] + bb1;
                g_h[(size_t)va * H + col] = o0;
                g_h[(size_t)va * H + col + 1] = o1;
                *(uint32_t*)&g_hb[(size_t)va * H + col] = packbf(o0, o1);
            }
            if (vb < NV) {
                float o0 = g0 * (xv[mt][nt][2] - sMu[row + 8]) * sRs[row + 8] + bb0;
                float o1 = g1 * (xv[mt][nt][3] - sMu[row + 8]) * sRs[row + 8] + bb1;
                g_h[(size_t)vb * H + col] = o0;
                g_h[(size_t)vb * H + col + 1] = o1;
                *(uint32_t*)&g_hb[(size_t)vb * H + col] = packbf(o0, o1);
            }
        }
}

// -------- loss --------
__global__ void k_loss(const float* pos0, const float* pos1,
                       const float* opw, const float* opb) {
    __shared__ double sAcc[8];
    int lane = threadIdx.x & 31;
    int wid = threadIdx.x >> 5;
    int gw = blockIdx.x * (blockDim.x >> 5) + wid;
    int nw = gridDim.x * (blockDim.x >> 5);
    double local = 0.0;
    for (int v = gw; v < NV; v += nw) {
        float h0 = g_h[(size_t)v * H + lane];
        float h1 = g_h[(size_t)v * H + lane + 32];
        float h2 = g_h[(size_t)v * H + lane + 64];
        float h3 = g_h[(size_t)v * H + lane + 96];
#pragma unroll
        for (int c = 0; c < 3; c++) {
            float s = h0 * opw[lane * 3 + c] + h1 * opw[(lane + 32) * 3 + c]
                    + h2 * opw[(lane + 64) * 3 + c] + h3 * opw[(lane + 96) * 3 + c];
#pragma unroll
            for (int off = 16; off; off >>= 1) s += __shfl_down_sync(0xffffffffu, s, off);
            if (lane == 0) {
                float vp = s + opb[c];
                float tg = pos1[v * 3 + c] - pos0[v * 3 + c];
                float d = vp - tg;
                local += (double)d * (double)d;
            }
        }
    }
    if (lane == 0) sAcc[wid] = local;
    __syncthreads();
    if (threadIdx.x == 0) {
        double t = 0.0;
        for (int i = 0; i < (int)(blockDim.x >> 5); i++) t += sAcc[i];
        atomicAdd(&g_loss, t);
    }
}

__global__ void k_final(float* out) {
    if (threadIdx.x == 0) out[0] = (float)(g_loss / (double)(NV * 3));
}

extern "C" void kernel_launch(void* const* d_in, const int* in_sizes, int n_in,
                              void* d_out, int out_size) {
    const float* pos0  = (const float*)d_in[0];
    const float* pos1  = (const float*)d_in[1];
    const float* z     = (const float*)d_in[2];
    const float* t     = (const float*)d_in[3];
    const int*   ei    = (const int*)d_in[4];
    const int*   batch = (const int*)d_in[5];
    const float* te_w1 = (const float*)d_in[6];
    const float* te_b1 = (const float*)d_in[7];
    const float* te_w2 = (const float*)d_in[8];
    const float* te_b2 = (const float*)d_in[9];
    const float* cp_w  = (const float*)d_in[10];
    const float* cp_b  = (const float*)d_in[11];
    const float* eb1   = (const float*)d_in[13];
    const float* eb2   = (const float*)d_in[15];
    const float* nb1   = (const float*)d_in[17];
    const float* nb2   = (const float*)d_in[19];
    const float* ln_g  = (const float*)d_in[20];
    const float* ln_b  = (const float*)d_in[21];
    const float* op_w  = (const float*)d_in[22];
    const float* op_b  = (const float*)d_in[23];

    cudaFuncSetAttribute(k_edge, cudaFuncAttributeMaxDynamicSharedMemorySize, ESMEM);
    cudaFuncSetAttribute(k_node, cudaFuncAttributeMaxDynamicSharedMemorySize, NSMEM);

    k_prelude<<<1, 32>>>(t, te_w1, te_b1, te_w2, te_b2);
    k_xt<<<(NV * 3 + 255) / 256, 256>>>(pos0, pos1, t);
    k_wt<<<1568, 256>>>((const float*)d_in[12], (const float*)d_in[14],
                        (const float*)d_in[16], (const float*)d_in[18]);
    k_h0tab<<<1, 128>>>(z, cp_w, cp_b);
    k_h0g<<<(NV * 32 + 255) / 256, 256>>>(batch);

    // counting sort of edges by dst
    k_zero_cnt<<<NBLK_SCAN, 256>>>();
    k_hist<<<(NE + 255) / 256, 256>>>(ei);
    k_scan1<<<NBLK_SCAN, 256>>>();
    k_scan2<<<1, 256>>>();
    k_scan3<<<NBLK_SCAN, 256>>>();
    k_zero_cnt<<<NBLK_SCAN, 256>>>();
    k_sortidx<<<(NE + 255) / 256, 256>>>(ei);

    for (int l = 0; l < NLAYERS; l++) {
        k_edge<<<NE / EBM, 256, ESMEM>>>(l, eb1 + (size_t)l * H, eb2 + (size_t)l * H);
        k_node<<<(NV + 63) / 64, 256, NSMEM>>>(l,
            nb1 + (size_t)l * H, nb2 + (size_t)l * H,
            ln_g + (size_t)l * H, ln_b + (size_t)l * H);
    }

    k_loss<<<256, 256>>>(pos0, pos1, op_w, op_b);
    k_final<<<1, 1>>>((float*)d_out);
}

// round 12
// speedup vs baseline: 6.5897x; 1.0977x over previous
#include <cuda_runtime.h>
#include <cuda_bf16.h>
#include <math.h>
#include <stdint.h>

#define NV 50000
#define NE 800000
#define H 128
#define LATD 64
#define TDIM 16
#define NLAYERS 4
#define EPSF 1e-5f

#define PADA 24
#define PADT 136
#define PADM 132
#define EBM 128
#define NTILE (NE / EBM)

// edge kernel smem layout (bytes)
#define PADW1 296
#define PADW2 136
#define PADAC 40
#define EOFF_W1  0
#define EOFF_W2  75776
#define EOFF_A   110592
#define EOFF_T   131072
#define EOFF_DST 165888
#define EOFF_SRC 166400
#define EOFF_DP  166912
#define ESMEM    168448

#define NSMEM (33792 + 16384)

// -------- scratch --------
__device__ float g_h[NV * H];
__device__ __align__(16) __nv_bfloat16 g_hb[NV * H];
__device__ float g_xt[NV * 3];
__device__ float g_temb[TDIM];
__device__ float g_h0tab[8][H];
__device__ double g_loss;

__device__ int g_cnt[NV];
__device__ int g_rowptr[NV + 1];
__device__ int g_esrc[NE];
__device__ int g_edst[NE];
__device__ __align__(16) __nv_bfloat16 g_msg[(size_t)NE * H];

// edge weights in exactly the resident-smem layout [l][n][k_padded]
__device__ __align__(16) __nv_bfloat16 g_ew1r[NLAYERS * 128 * PADW1];
__device__ __align__(16) __nv_bfloat16 g_ew2r[NLAYERS * 128 * PADW2];
// node weights (transposed [n][k])
__device__ __align__(16) __nv_bfloat16 g_nw1t[NLAYERS][H][256];
__device__ __align__(16) __nv_bfloat16 g_nw2t[NLAYERS][H][H];

__device__ __forceinline__ float siluf(float x) { return __fdividef(x, 1.f + __expf(-x)); }

__device__ __forceinline__ uint32_t packbf(float x, float y) {
    __nv_bfloat162 h = __floats2bfloat162_rn(x, y);
    return *(uint32_t*)&h;
}

__device__ __forceinline__ void mma_bf16(float* c, const uint32_t* a, const uint32_t* b) {
    asm volatile(
        "mma.sync.aligned.m16n8k16.row.col.f32.bf16.bf16.f32 "
        "{%0,%1,%2,%3}, {%4,%5,%6,%7}, {%8,%9}, {%0,%1,%2,%3};\n"
        : "+f"(c[0]), "+f"(c[1]), "+f"(c[2]), "+f"(c[3])
        : "r"(a[0]), "r"(a[1]), "r"(a[2]), "r"(a[3]), "r"(b[0]), "r"(b[1]));
}

__device__ __forceinline__ void ldsm4(uint32_t* r, const void* p) {
    uint32_t a = (uint32_t)__cvta_generic_to_shared(p);
    asm volatile("ldmatrix.sync.aligned.m8n8.x4.shared.b16 {%0,%1,%2,%3}, [%4];"
                 : "=r"(r[0]), "=r"(r[1]), "=r"(r[2]), "=r"(r[3]) : "r"(a));
}

__device__ __forceinline__ void cp16(void* smem, const void* gmem) {
    uint32_t s = (uint32_t)__cvta_generic_to_shared(smem);
    asm volatile("cp.async.cg.shared.global [%0], [%1], 16;" :: "r"(s), "l"(gmem));
}
#define CP_COMMIT() asm volatile("cp.async.commit_group;")
#define CP_WAIT(n)  asm volatile("cp.async.wait_group %0;" :: "n"(n))

// -------- launch 1: prelude (loss, temb, h0 table, zero cnt) --------
__global__ void k_pre(const float* t, const float* tw1, const float* tb1,
                      const float* tw2, const float* tb2,
                      const float* z, const float* cw, const float* cb) {
    __shared__ float s1[TDIM], stemb[TDIM], sz[8][LATD];
    int tid = threadIdx.x;  // 1024
    if (tid == 0) g_loss = 0.0;
    float ts = t[0];
    if (tid < TDIM) s1[tid] = siluf(ts * tw1[tid] + tb1[tid]);
    for (int i = tid; i < 8 * LATD; i += 1024) sz[i >> 6][i & 63] = z[i];
    __syncthreads();
    if (tid < TDIM) {
        float a = tb2[tid];
#pragma unroll
        for (int k = 0; k < TDIM; k++) a += s1[k] * tw2[k * TDIM + tid];
        stemb[tid] = a;
        g_temb[tid] = a;
    }
    __syncthreads();
    {
        int bb = tid >> 7, n = tid & 127;   // 1024 = 8 x 128
        float acc = cb[n];
#pragma unroll 16
        for (int k = 0; k < LATD; k++) acc += sz[bb][k] * cw[k * H + n];
#pragma unroll
        for (int k = 0; k < TDIM; k++) acc += stemb[k] * cw[(LATD + k) * H + n];
        g_h0tab[bb][n] = acc;
    }
    for (int i = tid; i < NV; i += 1024) g_cnt[i] = 0;
}

// -------- launch 2: misc (xt + hist + h0 gather) --------
__global__ void k_misc(const float* pos0, const float* pos1, const float* t,
                       const int* ei, const int* batch) {
    int idx = blockIdx.x * 256 + threadIdx.x;
    if (idx < NV * 3) {
        float ts = t[0];
        g_xt[idx] = (1.f - ts) * pos0[idx] + ts * pos1[idx];
    } else if (idx < NV * 3 + NE) {
        int e = idx - NV * 3;
        atomicAdd(&g_cnt[ei[NE + e]], 1);
    } else {
        int j = idx - NV * 3 - NE;
        if (j < NV * 32) {
            int v = j >> 5, c4 = (j & 31) * 4;
            float4 h4 = *(const float4*)&g_h0tab[batch[v]][c4];
            *(float4*)&g_h[(size_t)v * H + c4] = h4;
            uint2 p = make_uint2(packbf(h4.x, h4.y), packbf(h4.z, h4.w));
            *(uint2*)&g_hb[(size_t)v * H + c4] = p;
        }
    }
}

// -------- launch 3: weight prep --------
__global__ void k_wt(const float* ew1, const float* ew2, const float* nw1, const float* nw2) {
    int i = blockIdx.x * 256 + threadIdx.x;
    const int S1 = NLAYERS * 128 * PADW1;   // 151552
    const int S2 = NLAYERS * 128 * PADW2;   // 69632
    const int S3 = NLAYERS * H * 256;       // 131072
    const int S4 = NLAYERS * H * H;         // 65536
    if (i < S1) {
        int l = i / (128 * PADW1), r = i % (128 * PADW1), n = r / PADW1, k = r % PADW1;
        float v = (k < 259) ? ew1[((size_t)l * 259 + k) * H + n] : 0.f;
        g_ew1r[i] = __float2bfloat16(v);
    } else if (i < S1 + S2) {
        int j = i - S1;
        int l = j / (128 * PADW2), r = j % (128 * PADW2), n = r / PADW2, k = r % PADW2;
        float v = (k < 128) ? ew2[((size_t)l * H + k) * H + n] : 0.f;
        g_ew2r[j] = __float2bfloat16(v);
    } else if (i < S1 + S2 + S3) {
        int j = i - S1 - S2;
        int l = j / (H * 256), r = j % (H * 256), n = r / 256, k = r % 256;
        g_nw1t[l][n][k] = __float2bfloat16(nw1[((size_t)l * 256 + k) * H + n]);
    } else if (i < S1 + S2 + S3 + S4) {
        int j = i - S1 - S2 - S3;
        int l = j / (H * H), r = j % (H * H), n = r / H, k = r % H;
        g_nw2t[l][n][k] = __float2bfloat16(nw2[((size_t)l * H + k) * H + n]);
    }
}

// -------- launch 4: single-block scan of g_cnt -> g_rowptr, re-zero g_cnt --------
__global__ void k_scan() {
    __shared__ int swarp[32];
    __shared__ int scarry;
    int tid = threadIdx.x;  // 1024
    int lane = tid & 31, w = tid >> 5;
    if (tid == 0) scarry = 0;
    __syncthreads();
    for (int base = 0; base < NV; base += 1024) {
        int i = base + tid;
        int v = (i < NV) ? g_cnt[i] : 0;
        int x = v;
#pragma unroll
        for (int off = 1; off < 32; off <<= 1) {
            int y = __shfl_up_sync(0xffffffffu, x, off);
            if (lane >= off) x += y;
        }
        if (lane == 31) swarp[w] = x;
        __syncthreads();
        if (w == 0) {
            int y = swarp[lane];
#pragma unroll
            for (int off = 1; off < 32; off <<= 1) {
                int z2 = __shfl_up_sync(0xffffffffu, y, off);
                if (lane >= off) y += z2;
            }
            swarp[lane] = y;
        }
        __syncthreads();
        int excl = (w > 0 ? swarp[w - 1] : 0) + (x - v);
        if (i < NV) g_rowptr[i] = scarry + excl;
        __syncthreads();
        if (tid == 0) scarry += swarp[31];
        __syncthreads();
    }
    if (tid == 0) g_rowptr[NV] = NE;
    for (int i = tid; i < NV; i += 1024) g_cnt[i] = 0;
}

// -------- launch 5: stable bucket scatter --------
__global__ void k_sortidx(const int* ei) {
    int e = blockIdx.x * 256 + threadIdx.x;
    if (e < NE) {
        int d = ei[NE + e];
        int s = ei[e];
        int p = g_rowptr[d] + atomicAdd(&g_cnt[d], 1);
        g_esrc[p] = s;
        g_edst[p] = d;
    }
}

// ===================== edge kernel: persistent, resident weights =====================
__global__ __launch_bounds__(256) void k_edge(int layer, const float* b1, const float* b2) {
    extern __shared__ __align__(16) unsigned char dyn[];
    __nv_bfloat16* w1r = (__nv_bfloat16*)(dyn + EOFF_W1);   // [128][296]
    __nv_bfloat16* w2r = (__nv_bfloat16*)(dyn + EOFF_W2);   // [128][136]
    __nv_bfloat16* sA  = (__nv_bfloat16*)(dyn + EOFF_A);    // [2][128][40]
    __nv_bfloat16* sT  = (__nv_bfloat16*)(dyn + EOFF_T);    // [128][136]
    int* sDst = (int*)(dyn + EOFF_DST);
    int* sSrc = (int*)(dyn + EOFF_SRC);
    float* sDp = (float*)(dyn + EOFF_DP);

    int tid = threadIdx.x;
    int lane = tid & 31, warp = tid >> 5;
    int wr = warp >> 2, wc = warp & 3;                      // warp tile m64 x n32
    int arow = lane & 15, acol = (lane >> 4) * 8;
    int brow = (lane & 7) + ((lane >> 4) * 8), bcol = ((lane >> 3) & 1) * 8;

    // resident weight load (once per launch)
    const __nv_bfloat16* w1g = g_ew1r + (size_t)layer * 128 * PADW1;
    const __nv_bfloat16* w2g = g_ew2r + (size_t)layer * 128 * PADW2;
    for (int i = tid; i < 128 * PADW1 / 8; i += 256) cp16(w1r + i * 8, w1g + i * 8);
    for (int i = tid; i < 128 * PADW2 / 8; i += 256) cp16(w2r + i * 8, w2g + i * 8);
    CP_COMMIT(); CP_WAIT(0);
    __syncthreads();

    auto loadA = [&](int ch, int buf) {
        int r = tid >> 1, half = tid & 1;
        __nv_bfloat16* dst = sA + buf * 128 * PADAC + r * PADAC + half * 16;
        if (ch < 8) {
            const __nv_bfloat16* src = (ch < 4)
                ? &g_hb[(size_t)sDst[r] * H + ch * 32 + half * 16]
                : &g_hb[(size_t)sSrc[r] * H + (ch - 4) * 32 + half * 16];
            cp16(dst, src);
            cp16(dst + 8, src + 8);
        } else {
            uint4 z = make_uint4(0u, 0u, 0u, 0u);
            if (half == 0) {
                *(uint4*)dst = make_uint4(packbf(sDp[r * 3], sDp[r * 3 + 1]),
                                          packbf(sDp[r * 3 + 2], 0.f), 0u, 0u);
                *(uint4*)(dst + 8) = z;
            } else {
                *(uint4*)dst = z;
                *(uint4*)(dst + 8) = z;
            }
        }
    };

    for (int tile = blockIdx.x; tile < NTILE; tile += gridDim.x) {
        int e0 = tile * EBM;
        __syncthreads();
        if (tid < EBM) { sDst[tid] = g_edst[e0 + tid]; sSrc[tid] = g_esrc[e0 + tid]; }
        __syncthreads();
        for (int i = tid; i < EBM * 3; i += 256) {
            int r = i / 3, c = i - r * 3;
            sDp[i] = g_xt[sDst[r] * 3 + c] - g_xt[sSrc[r] * 3 + c];
        }
        __syncthreads();

        float acc[4][4][4];
#pragma unroll
        for (int mt = 0; mt < 4; mt++)
#pragma unroll
            for (int nt = 0; nt < 4; nt++)
#pragma unroll
                for (int q = 0; q < 4; q++) acc[mt][nt][q] = 0.f;

        // ---------- stage 1: 9 chunks of K=32 vs resident w1r ----------
        loadA(0, 0); CP_COMMIT();
        for (int ch = 0; ch < 9; ch++) {
            if (ch < 8) { loadA(ch + 1, (ch + 1) & 1); CP_COMMIT(); CP_WAIT(1); }
            else        { CP_WAIT(0); }
            __syncthreads();
            const __nv_bfloat16* At = sA + (ch & 1) * 128 * PADAC;
            int k0 = ch * 32;
#pragma unroll
            for (int ks = 0; ks < 32; ks += 16) {
                uint32_t af[4][4], bfr[4][2];
#pragma unroll
                for (int mt = 0; mt < 4; mt++)
                    ldsm4(af[mt], At + (wr * 64 + mt * 16 + arow) * PADAC + ks + acol);
#pragma unroll
                for (int np = 0; np < 2; np++) {
                    uint32_t rr[4];
                    ldsm4(rr, w1r + (wc * 32 + np * 16 + brow) * PADW1 + k0 + ks + bcol);
                    bfr[np * 2][0] = rr[0]; bfr[np * 2][1] = rr[1];
                    bfr[np * 2 + 1][0] = rr[2]; bfr[np * 2 + 1][1] = rr[3];
                }
#pragma unroll
                for (int mt = 0; mt < 4; mt++)
#pragma unroll
                    for (int nt = 0; nt < 4; nt++)
                        mma_bf16(acc[mt][nt], af[mt], bfr[nt]);
            }
            __syncthreads();
        }

        // ---------- epilogue 1: t1 = silu(acc + b1) -> sT ----------
#pragma unroll
        for (int mt = 0; mt < 4; mt++)
#pragma unroll
            for (int nt = 0; nt < 4; nt++) {
                int row = wr * 64 + mt * 16 + (lane >> 2);
                int col = wc * 32 + nt * 8 + (lane & 3) * 2;
                float bb0 = b1[col], bb1 = b1[col + 1];
                *(uint32_t*)&sT[row * PADT + col] =
                    packbf(siluf(acc[mt][nt][0] + bb0), siluf(acc[mt][nt][1] + bb1));
                *(uint32_t*)&sT[(row + 8) * PADT + col] =
                    packbf(siluf(acc[mt][nt][2] + bb0), siluf(acc[mt][nt][3] + bb1));
#pragma unroll
                for (int q = 0; q < 4; q++) acc[mt][nt][q] = 0.f;
            }
        __syncthreads();

        // ---------- stage 2: t1[128x128] @ resident w2r ----------
#pragma unroll
        for (int ch = 0; ch < 4; ch++) {
            int k0 = ch * 32;
#pragma unroll
            for (int ks = 0; ks < 32; ks += 16) {
                uint32_t af[4][4], bfr[4][2];
#pragma unroll
                for (int mt = 0; mt < 4; mt++)
                    ldsm4(af[mt], sT + (wr * 64 + mt * 16 + arow) * PADT + k0 + ks + acol);
#pragma unroll
                for (int np = 0; np < 2; np++) {
                    uint32_t rr[4];
                    ldsm4(rr, w2r + (wc * 32 + np * 16 + brow) * PADW2 + k0 + ks + bcol);
                    bfr[np * 2][0] = rr[0]; bfr[np * 2][1] = rr[1];
                    bfr[np * 2 + 1][0] = rr[2]; bfr[np * 2 + 1][1] = rr[3];
                }
#pragma unroll
                for (int mt = 0; mt < 4; mt++)
#pragma unroll
                    for (int nt = 0; nt < 4; nt++)
                        mma_bf16(acc[mt][nt], af[mt], bfr[nt]);
            }
        }
        __syncthreads();

        // ---------- epilogue 2: m = silu(acc + b2) -> sT -> g_msg ----------
#pragma unroll
        for (int mt = 0; mt < 4; mt++)
#pragma unroll
            for (int nt = 0; nt < 4; nt++) {
                int row = wr * 64 + mt * 16 + (lane >> 2);
                int col = wc * 32 + nt * 8 + (lane & 3) * 2;
                float bb0 = b2[col], bb1 = b2[col + 1];
                *(uint32_t*)&sT[row * PADT + col] =
                    packbf(siluf(acc[mt][nt][0] + bb0), siluf(acc[mt][nt][1] + bb1));
                *(uint32_t*)&sT[(row + 8) * PADT + col] =
                    packbf(siluf(acc[mt][nt][2] + bb0), siluf(acc[mt][nt][3] + bb1));
            }
        __syncthreads();
#pragma unroll
        for (int it = 0; it < 8; it++) {
            int idx = tid + it * 256;
            int r = idx >> 4, c8 = (idx & 15) * 8;
            *(uint4*)&g_msg[(size_t)(e0 + r) * H + c8] = *(uint4*)&sT[r * PADT + c8];
        }
    }
}

// ===================== node kernel (mma.sync + CSR gather + LN) =====================
__global__ __launch_bounds__(256) void k_node(int layer,
        const float* b1, const float* b2, const float* lng, const float* lnb) {
    extern __shared__ __align__(16) unsigned char dynn[];
    __nv_bfloat16* sA = (__nv_bfloat16*)dynn;
    __nv_bfloat16* sB = (__nv_bfloat16*)(dynn + 3072);
    __nv_bfloat16* sT = (__nv_bfloat16*)(dynn + 9216);
    float* sX = (float*)dynn;
    __nv_bfloat16* sAgg = (__nv_bfloat16*)(dynn + 33792);
    __shared__ float sMu[64], sRs[64];
    __shared__ int sRp[65];

    int tid = threadIdx.x;
    int lane = tid & 31, warp = tid >> 5;
    int gID = lane >> 2, tIG = lane & 3;
    int wr = warp >> 2, wc = warp & 3;
    int v0 = blockIdx.x * 64;

    if (tid < 65) {
        int v = v0 + tid;
        sRp[tid] = g_rowptr[v > NV ? NV : v];
    }
    __syncthreads();

#pragma unroll
    for (int i = 0; i < 8; i++) {
        int r = warp * 8 + i;
        float a0 = 0.f, a1 = 0.f, a2 = 0.f, a3 = 0.f;
        int s = sRp[r], e = sRp[r + 1];
        for (int ed = s; ed < e; ed++) {
            uint2 q = *(const uint2*)&g_msg[(size_t)ed * H + lane * 4];
            __nv_bfloat162 q0 = *(__nv_bfloat162*)&q.x;
            __nv_bfloat162 q1 = *(__nv_bfloat162*)&q.y;
            a0 += __bfloat162float(q0.x); a1 += __bfloat162float(q0.y);
            a2 += __bfloat162float(q1.x); a3 += __bfloat162float(q1.y);
        }
        *(uint32_t*)&sAgg[r * 128 + lane * 4]     = packbf(a0, a1);
        *(uint32_t*)&sAgg[r * 128 + lane * 4 + 2] = packbf(a2, a3);
    }
    __syncthreads();

    float acc[2][4][4];
#pragma unroll
    for (int mt = 0; mt < 2; mt++)
#pragma unroll
        for (int nt = 0; nt < 4; nt++)
#pragma unroll
            for (int q = 0; q < 4; q++) acc[mt][nt][q] = 0.f;

    const __nv_bfloat16* w1t = &g_nw1t[layer][0][0];

    for (int ch = 0; ch < 16; ch++) {
        int k0 = ch * 16;
        __syncthreads();
#pragma unroll
        for (int it = 0; it < 4; it++) {
            int idx = tid + it * 256;
            int n = idx >> 3, p = idx & 7;
            *(uint32_t*)&sB[n * PADA + p * 2] = *(const uint32_t*)&w1t[n * 256 + k0 + p * 2];
        }
#pragma unroll
        for (int it = 0; it < 2; it++) {
            int idx = tid + it * 256;
            int r = idx >> 3, p = idx & 7;
            uint32_t val;
            if (k0 < 128) {
                int vv = v0 + r; if (vv >= NV) vv = NV - 1;
                val = *(const uint32_t*)&g_hb[(size_t)vv * H + k0 + p * 2];
            } else {
                val = *(uint32_t*)&sAgg[r * 128 + (k0 - 128) + p * 2];
            }
            *(uint32_t*)&sA[r * PADA + p * 2] = val;
        }
        __syncthreads();

        uint32_t af[2][4], bfr[4][2];
#pragma unroll
        for (int mt = 0; mt < 2; mt++) {
            int rrow = wr * 32 + mt * 16 + (lane & 15);
            ldsm4(af[mt], sA + rrow * PADA + (lane >> 4) * 8);
        }
#pragma unroll
        for (int np = 0; np < 2; np++) {
            uint32_t rr[4];
            int n = wc * 32 + np * 16 + (lane & 7) + (lane >> 4) * 8;
            ldsm4(rr, sB + n * PADA + ((lane >> 3) & 1) * 8);
            bfr[np * 2][0] = rr[0]; bfr[np * 2][1] = rr[1];
            bfr[np * 2 + 1][0] = rr[2]; bfr[np * 2 + 1][1] = rr[3];
        }
#pragma unroll
        for (int mt = 0; mt < 2; mt++)
#pragma unroll
            for (int nt = 0; nt < 4; nt++)
                mma_bf16(acc[mt][nt], af[mt], bfr[nt]);
    }
    __syncthreads();

#pragma unroll
    for (int mt = 0; mt < 2; mt++)
#pragma unroll
        for (int nt = 0; nt < 4; nt++) {
            int rrow = wr * 32 + mt * 16 + gID;
            int col = wc * 32 + nt * 8 + tIG * 2;
            float bb0 = b1[col], bb1 = b1[col + 1];
            *(uint32_t*)&sT[rrow * PADT + col] =
                packbf(siluf(acc[mt][nt][0] + bb0), siluf(acc[mt][nt][1] + bb1));
            *(uint32_t*)&sT[(rrow + 8) * PADT + col] =
                packbf(siluf(acc[mt][nt][2] + bb0), siluf(acc[mt][nt][3] + bb1));
#pragma unroll
            for (int q = 0; q < 4; q++) acc[mt][nt][q] = 0.f;
        }

    const __nv_bfloat16* w2t = &g_nw2t[layer][0][0];

    for (int ch = 0; ch < 8; ch++) {
        int k0 = ch * 16;
        __syncthreads();
#pragma unroll
        for (int it = 0; it < 4; it++) {
            int idx = tid + it * 256;
            int n = idx >> 3, p = idx & 7;
            *(uint32_t*)&sB[n * PADA + p * 2] = *(const uint32_t*)&w2t[n * H + k0 + p * 2];
        }
        __syncthreads();

        uint32_t af[2][4], bfr[4][2];
#pragma unroll
        for (int mt = 0; mt < 2; mt++) {
            int rrow = wr * 32 + mt * 16 + (lane & 15);
            ldsm4(af[mt], sT + rrow * PADT + k0 + (lane >> 4) * 8);
        }
#pragma unroll
        for (int np = 0; np < 2; np++) {
            uint32_t rr[4];
            int n = wc * 32 + np * 16 + (lane & 7) + (lane >> 4) * 8;
            ldsm4(rr, sB + n * PADA + ((lane >> 3) & 1) * 8);
            bfr[np * 2][0] = rr[0]; bfr[np * 2][1] = rr[1];
            bfr[np * 2 + 1][0] = rr[2]; bfr[np * 2 + 1][1] = rr[3];
        }
#pragma unroll
        for (int mt = 0; mt < 2; mt++)
#pragma unroll
            for (int nt = 0; nt < 4; nt++)
                mma_bf16(acc[mt][nt], af[mt], bfr[nt]);
    }
    __syncthreads();

    float xv[2][4][4];
#pragma unroll
    for (int mt = 0; mt < 2; mt++)
#pragma unroll
        for (int nt = 0; nt < 4; nt++) {
            int rrow = wr * 32 + mt * 16 + gID;
            int col = wc * 32 + nt * 8 + tIG * 2;
            float bb0 = b2[col], bb1 = b2[col + 1];
            int va = v0 + rrow; if (va >= NV) va = NV - 1;
            int vb = v0 + rrow + 8; if (vb >= NV) vb = NV - 1;
            xv[mt][nt][0] = acc[mt][nt][0] + bb0 + g_h[(size_t)va * H + col];
            xv[mt][nt][1] = acc[mt][nt][1] + bb1 + g_h[(size_t)va * H + col + 1];
            xv[mt][nt][2] = acc[mt][nt][2] + bb0 + g_h[(size_t)vb * H + col];
            xv[mt][nt][3] = acc[mt][nt][3] + bb1 + g_h[(size_t)vb * H + col + 1];
            sX[rrow * PADM + col]           = xv[mt][nt][0];
            sX[rrow * PADM + col + 1]       = xv[mt][nt][1];
            sX[(rrow + 8) * PADM + col]     = xv[mt][nt][2];
            sX[(rrow + 8) * PADM + col + 1] = xv[mt][nt][3];
        }
    __syncthreads();

#pragma unroll
    for (int i = 0; i < 8; i++) {
        int rrow = warp * 8 + i;
        float4 v = *(float4*)&sX[rrow * PADM + lane * 4];
        float s = v.x + v.y + v.z + v.w;
        float s2 = v.x * v.x + v.y * v.y + v.z * v.z + v.w * v.w;
#pragma unroll
        for (int off = 16; off; off >>= 1) {
            s += __shfl_xor_sync(0xffffffffu, s, off);
            s2 += __shfl_xor_sync(0xffffffffu, s2, off);
        }
        if (lane == 0) {
            float mu = s * (1.f / H);
            float var = s2 * (1.f / H) - mu * mu;
            sMu[rrow] = mu;
            sRs[rrow] = rsqrtf(var + EPSF);
        }
    }
    __syncthreads();

#pragma unroll
    for (int mt = 0; mt < 2; mt++)
#pragma unroll
        for (int nt = 0; nt < 4; nt++) {
            int rrow = wr * 32 + mt * 16 + gID;
            int col = wc * 32 + nt * 8 + tIG * 2;
            float g0 = lng[col], g1 = lng[col + 1];
            float bb0 = lnb[col], bb1 = lnb[col + 1];
            int va = v0 + rrow, vb = v0 + rrow + 8;
            if (va < NV) {
                float o0 = g0 * (xv[mt][nt][0] - sMu[rrow]) * sRs[rrow] + bb0;
                float o1 = g1 * (xv[mt][nt][1] - sMu[rrow]) * sRs[rrow] + bb1;
                g_h[(size_t)va * H + col] = o0;
                g_h[(size_t)va * H + col + 1] = o1;
                *(uint32_t*)&g_hb[(size_t)va * H + col] = packbf(o0, o1);
            }
            if (vb < NV) {
                float o0 = g0 * (xv[mt][nt][2] - sMu[rrow + 8]) * sRs[rrow + 8] + bb0;
                float o1 = g1 * (xv[mt][nt][3] - sMu[rrow + 8]) * sRs[rrow + 8] + bb1;
                g_h[(size_t)vb * H + col] = o0;
                g_h[(size_t)vb * H + col + 1] = o1;
                *(uint32_t*)&g_hb[(size_t)vb * H + col] = packbf(o0, o1);
            }
        }
}

// -------- loss --------
__global__ void k_loss(const float* pos0, const float* pos1,
                       const float* opw, const float* opb) {
    __shared__ double sAcc[8];
    int lane = threadIdx.x & 31;
    int wid = threadIdx.x >> 5;
    int gw = blockIdx.x * (blockDim.x >> 5) + wid;
    int nw = gridDim.x * (blockDim.x >> 5);
    double local = 0.0;
    for (int v = gw; v < NV; v += nw) {
        float h0 = g_h[(size_t)v * H + lane];
        float h1 = g_h[(size_t)v * H + lane + 32];
        float h2 = g_h[(size_t)v * H + lane + 64];
        float h3 = g_h[(size_t)v * H + lane + 96];
#pragma unroll
        for (int c = 0; c < 3; c++) {
            float s = h0 * opw[lane * 3 + c] + h1 * opw[(lane + 32) * 3 + c]
                    + h2 * opw[(lane + 64) * 3 + c] + h3 * opw[(lane + 96) * 3 + c];
#pragma unroll
            for (int off = 16; off; off >>= 1) s += __shfl_down_sync(0xffffffffu, s, off);
            if (lane == 0) {
                float vp = s + opb[c];
                float tg = pos1[v * 3 + c] - pos0[v * 3 + c];
                float d = vp - tg;
                local += (double)d * (double)d;
            }
        }
    }
    if (lane == 0) sAcc[wid] = local;
    __syncthreads();
    if (threadIdx.x == 0) {
        double t = 0.0;
        for (int i = 0; i < (int)(blockDim.x >> 5); i++) t += sAcc[i];
        atomicAdd(&g_loss, t);
    }
}

__global__ void k_final(float* out) {
    if (threadIdx.x == 0) out[0] = (float)(g_loss / (double)(NV * 3));
}

extern "C" void kernel_launch(void* const* d_in, const int* in_sizes, int n_in,
                              void* d_out, int out_size) {
    const float* pos0  = (const float*)d_in[0];
    const float* pos1  = (const float*)d_in[1];
    const float* z     = (const float*)d_in[2];
    const float* t     = (const float*)d_in[3];
    const int*   ei    = (const int*)d_in[4];
    const int*   batch = (const int*)d_in[5];
    const float* te_w1 = (const float*)d_in[6];
    const float* te_b1 = (const float*)d_in[7];
    const float* te_w2 = (const float*)d_in[8];
    const float* te_b2 = (const float*)d_in[9];
    const float* cp_w  = (const float*)d_in[10];
    const float* cp_b  = (const float*)d_in[11];
    const float* eb1   = (const float*)d_in[13];
    const float* eb2   = (const float*)d_in[15];
    const float* nb1   = (const float*)d_in[17];
    const float* nb2   = (const float*)d_in[19];
    const float* ln_g  = (const float*)d_in[20];
    const float* ln_b  = (const float*)d_in[21];
    const float* op_w  = (const float*)d_in[22];
    const float* op_b  = (const float*)d_in[23];

    cudaFuncSetAttribute(k_edge, cudaFuncAttributeMaxDynamicSharedMemorySize, ESMEM);
    cudaFuncSetAttribute(k_node, cudaFuncAttributeMaxDynamicSharedMemorySize, NSMEM);

    // launches 1-5 (so launch 6 = k_edge layer 0 is the ncu-captured kernel)
    k_pre<<<1, 1024>>>(t, te_w1, te_b1, te_w2, te_b2, z, cp_w, cp_b);
    k_misc<<<(NV * 3 + NE + NV * 32 + 255) / 256, 256>>>(pos0, pos1, t, ei, batch);
    k_wt<<<1632, 256>>>((const float*)d_in[12], (const float*)d_in[14],
                        (const float*)d_in[16], (const float*)d_in[18]);
    k_scan<<<1, 1024>>>();
    k_sortidx<<<(NE + 255) / 256, 256>>>(ei);

    for (int l = 0; l < NLAYERS; l++) {
        k_edge<<<148, 256, ESMEM>>>(l, eb1 + (size_t)l * H, eb2 + (size_t)l * H);
        k_node<<<(NV + 63) / 64, 256, NSMEM>>>(l,
            nb1 + (size_t)l * H, nb2 + (size_t)l * H,
            ln_g + (size_t)l * H, ln_b + (size_t)l * H);
    }

    k_loss<<<256, 256>>>(pos0, pos1, op_w, op_b);
    k_final<<<1, 1>>>((float*)d_out);
}

// round 14
// speedup vs baseline: 6.7016x; 1.0170x over previous
#include <cuda_runtime.h>
#include <cuda_bf16.h>
#include <math.h>
#include <stdint.h>

#define NV 50000
#define NE 800000
#define H 128
#define LATD 64
#define TDIM 16
#define NLAYERS 4
#define EPSF 1e-5f

#define PADA 24
#define PADT 136
#define PADM 132
#define EBM 128
#define NTILE (NE / EBM)

// edge kernel smem layout (bytes)
#define PADW1 296
#define PADW2 136
#define PADAC 40
#define EOFF_W1  0
#define EOFF_W2  75776
#define EOFF_A   110592
#define EOFF_T   131072
#define EOFF_DST 165888
#define EOFF_SRC 166400
#define EOFF_DP  166912
#define ESMEM    168448

#define NSMEM (33792 + 16384)

// -------- scratch --------
__device__ float g_h[NV * H];
__device__ __align__(16) __nv_bfloat16 g_hb[NV * H];
__device__ float g_xt[NV * 3];
__device__ float g_h0tab[8][H];
__device__ double g_loss;

__device__ __align__(16) int g_cnt[NV];      // INVARIANT: zero at entry of every kernel_launch
__device__ __align__(16) int g_rowptr[NV + 4];
__device__ int g_esrc[NE];
__device__ int g_edst[NE];
__device__ __align__(16) __nv_bfloat16 g_msg[(size_t)NE * H];

__device__ __align__(16) __nv_bfloat16 g_ew1r[NLAYERS * 128 * PADW1];
__device__ __align__(16) __nv_bfloat16 g_ew2r[NLAYERS * 128 * PADW2];
__device__ __align__(16) __nv_bfloat16 g_nw1t[NLAYERS][H][256];
__device__ __align__(16) __nv_bfloat16 g_nw2t[NLAYERS][H][H];

__device__ __forceinline__ float siluf(float x) { return __fdividef(x, 1.f + __expf(-x)); }

__device__ __forceinline__ uint32_t packbf(float x, float y) {
    __nv_bfloat162 h = __floats2bfloat162_rn(x, y);
    return *(uint32_t*)&h;
}

__device__ __forceinline__ void mma_bf16(float* c, const uint32_t* a, const uint32_t* b) {
    asm volatile(
        "mma.sync.aligned.m16n8k16.row.col.f32.bf16.bf16.f32 "
        "{%0,%1,%2,%3}, {%4,%5,%6,%7}, {%8,%9}, {%0,%1,%2,%3};\n"
        : "+f"(c[0]), "+f"(c[1]), "+f"(c[2]), "+f"(c[3])
        : "r"(a[0]), "r"(a[1]), "r"(a[2]), "r"(a[3]), "r"(b[0]), "r"(b[1]));
}

__device__ __forceinline__ void ldsm4(uint32_t* r, const void* p) {
    uint32_t a = (uint32_t)__cvta_generic_to_shared(p);
    asm volatile("ldmatrix.sync.aligned.m8n8.x4.shared.b16 {%0,%1,%2,%3}, [%4];"
                 : "=r"(r[0]), "=r"(r[1]), "=r"(r[2]), "=r"(r[3]) : "r"(a));
}

__device__ __forceinline__ void cp16(void* smem, const void* gmem) {
    uint32_t s = (uint32_t)__cvta_generic_to_shared(smem);
    asm volatile("cp.async.cg.shared.global [%0], [%1], 16;" :: "r"(s), "l"(gmem));
}
#define CP_COMMIT() asm volatile("cp.async.commit_group;")
#define CP_WAIT(n)  asm volatile("cp.async.wait_group %0;" :: "n"(n))

// ======== launch 1: k_pre — prelude/h0tab (block 0), weights, histogram, xt ========
#define WT_TOTAL (NLAYERS * 128 * PADW1 + NLAYERS * 128 * PADW2 + NLAYERS * H * 256 + NLAYERS * H * H)  // 417792
#define B_WT   1
#define B_HIST (B_WT + WT_TOTAL / 1024)            // 409
#define B_XT   (B_HIST + (NE + 1023) / 1024)       // 1191
#define B_PRE  (B_XT + (NV * 3 + 1023) / 1024)     // 1338

__global__ __launch_bounds__(1024) void k_pre(
        const float* t, const float* tw1, const float* tb1,
        const float* tw2, const float* tb2,
        const float* z, const float* cw, const float* cb,
        const float* pos0, const float* pos1, const int* ei,
        const float* ew1, const float* ew2, const float* nw1, const float* nw2) {
    int b = blockIdx.x, tid = threadIdx.x;
    if (b == 0) {
        __shared__ float s1[TDIM], stemb[TDIM], sz[8][LATD];
        if (tid == 0) g_loss = 0.0;
        float ts = t[0];
        if (tid < TDIM) s1[tid] = siluf(ts * tw1[tid] + tb1[tid]);
        for (int i = tid; i < 8 * LATD; i += 1024) sz[i >> 6][i & 63] = z[i];
        __syncthreads();
        if (tid < TDIM) {
            float a = tb2[tid];
#pragma unroll
            for (int k = 0; k < TDIM; k++) a += s1[k] * tw2[k * TDIM + tid];
            stemb[tid] = a;
        }
        __syncthreads();
        int bb = tid >> 7, n = tid & 127;
        float acc = cb[n];
#pragma unroll 16
        for (int k = 0; k < LATD; k++) acc += sz[bb][k] * cw[k * H + n];
#pragma unroll
        for (int k = 0; k < TDIM; k++) acc += stemb[k] * cw[(LATD + k) * H + n];
        g_h0tab[bb][n] = acc;
    } else if (b < B_HIST) {
        int i = (b - B_WT) * 1024 + tid;
        const int S1 = NLAYERS * 128 * PADW1;
        const int S2 = NLAYERS * 128 * PADW2;
        const int S3 = NLAYERS * H * 256;
        if (i < S1) {
            int l = i / (128 * PADW1), r = i % (128 * PADW1), n = r / PADW1, k = r % PADW1;
            float v = (k < 259) ? ew1[((size_t)l * 259 + k) * H + n] : 0.f;
            g_ew1r[i] = __float2bfloat16(v);
        } else if (i < S1 + S2) {
            int j = i - S1;
            int l = j / (128 * PADW2), r = j % (128 * PADW2), n = r / PADW2, k = r % PADW2;
            float v = (k < 128) ? ew2[((size_t)l * H + k) * H + n] : 0.f;
            g_ew2r[j] = __float2bfloat16(v);
        } else if (i < S1 + S2 + S3) {
            int j = i - S1 - S2;
            int l = j / (H * 256), r = j % (H * 256), n = r / 256, k = r % 256;
            g_nw1t[l][n][k] = __float2bfloat16(nw1[((size_t)l * 256 + k) * H + n]);
        } else {
            int j = i - S1 - S2 - S3;
            int l = j / (H * H), r = j % (H * H), n = r / H, k = r % H;
            g_nw2t[l][n][k] = __float2bfloat16(nw2[((size_t)l * H + k) * H + n]);
        }
    } else if (b < B_XT) {
        int e = (b - B_HIST) * 1024 + tid;
        if (e < NE) atomicAdd(&g_cnt[ei[NE + e]], 1);
    } else {
        int i = (b - B_XT) * 1024 + tid;
        if (i < NV * 3) {
            float ts = t[0];
            g_xt[i] = (1.f - ts) * pos0[i] + ts * pos1[i];
        }
    }
}

// ======== launch 2: k_scan — coarsened exclusive scan cnt -> rowptr; re-zero cnt ====
__global__ __launch_bounds__(1024) void k_scan() {
    __shared__ int swarp[32];
    int tid = threadIdx.x, lane = tid & 31, w = tid >> 5;
    int carry = 0;
    for (int base = 0; base < NV; base += 4096) {
        int i = base + tid * 4;
        int4 v = make_int4(0, 0, 0, 0);
        if (i < NV) v = *(const int4*)&g_cnt[i];
        int s = v.x + v.y + v.z + v.w;
        int x = s;
#pragma unroll
        for (int off = 1; off < 32; off <<= 1) {
            int y = __shfl_up_sync(0xffffffffu, x, off);
            if (lane >= off) x += y;
        }
        if (lane == 31) swarp[w] = x;
        __syncthreads();
        if (w == 0) {
            int y = swarp[lane];
#pragma unroll
            for (int off = 1; off < 32; off <<= 1) {
                int z2 = __shfl_up_sync(0xffffffffu, y, off);
                if (lane >= off) y += z2;
            }
            swarp[lane] = y;
        }
        __syncthreads();
        int wb = (w > 0) ? swarp[w - 1] : 0;
        int tot = swarp[31];
        int excl = carry + wb + (x - s);
        if (i < NV) {
            g_rowptr[i]     = excl;
            g_rowptr[i + 1] = excl + v.x;
            g_rowptr[i + 2] = excl + v.x + v.y;
            g_rowptr[i + 3] = excl + v.x + v.y + v.z;
        }
        carry += tot;
        __syncthreads();   // protect swarp reuse
    }
    if (tid == 0) g_rowptr[NV] = NE;
    for (int i = tid * 4; i < NV; i += 4096)
        *(int4*)&g_cnt[i] = make_int4(0, 0, 0, 0);
}

// ======== launch 3: k_sorth — bucket scatter + h0 gather ========
__global__ void k_sorth(const int* ei, const int* batch) {
    int idx = blockIdx.x * 256 + threadIdx.x;
    if (idx < NE) {
        int d = ei[NE + idx];
        int s = ei[idx];
        int p = g_rowptr[d] + atomicAdd(&g_cnt[d], 1);
        g_esrc[p] = s;
        g_edst[p] = d;
    } else {
        int j = idx - NE;
        if (j < NV * 32) {
            int v = j >> 5, c4 = (j & 31) * 4;
            float4 h4 = *(const float4*)&g_h0tab[batch[v]][c4];
            *(float4*)&g_h[(size_t)v * H + c4] = h4;
            uint2 p = make_uint2(packbf(h4.x, h4.y), packbf(h4.z, h4.w));
            *(uint2*)&g_hb[(size_t)v * H + c4] = p;
        }
    }
}

// ===================== launch 4: edge kernel (persistent, resident weights) ========
__global__ __launch_bounds__(256) void k_edge(int layer, const float* b1, const float* b2) {
    extern __shared__ __align__(16) unsigned char dyn[];
    __nv_bfloat16* w1r = (__nv_bfloat16*)(dyn + EOFF_W1);
    __nv_bfloat16* w2r = (__nv_bfloat16*)(dyn + EOFF_W2);
    __nv_bfloat16* sA  = (__nv_bfloat16*)(dyn + EOFF_A);
    __nv_bfloat16* sT  = (__nv_bfloat16*)(dyn + EOFF_T);
    int* sDst = (int*)(dyn + EOFF_DST);
    int* sSrc = (int*)(dyn + EOFF_SRC);
    float* sDp = (float*)(dyn + EOFF_DP);

    int tid = threadIdx.x;
    int lane = tid & 31, warp = tid >> 5;
    int wr = warp >> 2, wc = warp & 3;
    int arow = lane & 15, acol = (lane >> 4) * 8;
    int brow = (lane & 7) + ((lane >> 4) * 8), bcol = ((lane >> 3) & 1) * 8;

    const __nv_bfloat16* w1g = g_ew1r + (size_t)layer * 128 * PADW1;
    const __nv_bfloat16* w2g = g_ew2r + (size_t)layer * 128 * PADW2;
    for (int i = tid; i < 128 * PADW1 / 8; i += 256) cp16(w1r + i * 8, w1g + i * 8);
    for (int i = tid; i < 128 * PADW2 / 8; i += 256) cp16(w2r + i * 8, w2g + i * 8);
    CP_COMMIT(); CP_WAIT(0);
    __syncthreads();

    auto loadA = [&](int ch, int buf) {
        int r = tid >> 1, half = tid & 1;
        __nv_bfloat16* dst = sA + buf * 128 * PADAC + r * PADAC + half * 16;
        if (ch < 8) {
            const __nv_bfloat16* src = (ch < 4)
                ? &g_hb[(size_t)sDst[r] * H + ch * 32 + half * 16]
                : &g_hb[(size_t)sSrc[r] * H + (ch - 4) * 32 + half * 16];
            cp16(dst, src);
            cp16(dst + 8, src + 8);
        } else {
            uint4 z = make_uint4(0u, 0u, 0u, 0u);
            if (half == 0) {
                *(uint4*)dst = make_uint4(packbf(sDp[r * 3], sDp[r * 3 + 1]),
                                          packbf(sDp[r * 3 + 2], 0.f), 0u, 0u);
                *(uint4*)(dst + 8) = z;
            } else {
                *(uint4*)dst = z;
                *(uint4*)(dst + 8) = z;
            }
        }
    };

    for (int tile = blockIdx.x; tile < NTILE; tile += gridDim.x) {
        int e0 = tile * EBM;
        __syncthreads();
        if (tid < EBM) { sDst[tid] = g_edst[e0 + tid]; sSrc[tid] = g_esrc[e0 + tid]; }
        __syncthreads();
        for (int i = tid; i < EBM * 3; i += 256) {
            int r = i / 3, c = i - r * 3;
            sDp[i] = g_xt[sDst[r] * 3 + c] - g_xt[sSrc[r] * 3 + c];
        }
        __syncthreads();

        float acc[4][4][4];
#pragma unroll
        for (int mt = 0; mt < 4; mt++)
#pragma unroll
            for (int nt = 0; nt < 4; nt++)
#pragma unroll
                for (int q = 0; q < 4; q++) acc[mt][nt][q] = 0.f;

        loadA(0, 0); CP_COMMIT();
        for (int ch = 0; ch < 9; ch++) {
            if (ch < 8) { loadA(ch + 1, (ch + 1) & 1); CP_COMMIT(); CP_WAIT(1); }
            else        { CP_WAIT(0); }
            __syncthreads();
            const __nv_bfloat16* At = sA + (ch & 1) * 128 * PADAC;
            int k0 = ch * 32;
#pragma unroll
            for (int ks = 0; ks < 32; ks += 16) {
                uint32_t af[4][4], bfr[4][2];
#pragma unroll
                for (int mt = 0; mt < 4; mt++)
                    ldsm4(af[mt], At + (wr * 64 + mt * 16 + arow) * PADAC + ks + acol);
#pragma unroll
                for (int np = 0; np < 2; np++) {
                    uint32_t rr[4];
                    ldsm4(rr, w1r + (wc * 32 + np * 16 + brow) * PADW1 + k0 + ks + bcol);
                    bfr[np * 2][0] = rr[0]; bfr[np * 2][1] = rr[1];
                    bfr[np * 2 + 1][0] = rr[2]; bfr[np * 2 + 1][1] = rr[3];
                }
#pragma unroll
                for (int mt = 0; mt < 4; mt++)
#pragma unroll
                    for (int nt = 0; nt < 4; nt++)
                        mma_bf16(acc[mt][nt], af[mt], bfr[nt]);
            }
            __syncthreads();
        }

#pragma unroll
        for (int mt = 0; mt < 4; mt++)
#pragma unroll
            for (int nt = 0; nt < 4; nt++) {
                int row = wr * 64 + mt * 16 + (lane >> 2);
                int col = wc * 32 + nt * 8 + (lane & 3) * 2;
                float bb0 = b1[col], bb1 = b1[col + 1];
                *(uint32_t*)&sT[row * PADT + col] =
                    packbf(siluf(acc[mt][nt][0] + bb0), siluf(acc[mt][nt][1] + bb1));
                *(uint32_t*)&sT[(row + 8) * PADT + col] =
                    packbf(siluf(acc[mt][nt][2] + bb0), siluf(acc[mt][nt][3] + bb1));
#pragma unroll
                for (int q = 0; q < 4; q++) acc[mt][nt][q] = 0.f;
            }
        __syncthreads();

#pragma unroll
        for (int ch = 0; ch < 4; ch++) {
            int k0 = ch * 32;
#pragma unroll
            for (int ks = 0; ks < 32; ks += 16) {
                uint32_t af[4][4], bfr[4][2];
#pragma unroll
                for (int mt = 0; mt < 4; mt++)
                    ldsm4(af[mt], sT + (wr * 64 + mt * 16 + arow) * PADT + k0 + ks + acol);
#pragma unroll
                for (int np = 0; np < 2; np++) {
                    uint32_t rr[4];
                    ldsm4(rr, w2r + (wc * 32 + np * 16 + brow) * PADW2 + k0 + ks + bcol);
                    bfr[np * 2][0] = rr[0]; bfr[np * 2][1] = rr[1];
                    bfr[np * 2 + 1][0] = rr[2]; bfr[np * 2 + 1][1] = rr[3];
                }
#pragma unroll
                for (int mt = 0; mt < 4; mt++)
#pragma unroll
                    for (int nt = 0; nt < 4; nt++)
                        mma_bf16(acc[mt][nt], af[mt], bfr[nt]);
            }
        }
        __syncthreads();

#pragma unroll
        for (int mt = 0; mt < 4; mt++)
#pragma unroll
            for (int nt = 0; nt < 4; nt++) {
                int row = wr * 64 + mt * 16 + (lane >> 2);
                int col = wc * 32 + nt * 8 + (lane & 3) * 2;
                float bb0 = b2[col], bb1 = b2[col + 1];
                *(uint32_t*)&sT[row * PADT + col] =
                    packbf(siluf(acc[mt][nt][0] + bb0), siluf(acc[mt][nt][1] + bb1));
                *(uint32_t*)&sT[(row + 8) * PADT + col] =
                    packbf(siluf(acc[mt][nt][2] + bb0), siluf(acc[mt][nt][3] + bb1));
            }
        __syncthreads();
#pragma unroll
        for (int it = 0; it < 8; it++) {
            int idx = tid + it * 256;
            int r = idx >> 4, c8 = (idx & 15) * 8;
            *(uint4*)&g_msg[(size_t)(e0 + r) * H + c8] = *(uint4*)&sT[r * PADT + c8];
        }
    }
}

// ===================== node kernel (mma.sync + CSR gather + LN) =====================
__global__ __launch_bounds__(256) void k_node(int layer,
        const float* b1, const float* b2, const float* lng, const float* lnb) {
    extern __shared__ __align__(16) unsigned char dynn[];
    __nv_bfloat16* sA = (__nv_bfloat16*)dynn;
    __nv_bfloat16* sB = (__nv_bfloat16*)(dynn + 3072);
    __nv_bfloat16* sT = (__nv_bfloat16*)(dynn + 9216);
    float* sX = (float*)dynn;
    __nv_bfloat16* sAgg = (__nv_bfloat16*)(dynn + 33792);
    __shared__ float sMu[64], sRs[64];
    __shared__ int sRp[65];

    int tid = threadIdx.x;
    int lane = tid & 31, warp = tid >> 5;
    int gID = lane >> 2, tIG = lane & 3;
    int wr = warp >> 2, wc = warp & 3;
    int v0 = blockIdx.x * 64;

    if (tid < 65) {
        int v = v0 + tid;
        sRp[tid] = g_rowptr[v > NV ? NV : v];
    }
    __syncthreads();

#pragma unroll
    for (int i = 0; i < 8; i++) {
        int r = warp * 8 + i;
        float a0 = 0.f, a1 = 0.f, a2 = 0.f, a3 = 0.f;
        int s = sRp[r], e = sRp[r + 1];
        for (int ed = s; ed < e; ed++) {
            uint2 q = *(const uint2*)&g_msg[(size_t)ed * H + lane * 4];
            __nv_bfloat162 q0 = *(__nv_bfloat162*)&q.x;
            __nv_bfloat162 q1 = *(__nv_bfloat162*)&q.y;
            a0 += __bfloat162float(q0.x); a1 += __bfloat162float(q0.y);
            a2 += __bfloat162float(q1.x); a3 += __bfloat162float(q1.y);
        }
        *(uint32_t*)&sAgg[r * 128 + lane * 4]     = packbf(a0, a1);
        *(uint32_t*)&sAgg[r * 128 + lane * 4 + 2] = packbf(a2, a3);
    }
    __syncthreads();

    float acc[2][4][4];
#pragma unroll
    for (int mt = 0; mt < 2; mt++)
#pragma unroll
        for (int nt = 0; nt < 4; nt++)
#pragma unroll
            for (int q = 0; q < 4; q++) acc[mt][nt][q] = 0.f;

    const __nv_bfloat16* w1t = &g_nw1t[layer][0][0];

    for (int ch = 0; ch < 16; ch++) {
        int k0 = ch * 16;
        __syncthreads();
#pragma unroll
        for (int it = 0; it < 4; it++) {
            int idx = tid + it * 256;
            int n = idx >> 3, p = idx & 7;
            *(uint32_t*)&sB[n * PADA + p * 2] = *(const uint32_t*)&w1t[n * 256 + k0 + p * 2];
        }
#pragma unroll
        for (int it = 0; it < 2; it++) {
            int idx = tid + it * 256;
            int r = idx >> 3, p = idx & 7;
            uint32_t val;
            if (k0 < 128) {
                int vv = v0 + r; if (vv >= NV) vv = NV - 1;
                val = *(const uint32_t*)&g_hb[(size_t)vv * H + k0 + p * 2];
            } else {
                val = *(uint32_t*)&sAgg[r * 128 + (k0 - 128) + p * 2];
            }
            *(uint32_t*)&sA[r * PADA + p * 2] = val;
        }
        __syncthreads();

        uint32_t af[2][4], bfr[4][2];
#pragma unroll
        for (int mt = 0; mt < 2; mt++) {
            int rrow = wr * 32 + mt * 16 + (lane & 15);
            ldsm4(af[mt], sA + rrow * PADA + (lane >> 4) * 8);
        }
#pragma unroll
        for (int np = 0; np < 2; np++) {
            uint32_t rr[4];
            int n = wc * 32 + np * 16 + (lane & 7) + (lane >> 4) * 8;
            ldsm4(rr, sB + n * PADA + ((lane >> 3) & 1) * 8);
            bfr[np * 2][0] = rr[0]; bfr[np * 2][1] = rr[1];
            bfr[np * 2 + 1][0] = rr[2]; bfr[np * 2 + 1][1] = rr[3];
        }
#pragma unroll
        for (int mt = 0; mt < 2; mt++)
#pragma unroll
            for (int nt = 0; nt < 4; nt++)
                mma_bf16(acc[mt][nt], af[mt], bfr[nt]);
    }
    __syncthreads();

#pragma unroll
    for (int mt = 0; mt < 2; mt++)
#pragma unroll
        for (int nt = 0; nt < 4; nt++) {
            int rrow = wr * 32 + mt * 16 + gID;
            int col = wc * 32 + nt * 8 + tIG * 2;
            float bb0 = b1[col], bb1 = b1[col + 1];
            *(uint32_t*)&sT[rrow * PADT + col] =
                packbf(siluf(acc[mt][nt][0] + bb0), siluf(acc[mt][nt][1] + bb1));
            *(uint32_t*)&sT[(rrow + 8) * PADT + col] =
                packbf(siluf(acc[mt][nt][2] + bb0), siluf(acc[mt][nt][3] + bb1));
#pragma unroll
            for (int q = 0; q < 4; q++) acc[mt][nt][q] = 0.f;
        }

    const __nv_bfloat16* w2t = &g_nw2t[layer][0][0];

    for (int ch = 0; ch < 8; ch++) {
        int k0 = ch * 16;
        __syncthreads();
#pragma unroll
        for (int it = 0; it < 4; it++) {
            int idx = tid + it * 256;
            int n = idx >> 3, p = idx & 7;
            *(uint32_t*)&sB[n * PADA + p * 2] = *(const uint32_t*)&w2t[n * H + k0 + p * 2];
        }
        __syncthreads();

        uint32_t af[2][4], bfr[4][2];
#pragma unroll
        for (int mt = 0; mt < 2; mt++) {
            int rrow = wr * 32 + mt * 16 + (lane & 15);
            ldsm4(af[mt], sT + rrow * PADT + k0 + (lane >> 4) * 8);
        }
#pragma unroll
        for (int np = 0; np < 2; np++) {
            uint32_t rr[4];
            int n = wc * 32 + np * 16 + (lane & 7) + (lane >> 4) * 8;
            ldsm4(rr, sB + n * PADA + ((lane >> 3) & 1) * 8);
            bfr[np * 2][0] = rr[0]; bfr[np * 2][1] = rr[1];
            bfr[np * 2 + 1][0] = rr[2]; bfr[np * 2 + 1][1] = rr[3];
        }
#pragma unroll
        for (int mt = 0; mt < 2; mt++)
#pragma unroll
            for (int nt = 0; nt < 4; nt++)
                mma_bf16(acc[mt][nt], af[mt], bfr[nt]);
    }
    __syncthreads();

    float xv[2][4][4];
#pragma unroll
    for (int mt = 0; mt < 2; mt++)
#pragma unroll
        for (int nt = 0; nt < 4; nt++) {
            int rrow = wr * 32 + mt * 16 + gID;
            int col = wc * 32 + nt * 8 + tIG * 2;
            float bb0 = b2[col], bb1 = b2[col + 1];
            int va = v0 + rrow; if (va >= NV) va = NV - 1;
            int vb = v0 + rrow + 8; if (vb >= NV) vb = NV - 1;
            xv[mt][nt][0] = acc[mt][nt][0] + bb0 + g_h[(size_t)va * H + col];
            xv[mt][nt][1] = acc[mt][nt][1] + bb1 + g_h[(size_t)va * H + col + 1];
            xv[mt][nt][2] = acc[mt][nt][2] + bb0 + g_h[(size_t)vb * H + col];
            xv[mt][nt][3] = acc[mt][nt][3] + bb1 + g_h[(size_t)vb * H + col + 1];
            sX[rrow * PADM + col]           = xv[mt][nt][0];
            sX[rrow * PADM + col + 1]       = xv[mt][nt][1];
            sX[(rrow + 8) * PADM + col]     = xv[mt][nt][2];
            sX[(rrow + 8) * PADM + col + 1] = xv[mt][nt][3];
        }
    __syncthreads();

#pragma unroll
    for (int i = 0; i < 8; i++) {
        int rrow = warp * 8 + i;
        float4 v = *(float4*)&sX[rrow * PADM + lane * 4];
        float s = v.x + v.y + v.z + v.w;
        float s2 = v.x * v.x + v.y * v.y + v.z * v.z + v.w * v.w;
#pragma unroll
        for (int off = 16; off; off >>= 1) {
            s += __shfl_xor_sync(0xffffffffu, s, off);
            s2 += __shfl_xor_sync(0xffffffffu, s2, off);
        }
        if (lane == 0) {
            float mu = s * (1.f / H);
            float var = s2 * (1.f / H) - mu * mu;
            sMu[rrow] = mu;
            sRs[rrow] = rsqrtf(var + EPSF);
        }
    }
    __syncthreads();

#pragma unroll
    for (int mt = 0; mt < 2; mt++)
#pragma unroll
        for (int nt = 0; nt < 4; nt++) {
            int rrow = wr * 32 + mt * 16 + gID;
            int col = wc * 32 + nt * 8 + tIG * 2;
            float g0 = lng[col], g1 = lng[col + 1];
            float bb0 = lnb[col], bb1 = lnb[col + 1];
            int va = v0 + rrow, vb = v0 + rrow + 8;
            if (va < NV) {
                float o0 = g0 * (xv[mt][nt][0] - sMu[rrow]) * sRs[rrow] + bb0;
                float o1 = g1 * (xv[mt][nt][1] - sMu[rrow]) * sRs[rrow] + bb1;
                g_h[(size_t)va * H + col] = o0;
                g_h[(size_t)va * H + col + 1] = o1;
                *(uint32_t*)&g_hb[(size_t)va * H + col] = packbf(o0, o1);
            }
            if (vb < NV) {
                float o0 = g0 * (xv[mt][nt][2] - sMu[rrow + 8]) * sRs[rrow + 8] + bb0;
                float o1 = g1 * (xv[mt][nt][3] - sMu[rrow + 8]) * sRs[rrow + 8] + bb1;
                g_h[(size_t)vb * H + col] = o0;
                g_h[(size_t)vb * H + col + 1] = o1;
                *(uint32_t*)&g_hb[(size_t)vb * H + col] = packbf(o0, o1);
            }
        }
}

// -------- loss (also restores g_cnt = 0 invariant) --------
__global__ void k_loss(const float* pos0, const float* pos1,
                       const float* opw, const float* opb) {
    __shared__ double sAcc[8];
    int lane = threadIdx.x & 31;
    int wid = threadIdx.x >> 5;
    int gw = blockIdx.x * (blockDim.x >> 5) + wid;
    int nw = gridDim.x * (blockDim.x >> 5);
    double local = 0.0;
    for (int v = gw; v < NV; v += nw) {
        float h0 = g_h[(size_t)v * H + lane];
        float h1 = g_h[(size_t)v * H + lane + 32];
        float h2 = g_h[(size_t)v * H + lane + 64];
        float h3 = g_h[(size_t)v * H + lane + 96];
#pragma unroll
        for (int c = 0; c < 3; c++) {
            float s = h0 * opw[lane * 3 + c] + h1 * opw[(lane + 32) * 3 + c]
                    + h2 * opw[(lane + 64) * 3 + c] + h3 * opw[(lane + 96) * 3 + c];
#pragma unroll
            for (int off = 16; off; off >>= 1) s += __shfl_down_sync(0xffffffffu, s, off);
            if (lane == 0) {
                float vp = s + opb[c];
                float tg = pos1[v * 3 + c] - pos0[v * 3 + c];
                float d = vp - tg;
                local += (double)d * (double)d;
            }
        }
    }
    for (int i = blockIdx.x * blockDim.x + threadIdx.x; i < NV; i += gridDim.x * blockDim.x)
        g_cnt[i] = 0;
    if (lane == 0) sAcc[wid] = local;
    __syncthreads();
    if (threadIdx.x == 0) {
        double t = 0.0;
        for (int i = 0; i < (int)(blockDim.x >> 5); i++) t += sAcc[i];
        atomicAdd(&g_loss, t);
    }
}

__global__ void k_final(float* out) {
    if (threadIdx.x == 0) out[0] = (float)(g_loss / (double)(NV * 3));
}

extern "C" void kernel_launch(void* const* d_in, const int* in_sizes, int n_in,
                              void* d_out, int out_size) {
    const float* pos0  = (const float*)d_in[0];
    const float* pos1  = (const float*)d_in[1];
    const float* z     = (const float*)d_in[2];
    const float* t     = (const float*)d_in[3];
    const int*   ei    = (const int*)d_in[4];
    const int*   batch = (const int*)d_in[5];
    const float* te_w1 = (const float*)d_in[6];
    const float* te_b1 = (const float*)d_in[7];
    const float* te_w2 = (const float*)d_in[8];
    const float* te_b2 = (const float*)d_in[9];
    const float* cp_w  = (const float*)d_in[10];
    const float* cp_b  = (const float*)d_in[11];
    const float* eb1   = (const float*)d_in[13];
    const float* eb2   = (const float*)d_in[15];
    const float* nb1   = (const float*)d_in[17];
    const float* nb2   = (const float*)d_in[19];
    const float* ln_g  = (const float*)d_in[20];
    const float* ln_b  = (const float*)d_in[21];
    const float* op_w  = (const float*)d_in[22];
    const float* op_b  = (const float*)d_in[23];

    cudaFuncSetAttribute(k_edge, cudaFuncAttributeMaxDynamicSharedMemorySize, ESMEM);
    cudaFuncSetAttribute(k_node, cudaFuncAttributeMaxDynamicSharedMemorySize, NSMEM);

    // launch 1-3 prologue; launch 4 = k_edge layer 0 (ncu capture slot)
    k_pre<<<B_PRE, 1024>>>(t, te_w1, te_b1, te_w2, te_b2, z, cp_w, cp_b,
                           pos0, pos1, ei,
                           (const float*)d_in[12], (const float*)d_in[14],
                           (const float*)d_in[16], (const float*)d_in[18]);
    k_scan<<<1, 1024>>>();
    k_sorth<<<(NE + NV * 32 + 255) / 256, 256>>>(ei, batch);

    for (int l = 0; l < NLAYERS; l++) {
        k_edge<<<148, 256, ESMEM>>>(l, eb1 + (size_t)l * H, eb2 + (size_t)l * H);
        k_node<<<(NV + 63) / 64, 256, NSMEM>>>(l,
            nb1 + (size_t)l * H, nb2 + (size_t)l * H,
            ln_g + (size_t)l * H, ln_b + (size_t)l * H);
    }

    k_loss<<<256, 256>>>(pos0, pos1, op_w, op_b);
    k_final<<<1, 1>>>((float*)d_out);
}

// round 16
// speedup vs baseline: 7.0323x; 1.0493x over previous
#include <cuda_runtime.h>
#include <cuda_bf16.h>
#include <math.h>
#include <stdint.h>

#define NV 50000
#define NE 800000
#define H 128
#define LATD 64
#define TDIM 16
#define NLAYERS 4
#define EPSF 1e-5f

#define PADA 24
#define PADT 136
#define PADM 132
#define EBM 128
#define NTILE (NE / EBM)

// edge kernel smem layout (bytes)
#define PADW1 296
#define PADW2 136
#define PADAC 40
#define EOFF_W1  0
#define EOFF_W2  75776
#define EOFF_A   110592
#define EOFF_T   131072
#define EOFF_DST 165888
#define EOFF_SRC 166400
#define EOFF_DP  166912
#define ESMEM    168448

#define NSMEM (33792 + 16384)

// -------- scratch --------
__device__ float g_h[NV * H];
__device__ __align__(16) __nv_bfloat16 g_hb[NV * H];
__device__ float g_xt[NV * 3];
__device__ float g_h0tab[8][H];
__device__ double g_loss;

__device__ __align__(16) int g_cnt[NV];      // INVARIANT: zero at entry of every kernel_launch
__device__ __align__(16) int g_rowptr[NV + 4];
__device__ int g_esrc[NE];
__device__ int g_edst[NE];
__device__ __align__(16) __nv_bfloat16 g_msg[(size_t)NE * H];

__device__ __align__(16) __nv_bfloat16 g_ew1r[NLAYERS * 128 * PADW1];
__device__ __align__(16) __nv_bfloat16 g_ew2r[NLAYERS * 128 * PADW2];
__device__ __align__(16) __nv_bfloat16 g_nw1t[NLAYERS][H][256];
__device__ __align__(16) __nv_bfloat16 g_nw2t[NLAYERS][H][H];

__device__ __forceinline__ float siluf(float x) { return __fdividef(x, 1.f + __expf(-x)); }

__device__ __forceinline__ uint32_t packbf(float x, float y) {
    __nv_bfloat162 h = __floats2bfloat162_rn(x, y);
    return *(uint32_t*)&h;
}

__device__ __forceinline__ void mma_bf16(float* c, const uint32_t* a, const uint32_t* b) {
    asm volatile(
        "mma.sync.aligned.m16n8k16.row.col.f32.bf16.bf16.f32 "
        "{%0,%1,%2,%3}, {%4,%5,%6,%7}, {%8,%9}, {%0,%1,%2,%3};\n"
        : "+f"(c[0]), "+f"(c[1]), "+f"(c[2]), "+f"(c[3])
        : "r"(a[0]), "r"(a[1]), "r"(a[2]), "r"(a[3]), "r"(b[0]), "r"(b[1]));
}

__device__ __forceinline__ void ldsm4(uint32_t* r, const void* p) {
    uint32_t a = (uint32_t)__cvta_generic_to_shared(p);
    asm volatile("ldmatrix.sync.aligned.m8n8.x4.shared.b16 {%0,%1,%2,%3}, [%4];"
                 : "=r"(r[0]), "=r"(r[1]), "=r"(r[2]), "=r"(r[3]) : "r"(a));
}

__device__ __forceinline__ void cp16(void* smem, const void* gmem) {
    uint32_t s = (uint32_t)__cvta_generic_to_shared(smem);
    asm volatile("cp.async.cg.shared.global [%0], [%1], 16;" :: "r"(s), "l"(gmem));
}
#define CP_COMMIT() asm volatile("cp.async.commit_group;")
#define CP_WAIT(n)  asm volatile("cp.async.wait_group %0;" :: "n"(n))

// ======== launch 1: k_pre — prelude/h0tab (block 0), weights, histogram, xt ========
#define WT_TOTAL (NLAYERS * 128 * PADW1 + NLAYERS * 128 * PADW2 + NLAYERS * H * 256 + NLAYERS * H * H)
#define B_WT   1
#define B_HIST (B_WT + WT_TOTAL / 1024)            // 409
#define B_XT   (B_HIST + (NE + 1023) / 1024)       // 1191
#define B_PRE  (B_XT + (NV * 3 + 1023) / 1024)     // 1338

__global__ __launch_bounds__(1024) void k_pre(
        const float* t, const float* tw1, const float* tb1,
        const float* tw2, const float* tb2,
        const float* z, const float* cw, const float* cb,
        const float* pos0, const float* pos1, const int* ei,
        const float* ew1, const float* ew2, const float* nw1, const float* nw2) {
    int b = blockIdx.x, tid = threadIdx.x;
    if (b == 0) {
        __shared__ float s1[TDIM], stemb[TDIM], sz[8][LATD];
        if (tid == 0) g_loss = 0.0;
        float ts = t[0];
        if (tid < TDIM) s1[tid] = siluf(ts * tw1[tid] + tb1[tid]);
        for (int i = tid; i < 8 * LATD; i += 1024) sz[i >> 6][i & 63] = z[i];
        __syncthreads();
        if (tid < TDIM) {
            float a = tb2[tid];
#pragma unroll
            for (int k = 0; k < TDIM; k++) a += s1[k] * tw2[k * TDIM + tid];
            stemb[tid] = a;
        }
        __syncthreads();
        int bb = tid >> 7, n = tid & 127;
        float acc = cb[n];
#pragma unroll 16
        for (int k = 0; k < LATD; k++) acc += sz[bb][k] * cw[k * H + n];
#pragma unroll
        for (int k = 0; k < TDIM; k++) acc += stemb[k] * cw[(LATD + k) * H + n];
        g_h0tab[bb][n] = acc;
    } else if (b < B_HIST) {
        int i = (b - B_WT) * 1024 + tid;
        const int S1 = NLAYERS * 128 * PADW1;
        const int S2 = NLAYERS * 128 * PADW2;
        const int S3 = NLAYERS * H * 256;
        if (i < S1) {
            int l = i / (128 * PADW1), r = i % (128 * PADW1), n = r / PADW1, k = r % PADW1;
            float v = (k < 259) ? ew1[((size_t)l * 259 + k) * H + n] : 0.f;
            g_ew1r[i] = __float2bfloat16(v);
        } else if (i < S1 + S2) {
            int j = i - S1;
            int l = j / (128 * PADW2), r = j % (128 * PADW2), n = r / PADW2, k = r % PADW2;
            float v = (k < 128) ? ew2[((size_t)l * H + k) * H + n] : 0.f;
            g_ew2r[j] = __float2bfloat16(v);
        } else if (i < S1 + S2 + S3) {
            int j = i - S1 - S2;
            int l = j / (H * 256), r = j % (H * 256), n = r / 256, k = r % 256;
            g_nw1t[l][n][k] = __float2bfloat16(nw1[((size_t)l * 256 + k) * H + n]);
        } else {
            int j = i - S1 - S2 - S3;
            int l = j / (H * H), r = j % (H * H), n = r / H, k = r % H;
            g_nw2t[l][n][k] = __float2bfloat16(nw2[((size_t)l * H + k) * H + n]);
        }
    } else if (b < B_XT) {
        int e = (b - B_HIST) * 1024 + tid;
        if (e < NE) atomicAdd(&g_cnt[ei[NE + e]], 1);
    } else {
        int i = (b - B_XT) * 1024 + tid;
        if (i < NV * 3) {
            float ts = t[0];
            g_xt[i] = (1.f - ts) * pos0[i] + ts * pos1[i];
        }
    }
}

// ======== launch 2: k_scan ========
__global__ __launch_bounds__(1024) void k_scan() {
    __shared__ int swarp[32];
    int tid = threadIdx.x, lane = tid & 31, w = tid >> 5;
    int carry = 0;
    for (int base = 0; base < NV; base += 4096) {
        int i = base + tid * 4;
        int4 v = make_int4(0, 0, 0, 0);
        if (i < NV) v = *(const int4*)&g_cnt[i];
        int s = v.x + v.y + v.z + v.w;
        int x = s;
#pragma unroll
        for (int off = 1; off < 32; off <<= 1) {
            int y = __shfl_up_sync(0xffffffffu, x, off);
            if (lane >= off) x += y;
        }
        if (lane == 31) swarp[w] = x;
        __syncthreads();
        if (w == 0) {
            int y = swarp[lane];
#pragma unroll
            for (int off = 1; off < 32; off <<= 1) {
                int z2 = __shfl_up_sync(0xffffffffu, y, off);
                if (lane >= off) y += z2;
            }
            swarp[lane] = y;
        }
        __syncthreads();
        int wb = (w > 0) ? swarp[w - 1] : 0;
        int tot = swarp[31];
        int excl = carry + wb + (x - s);
        if (i < NV) {
            g_rowptr[i]     = excl;
            g_rowptr[i + 1] = excl + v.x;
            g_rowptr[i + 2] = excl + v.x + v.y;
            g_rowptr[i + 3] = excl + v.x + v.y + v.z;
        }
        carry += tot;
        __syncthreads();
    }
    if (tid == 0) g_rowptr[NV] = NE;
    for (int i = tid * 4; i < NV; i += 4096)
        *(int4*)&g_cnt[i] = make_int4(0, 0, 0, 0);
}

// ======== launch 3: k_sorth ========
__global__ void k_sorth(const int* ei, const int* batch) {
    int idx = blockIdx.x * 256 + threadIdx.x;
    if (idx < NE) {
        int d = ei[NE + idx];
        int s = ei[idx];
        int p = g_rowptr[d] + atomicAdd(&g_cnt[d], 1);
        g_esrc[p] = s;
        g_edst[p] = d;
    } else {
        int j = idx - NE;
        if (j < NV * 32) {
            int v = j >> 5, c4 = (j & 31) * 4;
            float4 h4 = *(const float4*)&g_h0tab[batch[v]][c4];
            *(float4*)&g_h[(size_t)v * H + c4] = h4;
            uint2 p = make_uint2(packbf(h4.x, h4.y), packbf(h4.z, h4.w));
            *(uint2*)&g_hb[(size_t)v * H + c4] = p;
        }
    }
}

// ===================== launch 4: edge kernel — 512 threads, 16 warps (4x4 m32n32) ====
__global__ __launch_bounds__(512) void k_edge(int layer, const float* b1, const float* b2) {
    extern __shared__ __align__(16) unsigned char dyn[];
    __nv_bfloat16* w1r = (__nv_bfloat16*)(dyn + EOFF_W1);
    __nv_bfloat16* w2r = (__nv_bfloat16*)(dyn + EOFF_W2);
    __nv_bfloat16* sA  = (__nv_bfloat16*)(dyn + EOFF_A);
    __nv_bfloat16* sT  = (__nv_bfloat16*)(dyn + EOFF_T);
    int* sDst = (int*)(dyn + EOFF_DST);
    int* sSrc = (int*)(dyn + EOFF_SRC);
    float* sDp = (float*)(dyn + EOFF_DP);

    int tid = threadIdx.x;
    int lane = tid & 31, warp = tid >> 5;
    int wr = warp >> 2, wc = warp & 3;          // 4x4 warp grid: m32 x n32 each
    int arow = lane & 15, acol = (lane >> 4) * 8;
    int brow = (lane & 7) + ((lane >> 4) * 8), bcol = ((lane >> 3) & 1) * 8;

    const __nv_bfloat16* w1g = g_ew1r + (size_t)layer * 128 * PADW1;
    const __nv_bfloat16* w2g = g_ew2r + (size_t)layer * 128 * PADW2;
    for (int i = tid; i < 128 * PADW1 / 8; i += 512) cp16(w1r + i * 8, w1g + i * 8);
    for (int i = tid; i < 128 * PADW2 / 8; i += 512) cp16(w2r + i * 8, w2g + i * 8);
    CP_COMMIT(); CP_WAIT(0);
    __syncthreads();

    // one cp16 per thread per chunk: 128 rows x 32 cols bf16 = 8KB = 512 x 16B
    auto loadA = [&](int ch, int buf) {
        int r = tid >> 2, seg = tid & 3;
        __nv_bfloat16* dst = sA + buf * 128 * PADAC + r * PADAC + seg * 8;
        if (ch < 8) {
            const __nv_bfloat16* src = (ch < 4)
                ? &g_hb[(size_t)sDst[r] * H + ch * 32 + seg * 8]
                : &g_hb[(size_t)sSrc[r] * H + (ch - 4) * 32 + seg * 8];
            cp16(dst, src);
        } else {
            uint4 z = make_uint4(0u, 0u, 0u, 0u);
            if (seg == 0)
                *(uint4*)dst = make_uint4(packbf(sDp[r * 3], sDp[r * 3 + 1]),
                                          packbf(sDp[r * 3 + 2], 0.f), 0u, 0u);
            else
                *(uint4*)dst = z;
        }
    };

    for (int tile = blockIdx.x; tile < NTILE; tile += gridDim.x) {
        int e0 = tile * EBM;
        __syncthreads();
        if (tid < EBM) { sDst[tid] = g_edst[e0 + tid]; sSrc[tid] = g_esrc[e0 + tid]; }
        __syncthreads();
        if (tid < EBM * 3) {
            int r = tid / 3, c = tid - r * 3;
            sDp[tid] = g_xt[sDst[r] * 3 + c] - g_xt[sSrc[r] * 3 + c];
        }
        __syncthreads();

        float acc[2][4][4];
#pragma unroll
        for (int mt = 0; mt < 2; mt++)
#pragma unroll
            for (int nt = 0; nt < 4; nt++)
#pragma unroll
                for (int q = 0; q < 4; q++) acc[mt][nt][q] = 0.f;

        // ---------- stage 1: 9 chunks of K=32 vs resident w1r ----------
        loadA(0, 0); CP_COMMIT();
        for (int ch = 0; ch < 9; ch++) {
            if (ch < 8) { loadA(ch + 1, (ch + 1) & 1); CP_COMMIT(); CP_WAIT(1); }
            else        { CP_WAIT(0); }
            __syncthreads();
            const __nv_bfloat16* At = sA + (ch & 1) * 128 * PADAC;
            int k0 = ch * 32;
#pragma unroll
            for (int ks = 0; ks < 32; ks += 16) {
                uint32_t af[2][4], bfr[4][2];
#pragma unroll
                for (int mt = 0; mt < 2; mt++)
                    ldsm4(af[mt], At + (wr * 32 + mt * 16 + arow) * PADAC + ks + acol);
#pragma unroll
                for (int np = 0; np < 2; np++) {
                    uint32_t rr[4];
                    ldsm4(rr, w1r + (wc * 32 + np * 16 + brow) * PADW1 + k0 + ks + bcol);
                    bfr[np * 2][0] = rr[0]; bfr[np * 2][1] = rr[1];
                    bfr[np * 2 + 1][0] = rr[2]; bfr[np * 2 + 1][1] = rr[3];
                }
#pragma unroll
                for (int mt = 0; mt < 2; mt++)
#pragma unroll
                    for (int nt = 0; nt < 4; nt++)
                        mma_bf16(acc[mt][nt], af[mt], bfr[nt]);
            }
            __syncthreads();
        }

        // ---------- epilogue 1: t1 = silu(acc + b1) -> sT ----------
#pragma unroll
        for (int mt = 0; mt < 2; mt++)
#pragma unroll
            for (int nt = 0; nt < 4; nt++) {
                int row = wr * 32 + mt * 16 + (lane >> 2);
                int col = wc * 32 + nt * 8 + (lane & 3) * 2;
                float bb0 = b1[col], bb1 = b1[col + 1];
                *(uint32_t*)&sT[row * PADT + col] =
                    packbf(siluf(acc[mt][nt][0] + bb0), siluf(acc[mt][nt][1] + bb1));
                *(uint32_t*)&sT[(row + 8) * PADT + col] =
                    packbf(siluf(acc[mt][nt][2] + bb0), siluf(acc[mt][nt][3] + bb1));
#pragma unroll
                for (int q = 0; q < 4; q++) acc[mt][nt][q] = 0.f;
            }
        __syncthreads();

        // ---------- stage 2: t1[128x128] @ resident w2r ----------
#pragma unroll
        for (int ch = 0; ch < 4; ch++) {
            int k0 = ch * 32;
#pragma unroll
            for (int ks = 0; ks < 32; ks += 16) {
                uint32_t af[2][4], bfr[4][2];
#pragma unroll
                for (int mt = 0; mt < 2; mt++)
                    ldsm4(af[mt], sT + (wr * 32 + mt * 16 + arow) * PADT + k0 + ks + acol);
#pragma unroll
                for (int np = 0; np < 2; np++) {
                    uint32_t rr[4];
                    ldsm4(rr, w2r + (wc * 32 + np * 16 + brow) * PADW2 + k0 + ks + bcol);
                    bfr[np * 2][0] = rr[0]; bfr[np * 2][1] = rr[1];
                    bfr[np * 2 + 1][0] = rr[2]; bfr[np * 2 + 1][1] = rr[3];
                }
#pragma unroll
                for (int mt = 0; mt < 2; mt++)
#pragma unroll
                    for (int nt = 0; nt < 4; nt++)
                        mma_bf16(acc[mt][nt], af[mt], bfr[nt]);
            }
        }
        __syncthreads();

        // ---------- epilogue 2: m = silu(acc + b2) -> sT -> g_msg ----------
#pragma unroll
        for (int mt = 0; mt < 2; mt++)
#pragma unroll
            for (int nt = 0; nt < 4; nt++) {
                int row = wr * 32 + mt * 16 + (lane >> 2);
                int col = wc * 32 + nt * 8 + (lane & 3) * 2;
                float bb0 = b2[col], bb1 = b2[col + 1];
                *(uint32_t*)&sT[row * PADT + col] =
                    packbf(siluf(acc[mt][nt][0] + bb0), siluf(acc[mt][nt][1] + bb1));
                *(uint32_t*)&sT[(row + 8) * PADT + col] =
                    packbf(siluf(acc[mt][nt][2] + bb0), siluf(acc[mt][nt][3] + bb1));
            }
        __syncthreads();
#pragma unroll
        for (int it = 0; it < 4; it++) {
            int idx = tid + it * 512;
            int r = idx >> 4, c8 = (idx & 15) * 8;
            *(uint4*)&g_msg[(size_t)(e0 + r) * H + c8] = *(uint4*)&sT[r * PADT + c8];
        }
    }
}

// ===================== node kernel (unchanged) =====================
__global__ __launch_bounds__(256) void k_node(int layer,
        const float* b1, const float* b2, const float* lng, const float* lnb) {
    extern __shared__ __align__(16) unsigned char dynn[];
    __nv_bfloat16* sA = (__nv_bfloat16*)dynn;
    __nv_bfloat16* sB = (__nv_bfloat16*)(dynn + 3072);
    __nv_bfloat16* sT = (__nv_bfloat16*)(dynn + 9216);
    float* sX = (float*)dynn;
    __nv_bfloat16* sAgg = (__nv_bfloat16*)(dynn + 33792);
    __shared__ float sMu[64], sRs[64];
    __shared__ int sRp[65];

    int tid = threadIdx.x;
    int lane = tid & 31, warp = tid >> 5;
    int gID = lane >> 2, tIG = lane & 3;
    int wr = warp >> 2, wc = warp & 3;
    int v0 = blockIdx.x * 64;

    if (tid < 65) {
        int v = v0 + tid;
        sRp[tid] = g_rowptr[v > NV ? NV : v];
    }
    __syncthreads();

#pragma unroll
    for (int i = 0; i < 8; i++) {
        int r = warp * 8 + i;
        float a0 = 0.f, a1 = 0.f, a2 = 0.f, a3 = 0.f;
        int s = sRp[r], e = sRp[r + 1];
        for (int ed = s; ed < e; ed++) {
            uint2 q = *(const uint2*)&g_msg[(size_t)ed * H + lane * 4];
            __nv_bfloat162 q0 = *(__nv_bfloat162*)&q.x;
            __nv_bfloat162 q1 = *(__nv_bfloat162*)&q.y;
            a0 += __bfloat162float(q0.x); a1 += __bfloat162float(q0.y);
            a2 += __bfloat162float(q1.x); a3 += __bfloat162float(q1.y);
        }
        *(uint32_t*)&sAgg[r * 128 + lane * 4]     = packbf(a0, a1);
        *(uint32_t*)&sAgg[r * 128 + lane * 4 + 2] = packbf(a2, a3);
    }
    __syncthreads();

    float acc[2][4][4];
#pragma unroll
    for (int mt = 0; mt < 2; mt++)
#pragma unroll
        for (int nt = 0; nt < 4; nt++)
#pragma unroll
            for (int q = 0; q < 4; q++) acc[mt][nt][q] = 0.f;

    const __nv_bfloat16* w1t = &g_nw1t[layer][0][0];

    for (int ch = 0; ch < 16; ch++) {
        int k0 = ch * 16;
        __syncthreads();
#pragma unroll
        for (int it = 0; it < 4; it++) {
            int idx = tid + it * 256;
            int n = idx >> 3, p = idx & 7;
            *(uint32_t*)&sB[n * PADA + p * 2] = *(const uint32_t*)&w1t[n * 256 + k0 + p * 2];
        }
#pragma unroll
        for (int it = 0; it < 2; it++) {
            int idx = tid + it * 256;
            int r = idx >> 3, p = idx & 7;
            uint32_t val;
            if (k0 < 128) {
                int vv = v0 + r; if (vv >= NV) vv = NV - 1;
                val = *(const uint32_t*)&g_hb[(size_t)vv * H + k0 + p * 2];
            } else {
                val = *(uint32_t*)&sAgg[r * 128 + (k0 - 128) + p * 2];
            }
            *(uint32_t*)&sA[r * PADA + p * 2] = val;
        }
        __syncthreads();

        uint32_t af[2][4], bfr[4][2];
#pragma unroll
        for (int mt = 0; mt < 2; mt++) {
            int rrow = wr * 32 + mt * 16 + (lane & 15);
            ldsm4(af[mt], sA + rrow * PADA + (lane >> 4) * 8);
        }
#pragma unroll
        for (int np = 0; np < 2; np++) {
            uint32_t rr[4];
            int n = wc * 32 + np * 16 + (lane & 7) + (lane >> 4) * 8;
            ldsm4(rr, sB + n * PADA + ((lane >> 3) & 1) * 8);
            bfr[np * 2][0] = rr[0]; bfr[np * 2][1] = rr[1];
            bfr[np * 2 + 1][0] = rr[2]; bfr[np * 2 + 1][1] = rr[3];
        }
#pragma unroll
        for (int mt = 0; mt < 2; mt++)
#pragma unroll
            for (int nt = 0; nt < 4; nt++)
                mma_bf16(acc[mt][nt], af[mt], bfr[nt]);
    }
    __syncthreads();

#pragma unroll
    for (int mt = 0; mt < 2; mt++)
#pragma unroll
        for (int nt = 0; nt < 4; nt++) {
            int rrow = wr * 32 + mt * 16 + gID;
            int col = wc * 32 + nt * 8 + tIG * 2;
            float bb0 = b1[col], bb1 = b1[col + 1];
            *(uint32_t*)&sT[rrow * PADT + col] =
                packbf(siluf(acc[mt][nt][0] + bb0), siluf(acc[mt][nt][1] + bb1));
            *(uint32_t*)&sT[(rrow + 8) * PADT + col] =
                packbf(siluf(acc[mt][nt][2] + bb0), siluf(acc[mt][nt][3] + bb1));
#pragma unroll
            for (int q = 0; q < 4; q++) acc[mt][nt][q] = 0.f;
        }

    const __nv_bfloat16* w2t = &g_nw2t[layer][0][0];

    for (int ch = 0; ch < 8; ch++) {
        int k0 = ch * 16;
        __syncthreads();
#pragma unroll
        for (int it = 0; it < 4; it++) {
            int idx = tid + it * 256;
            int n = idx >> 3, p = idx & 7;
            *(uint32_t*)&sB[n * PADA + p * 2] = *(const uint32_t*)&w2t[n * H + k0 + p * 2];
        }
        __syncthreads();

        uint32_t af[2][4], bfr[4][2];
#pragma unroll
        for (int mt = 0; mt < 2; mt++) {
            int rrow = wr * 32 + mt * 16 + (lane & 15);
            ldsm4(af[mt], sT + rrow * PADT + k0 + (lane >> 4) * 8);
        }
#pragma unroll
        for (int np = 0; np < 2; np++) {
            uint32_t rr[4];
            int n = wc * 32 + np * 16 + (lane & 7) + (lane >> 4) * 8;
            ldsm4(rr, sB + n * PADA + ((lane >> 3) & 1) * 8);
            bfr[np * 2][0] = rr[0]; bfr[np * 2][1] = rr[1];
            bfr[np * 2 + 1][0] = rr[2]; bfr[np * 2 + 1][1] = rr[3];
        }
#pragma unroll
        for (int mt = 0; mt < 2; mt++)
#pragma unroll
            for (int nt = 0; nt < 4; nt++)
                mma_bf16(acc[mt][nt], af[mt], bfr[nt]);
    }
    __syncthreads();

    float xv[2][4][4];
#pragma unroll
    for (int mt = 0; mt < 2; mt++)
#pragma unroll
        for (int nt = 0; nt < 4; nt++) {
            int rrow = wr * 32 + mt * 16 + gID;
            int col = wc * 32 + nt * 8 + tIG * 2;
            float bb0 = b2[col], bb1 = b2[col + 1];
            int va = v0 + rrow; if (va >= NV) va = NV - 1;
            int vb = v0 + rrow + 8; if (vb >= NV) vb = NV - 1;
            xv[mt][nt][0] = acc[mt][nt][0] + bb0 + g_h[(size_t)va * H + col];
            xv[mt][nt][1] = acc[mt][nt][1] + bb1 + g_h[(size_t)va * H + col + 1];
            xv[mt][nt][2] = acc[mt][nt][2] + bb0 + g_h[(size_t)vb * H + col];
            xv[mt][nt][3] = acc[mt][nt][3] + bb1 + g_h[(size_t)vb * H + col + 1];
            sX[rrow * PADM + col]           = xv[mt][nt][0];
            sX[rrow * PADM + col + 1]       = xv[mt][nt][1];
            sX[(rrow + 8) * PADM + col]     = xv[mt][nt][2];
            sX[(rrow + 8) * PADM + col + 1] = xv[mt][nt][3];
        }
    __syncthreads();

#pragma unroll
    for (int i = 0; i < 8; i++) {
        int rrow = warp * 8 + i;
        float4 v = *(float4*)&sX[rrow * PADM + lane * 4];
        float s = v.x + v.y + v.z + v.w;
        float s2 = v.x * v.x + v.y * v.y + v.z * v.z + v.w * v.w;
#pragma unroll
        for (int off = 16; off; off >>= 1) {
            s += __shfl_xor_sync(0xffffffffu, s, off);
            s2 += __shfl_xor_sync(0xffffffffu, s2, off);
        }
        if (lane == 0) {
            float mu = s * (1.f / H);
            float var = s2 * (1.f / H) - mu * mu;
            sMu[rrow] = mu;
            sRs[rrow] = rsqrtf(var + EPSF);
        }
    }
    __syncthreads();

#pragma unroll
    for (int mt = 0; mt < 2; mt++)
#pragma unroll
        for (int nt = 0; nt < 4; nt++) {
            int rrow = wr * 32 + mt * 16 + gID;
            int col = wc * 32 + nt * 8 + tIG * 2;
            float g0 = lng[col], g1 = lng[col + 1];
            float bb0 = lnb[col], bb1 = lnb[col + 1];
            int va = v0 + rrow, vb = v0 + rrow + 8;
            if (va < NV) {
                float o0 = g0 * (xv[mt][nt][0] - sMu[rrow]) * sRs[rrow] + bb0;
                float o1 = g1 * (xv[mt][nt][1] - sMu[rrow]) * sRs[rrow] + bb1;
                g_h[(size_t)va * H + col] = o0;
                g_h[(size_t)va * H + col + 1] = o1;
                *(uint32_t*)&g_hb[(size_t)va * H + col] = packbf(o0, o1);
            }
            if (vb < NV) {
                float o0 = g0 * (xv[mt][nt][2] - sMu[rrow + 8]) * sRs[rrow + 8] + bb0;
                float o1 = g1 * (xv[mt][nt][3] - sMu[rrow + 8]) * sRs[rrow + 8] + bb1;
                g_h[(size_t)vb * H + col] = o0;
                g_h[(size_t)vb * H + col + 1] = o1;
                *(uint32_t*)&g_hb[(size_t)vb * H + col] = packbf(o0, o1);
            }
        }
}

// -------- loss (also restores g_cnt = 0 invariant) --------
__global__ void k_loss(const float* pos0, const float* pos1,
                       const float* opw, const float* opb) {
    __shared__ double sAcc[8];
    int lane = threadIdx.x & 31;
    int wid = threadIdx.x >> 5;
    int gw = blockIdx.x * (blockDim.x >> 5) + wid;
    int nw = gridDim.x * (blockDim.x >> 5);
    double local = 0.0;
    for (int v = gw; v < NV; v += nw) {
        float h0 = g_h[(size_t)v * H + lane];
        float h1 = g_h[(size_t)v * H + lane + 32];
        float h2 = g_h[(size_t)v * H + lane + 64];
        float h3 = g_h[(size_t)v * H + lane + 96];
#pragma unroll
        for (int c = 0; c < 3; c++) {
            float s = h0 * opw[lane * 3 + c] + h1 * opw[(lane + 32) * 3 + c]
                    + h2 * opw[(lane + 64) * 3 + c] + h3 * opw[(lane + 96) * 3 + c];
#pragma unroll
            for (int off = 16; off; off >>= 1) s += __shfl_down_sync(0xffffffffu, s, off);
            if (lane == 0) {
                float vp = s + opb[c];
                float tg = pos1[v * 3 + c] - pos0[v * 3 + c];
                float d = vp - tg;
                local += (double)d * (double)d;
            }
        }
    }
    for (int i = blockIdx.x * blockDim.x + threadIdx.x; i < NV; i += gridDim.x * blockDim.x)
        g_cnt[i] = 0;
    if (lane == 0) sAcc[wid] = local;
    __syncthreads();
    if (threadIdx.x == 0) {
        double t = 0.0;
        for (int i = 0; i < (int)(blockDim.x >> 5); i++) t += sAcc[i];
        atomicAdd(&g_loss, t);
    }
}

__global__ void k_final(float* out) {
    if (threadIdx.x == 0) out[0] = (float)(g_loss / (double)(NV * 3));
}

extern "C" void kernel_launch(void* const* d_in, const int* in_sizes, int n_in,
                              void* d_out, int out_size) {
    const float* pos0  = (const float*)d_in[0];
    const float* pos1  = (const float*)d_in[1];
    const float* z     = (const float*)d_in[2];
    const float* t     = (const float*)d_in[3];
    const int*   ei    = (const int*)d_in[4];
    const int*   batch = (const int*)d_in[5];
    const float* te_w1 = (const float*)d_in[6];
    const float* te_b1 = (const float*)d_in[7];
    const float* te_w2 = (const float*)d_in[8];
    const float* te_b2 = (const float*)d_in[9];
    const float* cp_w  = (const float*)d_in[10];
    const float* cp_b  = (const float*)d_in[11];
    const float* eb1   = (const float*)d_in[13];
    const float* eb2   = (const float*)d_in[15];
    const float* nb1   = (const float*)d_in[17];
    const float* nb2   = (const float*)d_in[19];
    const float* ln_g  = (const float*)d_in[20];
    const float* ln_b  = (const float*)d_in[21];
    const float* op_w  = (const float*)d_in[22];
    const float* op_b  = (const float*)d_in[23];

    cudaFuncSetAttribute(k_edge, cudaFuncAttributeMaxDynamicSharedMemorySize, ESMEM);
    cudaFuncSetAttribute(k_node, cudaFuncAttributeMaxDynamicSharedMemorySize, NSMEM);

    k_pre<<<B_PRE, 1024>>>(t, te_w1, te_b1, te_w2, te_b2, z, cp_w, cp_b,
                           pos0, pos1, ei,
                           (const float*)d_in[12], (const float*)d_in[14],
                           (const float*)d_in[16], (const float*)d_in[18]);
    k_scan<<<1, 1024>>>();
    k_sorth<<<(NE + NV * 32 + 255) / 256, 256>>>(ei, batch);

    for (int l = 0; l < NLAYERS; l++) {
        k_edge<<<148, 512, ESMEM>>>(l, eb1 + (size_t)l * H, eb2 + (size_t)l * H);
        k_node<<<(NV + 63) / 64, 256, NSMEM>>>(l,
            nb1 + (size_t)l * H, nb2 + (size_t)l * H,
            ln_g + (size_t)l * H, ln_b + (size_t)l * H);
    }

    k_loss<<<256, 256>>>(pos0, pos1, op_w, op_b);
    k_final<<<1, 1>>>((float*)d_out);
}

// round 17
// speedup vs baseline: 7.6441x; 1.0870x over previous
#include <cuda_runtime.h>
#include <cuda_bf16.h>
#include <math.h>
#include <stdint.h>

#define NV 50000
#define NE 800000
#define H 128
#define LATD 64
#define TDIM 16
#define NLAYERS 4
#define EPSF 1e-5f

#define PADA 24
#define PADT 136
#define PADM 132
#define EBM 128
#define NTILE (NE / EBM)

// edge kernel smem layout (bytes)
#define PADW1 296
#define PADW2 136
#define PADAC 40
#define EOFF_W1  0
#define EOFF_W2  75776
#define EOFF_A   110592          // 4 x 128 x PADAC bf16 = 40960
#define EOFF_T   151552          // 128 x PADT bf16 = 34816
#define EOFF_DST 186368
#define EOFF_SRC 186880
#define EOFF_DP  187392          // 128*3 floats = 1536
#define ESMEM    189440

#define NSMEM (33792 + 16384)

// -------- scratch --------
__device__ float g_h[NV * H];
__device__ __align__(16) __nv_bfloat16 g_hb[NV * H];
__device__ float g_xt[NV * 3];
__device__ float g_h0tab[8][H];
__device__ double g_loss;

__device__ __align__(16) int g_cnt[NV];      // INVARIANT: zero at entry of every kernel_launch
__device__ __align__(16) int g_rowptr[NV + 4];
__device__ int g_esrc[NE];
__device__ int g_edst[NE];
__device__ __align__(16) __nv_bfloat16 g_msg[(size_t)NE * H];

__device__ __align__(16) __nv_bfloat16 g_ew1r[NLAYERS * 128 * PADW1];
__device__ __align__(16) __nv_bfloat16 g_ew2r[NLAYERS * 128 * PADW2];
__device__ __align__(16) __nv_bfloat16 g_nw1t[NLAYERS][H][256];
__device__ __align__(16) __nv_bfloat16 g_nw2t[NLAYERS][H][H];

__device__ __forceinline__ float siluf(float x) { return __fdividef(x, 1.f + __expf(-x)); }

__device__ __forceinline__ uint32_t packbf(float x, float y) {
    __nv_bfloat162 h = __floats2bfloat162_rn(x, y);
    return *(uint32_t*)&h;
}

__device__ __forceinline__ void mma_bf16(float* c, const uint32_t* a, const uint32_t* b) {
    asm volatile(
        "mma.sync.aligned.m16n8k16.row.col.f32.bf16.bf16.f32 "
        "{%0,%1,%2,%3}, {%4,%5,%6,%7}, {%8,%9}, {%0,%1,%2,%3};\n"
        : "+f"(c[0]), "+f"(c[1]), "+f"(c[2]), "+f"(c[3])
        : "r"(a[0]), "r"(a[1]), "r"(a[2]), "r"(a[3]), "r"(b[0]), "r"(b[1]));
}

__device__ __forceinline__ void ldsm4(uint32_t* r, const void* p) {
    uint32_t a = (uint32_t)__cvta_generic_to_shared(p);
    asm volatile("ldmatrix.sync.aligned.m8n8.x4.shared.b16 {%0,%1,%2,%3}, [%4];"
                 : "=r"(r[0]), "=r"(r[1]), "=r"(r[2]), "=r"(r[3]) : "r"(a));
}

__device__ __forceinline__ void cp16(void* smem, const void* gmem) {
    uint32_t s = (uint32_t)__cvta_generic_to_shared(smem);
    asm volatile("cp.async.cg.shared.global [%0], [%1], 16;" :: "r"(s), "l"(gmem));
}
#define CP_COMMIT() asm volatile("cp.async.commit_group;")
#define CP_WAIT(n)  asm volatile("cp.async.wait_group %0;" :: "n"(n))

// ======== launch 1: k_pre — prelude/h0tab (block 0), weights, histogram, xt ========
#define WT_TOTAL (NLAYERS * 128 * PADW1 + NLAYERS * 128 * PADW2 + NLAYERS * H * 256 + NLAYERS * H * H)
#define B_WT   1
#define B_HIST (B_WT + WT_TOTAL / 1024)            // 409
#define B_XT   (B_HIST + (NE + 1023) / 1024)       // 1191
#define B_PRE  (B_XT + (NV * 3 + 1023) / 1024)     // 1338

__global__ __launch_bounds__(1024) void k_pre(
        const float* t, const float* tw1, const float* tb1,
        const float* tw2, const float* tb2,
        const float* z, const float* cw, const float* cb,
        const float* pos0, const float* pos1, const int* ei,
        const float* ew1, const float* ew2, const float* nw1, const float* nw2) {
    int b = blockIdx.x, tid = threadIdx.x;
    if (b == 0) {
        __shared__ float s1[TDIM], stemb[TDIM], sz[8][LATD];
        if (tid == 0) g_loss = 0.0;
        float ts = t[0];
        if (tid < TDIM) s1[tid] = siluf(ts * tw1[tid] + tb1[tid]);
        for (int i = tid; i < 8 * LATD; i += 1024) sz[i >> 6][i & 63] = z[i];
        __syncthreads();
        if (tid < TDIM) {
            float a = tb2[tid];
#pragma unroll
            for (int k = 0; k < TDIM; k++) a += s1[k] * tw2[k * TDIM + tid];
            stemb[tid] = a;
        }
        __syncthreads();
        int bb = tid >> 7, n = tid & 127;
        float acc = cb[n];
#pragma unroll 16
        for (int k = 0; k < LATD; k++) acc += sz[bb][k] * cw[k * H + n];
#pragma unroll
        for (int k = 0; k < TDIM; k++) acc += stemb[k] * cw[(LATD + k) * H + n];
        g_h0tab[bb][n] = acc;
    } else if (b < B_HIST) {
        int i = (b - B_WT) * 1024 + tid;
        const int S1 = NLAYERS * 128 * PADW1;
        const int S2 = NLAYERS * 128 * PADW2;
        const int S3 = NLAYERS * H * 256;
        if (i < S1) {
            int l = i / (128 * PADW1), r = i % (128 * PADW1), n = r / PADW1, k = r % PADW1;
            float v = (k < 259) ? ew1[((size_t)l * 259 + k) * H + n] : 0.f;
            g_ew1r[i] = __float2bfloat16(v);
        } else if (i < S1 + S2) {
            int j = i - S1;
            int l = j / (128 * PADW2), r = j % (128 * PADW2), n = r / PADW2, k = r % PADW2;
            float v = (k < 128) ? ew2[((size_t)l * H + k) * H + n] : 0.f;
            g_ew2r[j] = __float2bfloat16(v);
        } else if (i < S1 + S2 + S3) {
            int j = i - S1 - S2;
            int l = j / (H * 256), r = j % (H * 256), n = r / 256, k = r % 256;
            g_nw1t[l][n][k] = __float2bfloat16(nw1[((size_t)l * 256 + k) * H + n]);
        } else {
            int j = i - S1 - S2 - S3;
            int l = j / (H * H), r = j % (H * H), n = r / H, k = r % H;
            g_nw2t[l][n][k] = __float2bfloat16(nw2[((size_t)l * H + k) * H + n]);
        }
    } else if (b < B_XT) {
        int e = (b - B_HIST) * 1024 + tid;
        if (e < NE) atomicAdd(&g_cnt[ei[NE + e]], 1);
    } else {
        int i = (b - B_XT) * 1024 + tid;
        if (i < NV * 3) {
            float ts = t[0];
            g_xt[i] = (1.f - ts) * pos0[i] + ts * pos1[i];
        }
    }
}

// ======== launch 2: k_scan ========
__global__ __launch_bounds__(1024) void k_scan() {
    __shared__ int swarp[32];
    int tid = threadIdx.x, lane = tid & 31, w = tid >> 5;
    int carry = 0;
    for (int base = 0; base < NV; base += 4096) {
        int i = base + tid * 4;
        int4 v = make_int4(0, 0, 0, 0);
        if (i < NV) v = *(const int4*)&g_cnt[i];
        int s = v.x + v.y + v.z + v.w;
        int x = s;
#pragma unroll
        for (int off = 1; off < 32; off <<= 1) {
            int y = __shfl_up_sync(0xffffffffu, x, off);
            if (lane >= off) x += y;
        }
        if (lane == 31) swarp[w] = x;
        __syncthreads();
        if (w == 0) {
            int y = swarp[lane];
#pragma unroll
            for (int off = 1; off < 32; off <<= 1) {
                int z2 = __shfl_up_sync(0xffffffffu, y, off);
                if (lane >= off) y += z2;
            }
            swarp[lane] = y;
        }
        __syncthreads();
        int wb = (w > 0) ? swarp[w - 1] : 0;
        int tot = swarp[31];
        int excl = carry + wb + (x - s);
        if (i < NV) {
            g_rowptr[i]     = excl;
            g_rowptr[i + 1] = excl + v.x;
            g_rowptr[i + 2] = excl + v.x + v.y;
            g_rowptr[i + 3] = excl + v.x + v.y + v.z;
        }
        carry += tot;
        __syncthreads();
    }
    if (tid == 0) g_rowptr[NV] = NE;
    for (int i = tid * 4; i < NV; i += 4096)
        *(int4*)&g_cnt[i] = make_int4(0, 0, 0, 0);
}

// ======== launch 3: k_sorth ========
__global__ void k_sorth(const int* ei, const int* batch) {
    int idx = blockIdx.x * 256 + threadIdx.x;
    if (idx < NE) {
        int d = ei[NE + idx];
        int s = ei[idx];
        int p = g_rowptr[d] + atomicAdd(&g_cnt[d], 1);
        g_esrc[p] = s;
        g_edst[p] = d;
    } else {
        int j = idx - NE;
        if (j < NV * 32) {
            int v = j >> 5, c4 = (j & 31) * 4;
            float4 h4 = *(const float4*)&g_h0tab[batch[v]][c4];
            *(float4*)&g_h[(size_t)v * H + c4] = h4;
            uint2 p = make_uint2(packbf(h4.x, h4.y), packbf(h4.z, h4.w));
            *(uint2*)&g_hb[(size_t)v * H + c4] = p;
        }
    }
}

// ===== launch 4: edge kernel — 512 threads, 4-deep A pipeline, 1 barrier/chunk =====
__global__ __launch_bounds__(512) void k_edge(int layer, const float* b1, const float* b2) {
    extern __shared__ __align__(16) unsigned char dyn[];
    __nv_bfloat16* w1r = (__nv_bfloat16*)(dyn + EOFF_W1);
    __nv_bfloat16* w2r = (__nv_bfloat16*)(dyn + EOFF_W2);
    __nv_bfloat16* sA  = (__nv_bfloat16*)(dyn + EOFF_A);    // [4][128][PADAC]
    __nv_bfloat16* sT  = (__nv_bfloat16*)(dyn + EOFF_T);
    int* sDst = (int*)(dyn + EOFF_DST);
    int* sSrc = (int*)(dyn + EOFF_SRC);
    float* sDp = (float*)(dyn + EOFF_DP);

    int tid = threadIdx.x;
    int lane = tid & 31, warp = tid >> 5;
    int wr = warp >> 2, wc = warp & 3;          // 4x4 warp grid: m32 x n32 each
    int arow = lane & 15, acol = (lane >> 4) * 8;
    int brow = (lane & 7) + ((lane >> 4) * 8), bcol = ((lane >> 3) & 1) * 8;

    const __nv_bfloat16* w1g = g_ew1r + (size_t)layer * 128 * PADW1;
    const __nv_bfloat16* w2g = g_ew2r + (size_t)layer * 128 * PADW2;
    for (int i = tid; i < 128 * PADW1 / 8; i += 512) cp16(w1r + i * 8, w1g + i * 8);
    for (int i = tid; i < 128 * PADW2 / 8; i += 512) cp16(w2r + i * 8, w2g + i * 8);
    CP_COMMIT(); CP_WAIT(0);
    __syncthreads();

    // one cp16 per thread per chunk: 128 rows x 32 cols bf16 = 8KB = 512 x 16B
    auto loadA = [&](int ch, int buf) {
        int r = tid >> 2, seg = tid & 3;
        __nv_bfloat16* dst = sA + buf * 128 * PADAC + r * PADAC + seg * 8;
        if (ch < 8) {
            const __nv_bfloat16* src = (ch < 4)
                ? &g_hb[(size_t)sDst[r] * H + ch * 32 + seg * 8]
                : &g_hb[(size_t)sSrc[r] * H + (ch - 4) * 32 + seg * 8];
            cp16(dst, src);
        } else {
            uint4 z = make_uint4(0u, 0u, 0u, 0u);
            if (seg == 0)
                *(uint4*)dst = make_uint4(packbf(sDp[r * 3], sDp[r * 3 + 1]),
                                          packbf(sDp[r * 3 + 2], 0.f), 0u, 0u);
            else
                *(uint4*)dst = z;
        }
    };

    for (int tile = blockIdx.x; tile < NTILE; tile += gridDim.x) {
        int e0 = tile * EBM;
        __syncthreads();
        if (tid < EBM) { sDst[tid] = g_edst[e0 + tid]; sSrc[tid] = g_esrc[e0 + tid]; }
        __syncthreads();
        if (tid < EBM * 3) {
            int r = tid / 3, c = tid - r * 3;
            sDp[tid] = g_xt[sDst[r] * 3 + c] - g_xt[sSrc[r] * 3 + c];
        }
        __syncthreads();

        float acc[2][4][4];
#pragma unroll
        for (int mt = 0; mt < 2; mt++)
#pragma unroll
            for (int nt = 0; nt < 4; nt++)
#pragma unroll
                for (int q = 0; q < 4; q++) acc[mt][nt][q] = 0.f;

        // ---------- stage 1: 9 chunks of K=32, 4-buffer pipeline, depth 3 ----------
        loadA(0, 0); CP_COMMIT();
        loadA(1, 1); CP_COMMIT();
        loadA(2, 2); CP_COMMIT();
#pragma unroll
        for (int ch = 0; ch < 9; ch++) {
            if (ch < 7)      CP_WAIT(2);
            else if (ch == 7) CP_WAIT(1);
            else              CP_WAIT(0);
            __syncthreads();                    // chunk ch visible; all done with ch-1
            if (ch + 3 < 9) { loadA(ch + 3, (ch + 3) & 3); CP_COMMIT(); }
            const __nv_bfloat16* At = sA + (ch & 3) * 128 * PADAC;
            int k0 = ch * 32;
#pragma unroll
            for (int ks = 0; ks < 32; ks += 16) {
                uint32_t af[2][4], bfr[4][2];
#pragma unroll
                for (int mt = 0; mt < 2; mt++)
                    ldsm4(af[mt], At + (wr * 32 + mt * 16 + arow) * PADAC + ks + acol);
#pragma unroll
                for (int np = 0; np < 2; np++) {
                    uint32_t rr[4];
                    ldsm4(rr, w1r + (wc * 32 + np * 16 + brow) * PADW1 + k0 + ks + bcol);
                    bfr[np * 2][0] = rr[0]; bfr[np * 2][1] = rr[1];
                    bfr[np * 2 + 1][0] = rr[2]; bfr[np * 2 + 1][1] = rr[3];
                }
#pragma unroll
                for (int mt = 0; mt < 2; mt++)
#pragma unroll
                    for (int nt = 0; nt < 4; nt++)
                        mma_bf16(acc[mt][nt], af[mt], bfr[nt]);
            }
        }

        // ---------- epilogue 1: t1 = silu(acc + b1) -> sT ----------
#pragma unroll
        for (int mt = 0; mt < 2; mt++)
#pragma unroll
            for (int nt = 0; nt < 4; nt++) {
                int row = wr * 32 + mt * 16 + (lane >> 2);
                int col = wc * 32 + nt * 8 + (lane & 3) * 2;
                float bb0 = b1[col], bb1 = b1[col + 1];
                *(uint32_t*)&sT[row * PADT + col] =
                    packbf(siluf(acc[mt][nt][0] + bb0), siluf(acc[mt][nt][1] + bb1));
                *(uint32_t*)&sT[(row + 8) * PADT + col] =
                    packbf(siluf(acc[mt][nt][2] + bb0), siluf(acc[mt][nt][3] + bb1));
#pragma unroll
                for (int q = 0; q < 4; q++) acc[mt][nt][q] = 0.f;
            }
        __syncthreads();

        // ---------- stage 2: t1[128x128] @ resident w2r ----------
#pragma unroll
        for (int ch = 0; ch < 4; ch++) {
            int k0 = ch * 32;
#pragma unroll
            for (int ks = 0; ks < 32; ks += 16) {
                uint32_t af[2][4], bfr[4][2];
#pragma unroll
                for (int mt = 0; mt < 2; mt++)
                    ldsm4(af[mt], sT + (wr * 32 + mt * 16 + arow) * PADT + k0 + ks + acol);
#pragma unroll
                for (int np = 0; np < 2; np++) {
                    uint32_t rr[4];
                    ldsm4(rr, w2r + (wc * 32 + np * 16 + brow) * PADW2 + k0 + ks + bcol);
                    bfr[np * 2][0] = rr[0]; bfr[np * 2][1] = rr[1];
                    bfr[np * 2 + 1][0] = rr[2]; bfr[np * 2 + 1][1] = rr[3];
                }
#pragma unroll
                for (int mt = 0; mt < 2; mt++)
#pragma unroll
                    for (int nt = 0; nt < 4; nt++)
                        mma_bf16(acc[mt][nt], af[mt], bfr[nt]);
            }
        }
        __syncthreads();

        // ---------- epilogue 2: m = silu(acc + b2) -> sT -> g_msg ----------
#pragma unroll
        for (int mt = 0; mt < 2; mt++)
#pragma unroll
            for (int nt = 0; nt < 4; nt++) {
                int row = wr * 32 + mt * 16 + (lane >> 2);
                int col = wc * 32 + nt * 8 + (lane & 3) * 2;
                float bb0 = b2[col], bb1 = b2[col + 1];
                *(uint32_t*)&sT[row * PADT + col] =
                    packbf(siluf(acc[mt][nt][0] + bb0), siluf(acc[mt][nt][1] + bb1));
                *(uint32_t*)&sT[(row + 8) * PADT + col] =
                    packbf(siluf(acc[mt][nt][2] + bb0), siluf(acc[mt][nt][3] + bb1));
            }
        __syncthreads();
#pragma unroll
        for (int it = 0; it < 4; it++) {
            int idx = tid + it * 512;
            int r = idx >> 4, c8 = (idx & 15) * 8;
            *(uint4*)&g_msg[(size_t)(e0 + r) * H + c8] = *(uint4*)&sT[r * PADT + c8];
        }
    }
}

// ===================== node kernel (unchanged) =====================
__global__ __launch_bounds__(256) void k_node(int layer,
        const float* b1, const float* b2, const float* lng, const float* lnb) {
    extern __shared__ __align__(16) unsigned char dynn[];
    __nv_bfloat16* sA = (__nv_bfloat16*)dynn;
    __nv_bfloat16* sB = (__nv_bfloat16*)(dynn + 3072);
    __nv_bfloat16* sT = (__nv_bfloat16*)(dynn + 9216);
    float* sX = (float*)dynn;
    __nv_bfloat16* sAgg = (__nv_bfloat16*)(dynn + 33792);
    __shared__ float sMu[64], sRs[64];
    __shared__ int sRp[65];

    int tid = threadIdx.x;
    int lane = tid & 31, warp = tid >> 5;
    int gID = lane >> 2, tIG = lane & 3;
    int wr = warp >> 2, wc = warp & 3;
    int v0 = blockIdx.x * 64;

    if (tid < 65) {
        int v = v0 + tid;
        sRp[tid] = g_rowptr[v > NV ? NV : v];
    }
    __syncthreads();

#pragma unroll
    for (int i = 0; i < 8; i++) {
        int r = warp * 8 + i;
        float a0 = 0.f, a1 = 0.f, a2 = 0.f, a3 = 0.f;
        int s = sRp[r], e = sRp[r + 1];
        for (int ed = s; ed < e; ed++) {
            uint2 q = *(const uint2*)&g_msg[(size_t)ed * H + lane * 4];
            __nv_bfloat162 q0 = *(__nv_bfloat162*)&q.x;
            __nv_bfloat162 q1 = *(__nv_bfloat162*)&q.y;
            a0 += __bfloat162float(q0.x); a1 += __bfloat162float(q0.y);
            a2 += __bfloat162float(q1.x); a3 += __bfloat162float(q1.y);
        }
        *(uint32_t*)&sAgg[r * 128 + lane * 4]     = packbf(a0, a1);
        *(uint32_t*)&sAgg[r * 128 + lane * 4 + 2] = packbf(a2, a3);
    }
    __syncthreads();

    float acc[2][4][4];
#pragma unroll
    for (int mt = 0; mt < 2; mt++)
#pragma unroll
        for (int nt = 0; nt < 4; nt++)
#pragma unroll
            for (int q = 0; q < 4; q++) acc[mt][nt][q] = 0.f;

    const __nv_bfloat16* w1t = &g_nw1t[layer][0][0];

    for (int ch = 0; ch < 16; ch++) {
        int k0 = ch * 16;
        __syncthreads();
#pragma unroll
        for (int it = 0; it < 4; it++) {
            int idx = tid + it * 256;
            int n = idx >> 3, p = idx & 7;
            *(uint32_t*)&sB[n * PADA + p * 2] = *(const uint32_t*)&w1t[n * 256 + k0 + p * 2];
        }
#pragma unroll
        for (int it = 0; it < 2; it++) {
            int idx = tid + it * 256;
            int r = idx >> 3, p = idx & 7;
            uint32_t val;
            if (k0 < 128) {
                int vv = v0 + r; if (vv >= NV) vv = NV - 1;
                val = *(const uint32_t*)&g_hb[(size_t)vv * H + k0 + p * 2];
            } else {
                val = *(uint32_t*)&sAgg[r * 128 + (k0 - 128) + p * 2];
            }
            *(uint32_t*)&sA[r * PADA + p * 2] = val;
        }
        __syncthreads();

        uint32_t af[2][4], bfr[4][2];
#pragma unroll
        for (int mt = 0; mt < 2; mt++) {
            int rrow = wr * 32 + mt * 16 + (lane & 15);
            ldsm4(af[mt], sA + rrow * PADA + (lane >> 4) * 8);
        }
#pragma unroll
        for (int np = 0; np < 2; np++) {
            uint32_t rr[4];
            int n = wc * 32 + np * 16 + (lane & 7) + (lane >> 4) * 8;
            ldsm4(rr, sB + n * PADA + ((lane >> 3) & 1) * 8);
            bfr[np * 2][0] = rr[0]; bfr[np * 2][1] = rr[1];
            bfr[np * 2 + 1][0] = rr[2]; bfr[np * 2 + 1][1] = rr[3];
        }
#pragma unroll
        for (int mt = 0; mt < 2; mt++)
#pragma unroll
            for (int nt = 0; nt < 4; nt++)
                mma_bf16(acc[mt][nt], af[mt], bfr[nt]);
    }
    __syncthreads();

#pragma unroll
    for (int mt = 0; mt < 2; mt++)
#pragma unroll
        for (int nt = 0; nt < 4; nt++) {
            int rrow = wr * 32 + mt * 16 + gID;
            int col = wc * 32 + nt * 8 + tIG * 2;
            float bb0 = b1[col], bb1 = b1[col + 1];
            *(uint32_t*)&sT[rrow * PADT + col] =
                packbf(siluf(acc[mt][nt][0] + bb0), siluf(acc[mt][nt][1] + bb1));
            *(uint32_t*)&sT[(rrow + 8) * PADT + col] =
                packbf(siluf(acc[mt][nt][2] + bb0), siluf(acc[mt][nt][3] + bb1));
#pragma unroll
            for (int q = 0; q < 4; q++) acc[mt][nt][q] = 0.f;
        }

    const __nv_bfloat16* w2t = &g_nw2t[layer][0][0];

    for (int ch = 0; ch < 8; ch++) {
        int k0 = ch * 16;
        __syncthreads();
#pragma unroll
        for (int it = 0; it < 4; it++) {
            int idx = tid + it * 256;
            int n = idx >> 3, p = idx & 7;
            *(uint32_t*)&sB[n * PADA + p * 2] = *(const uint32_t*)&w2t[n * H + k0 + p * 2];
        }
        __syncthreads();

        uint32_t af[2][4], bfr[4][2];
#pragma unroll
        for (int mt = 0; mt < 2; mt++) {
            int rrow = wr * 32 + mt * 16 + (lane & 15);
            ldsm4(af[mt], sT + rrow * PADT + k0 + (lane >> 4) * 8);
        }
#pragma unroll
        for (int np = 0; np < 2; np++) {
            uint32_t rr[4];
            int n = wc * 32 + np * 16 + (lane & 7) + (lane >> 4) * 8;
            ldsm4(rr, sB + n * PADA + ((lane >> 3) & 1) * 8);
            bfr[np * 2][0] = rr[0]; bfr[np * 2][1] = rr[1];
            bfr[np * 2 + 1][0] = rr[2]; bfr[np * 2 + 1][1] = rr[3];
        }
#pragma unroll
        for (int mt = 0; mt < 2; mt++)
#pragma unroll
            for (int nt = 0; nt < 4; nt++)
                mma_bf16(acc[mt][nt], af[mt], bfr[nt]);
    }
    __syncthreads();

    float xv[2][4][4];
#pragma unroll
    for (int mt = 0; mt < 2; mt++)
#pragma unroll
        for (int nt = 0; nt < 4; nt++) {
            int rrow = wr * 32 + mt * 16 + gID;
            int col = wc * 32 + nt * 8 + tIG * 2;
            float bb0 = b2[col], bb1 = b2[col + 1];
            int va = v0 + rrow; if (va >= NV) va = NV - 1;
            int vb = v0 + rrow + 8; if (vb >= NV) vb = NV - 1;
            xv[mt][nt][0] = acc[mt][nt][0] + bb0 + g_h[(size_t)va * H + col];
            xv[mt][nt][1] = acc[mt][nt][1] + bb1 + g_h[(size_t)va * H + col + 1];
            xv[mt][nt][2] = acc[mt][nt][2] + bb0 + g_h[(size_t)vb * H + col];
            xv[mt][nt][3] = acc[mt][nt][3] + bb1 + g_h[(size_t)vb * H + col + 1];
            sX[rrow * PADM + col]           = xv[mt][nt][0];
            sX[rrow * PADM + col + 1]       = xv[mt][nt][1];
            sX[(rrow + 8) * PADM + col]     = xv[mt][nt][2];
            sX[(rrow + 8) * PADM + col + 1] = xv[mt][nt][3];
        }
    __syncthreads();

#pragma unroll
    for (int i = 0; i < 8; i++) {
        int rrow = warp * 8 + i;
        float4 v = *(float4*)&sX[rrow * PADM + lane * 4];
        float s = v.x + v.y + v.z + v.w;
        float s2 = v.x * v.x + v.y * v.y + v.z * v.z + v.w * v.w;
#pragma unroll
        for (int off = 16; off; off >>= 1) {
            s += __shfl_xor_sync(0xffffffffu, s, off);
            s2 += __shfl_xor_sync(0xffffffffu, s2, off);
        }
        if (lane == 0) {
            float mu = s * (1.f / H);
            float var = s2 * (1.f / H) - mu * mu;
            sMu[rrow] = mu;
            sRs[rrow] = rsqrtf(var + EPSF);
        }
    }
    __syncthreads();

#pragma unroll
    for (int mt = 0; mt < 2; mt++)
#pragma unroll
        for (int nt = 0; nt < 4; nt++) {
            int rrow = wr * 32 + mt * 16 + gID;
            int col = wc * 32 + nt * 8 + tIG * 2;
            float g0 = lng[col], g1 = lng[col + 1];
            float bb0 = lnb[col], bb1 = lnb[col + 1];
            int va = v0 + rrow, vb = v0 + rrow + 8;
            if (va < NV) {
                float o0 = g0 * (xv[mt][nt][0] - sMu[rrow]) * sRs[rrow] + bb0;
                float o1 = g1 * (xv[mt][nt][1] - sMu[rrow]) * sRs[rrow] + bb1;
                g_h[(size_t)va * H + col] = o0;
                g_h[(size_t)va * H + col + 1] = o1;
                *(uint32_t*)&g_hb[(size_t)va * H + col] = packbf(o0, o1);
            }
            if (vb < NV) {
                float o0 = g0 * (xv[mt][nt][2] - sMu[rrow + 8]) * sRs[rrow + 8] + bb0;
                float o1 = g1 * (xv[mt][nt][3] - sMu[rrow + 8]) * sRs[rrow + 8] + bb1;
                g_h[(size_t)vb * H + col] = o0;
                g_h[(size_t)vb * H + col + 1] = o1;
                *(uint32_t*)&g_hb[(size_t)vb * H + col] = packbf(o0, o1);
            }
        }
}

// -------- loss (also restores g_cnt = 0 invariant) --------
__global__ void k_loss(const float* pos0, const float* pos1,
                       const float* opw, const float* opb) {
    __shared__ double sAcc[8];
    int lane = threadIdx.x & 31;
    int wid = threadIdx.x >> 5;
    int gw = blockIdx.x * (blockDim.x >> 5) + wid;
    int nw = gridDim.x * (blockDim.x >> 5);
    double local = 0.0;
    for (int v = gw; v < NV; v += nw) {
        float h0 = g_h[(size_t)v * H + lane];
        float h1 = g_h[(size_t)v * H + lane + 32];
        float h2 = g_h[(size_t)v * H + lane + 64];
        float h3 = g_h[(size_t)v * H + lane + 96];
#pragma unroll
        for (int c = 0; c < 3; c++) {
            float s = h0 * opw[lane * 3 + c] + h1 * opw[(lane + 32) * 3 + c]
                    + h2 * opw[(lane + 64) * 3 + c] + h3 * opw[(lane + 96) * 3 + c];
#pragma unroll
            for (int off = 16; off; off >>= 1) s += __shfl_down_sync(0xffffffffu, s, off);
            if (lane == 0) {
                float vp = s + opb[c];
                float tg = pos1[v * 3 + c] - pos0[v * 3 + c];
                float d = vp - tg;
                local += (double)d * (double)d;
            }
        }
    }
    for (int i = blockIdx.x * blockDim.x + threadIdx.x; i < NV; i += gridDim.x * blockDim.x)
        g_cnt[i] = 0;
    if (lane == 0) sAcc[wid] = local;
    __syncthreads();
    if (threadIdx.x == 0) {
        double t = 0.0;
        for (int i = 0; i < (int)(blockDim.x >> 5); i++) t += sAcc[i];
        atomicAdd(&g_loss, t);
    }
}

__global__ void k_final(float* out) {
    if (threadIdx.x == 0) out[0] = (float)(g_loss / (double)(NV * 3));
}

extern "C" void kernel_launch(void* const* d_in, const int* in_sizes, int n_in,
                              void* d_out, int out_size) {
    const float* pos0  = (const float*)d_in[0];
    const float* pos1  = (const float*)d_in[1];
    const float* z     = (const float*)d_in[2];
    const float* t     = (const float*)d_in[3];
    const int*   ei    = (const int*)d_in[4];
    const int*   batch = (const int*)d_in[5];
    const float* te_w1 = (const float*)d_in[6];
    const float* te_b1 = (const float*)d_in[7];
    const float* te_w2 = (const float*)d_in[8];
    const float* te_b2 = (const float*)d_in[9];
    const float* cp_w  = (const float*)d_in[10];
    const float* cp_b  = (const float*)d_in[11];
    const float* eb1   = (const float*)d_in[13];
    const float* eb2   = (const float*)d_in[15];
    const float* nb1   = (const float*)d_in[17];
    const float* nb2   = (const float*)d_in[19];
    const float* ln_g  = (const float*)d_in[20];
    const float* ln_b  = (const float*)d_in[21];
    const float* op_w  = (const float*)d_in[22];
    const float* op_b  = (const float*)d_in[23];

    cudaFuncSetAttribute(k_edge, cudaFuncAttributeMaxDynamicSharedMemorySize, ESMEM);
    cudaFuncSetAttribute(k_node, cudaFuncAttributeMaxDynamicSharedMemorySize, NSMEM);

    k_pre<<<B_PRE, 1024>>>(t, te_w1, te_b1, te_w2, te_b2, z, cp_w, cp_b,
                           pos0, pos1, ei,
                           (const float*)d_in[12], (const float*)d_in[14],
                           (const float*)d_in[16], (const float*)d_in[18]);
    k_scan<<<1, 1024>>>();
    k_sorth<<<(NE + NV * 32 + 255) / 256, 256>>>(ei, batch);

    for (int l = 0; l < NLAYERS; l++) {
        k_edge<<<148, 512, ESMEM>>>(l, eb1 + (size_t)l * H, eb2 + (size_t)l * H);
        k_node<<<(NV + 63) / 64, 256, NSMEM>>>(l,
            nb1 + (size_t)l * H, nb2 + (size_t)l * H,
            ln_g + (size_t)l * H, ln_b + (size_t)l * H);
    }

    k_loss<<<256, 256>>>(pos0, pos1, op_w, op_b);
    k_final<<<1, 1>>>((float*)d_out);
}